// round 8
// baseline (speedup 1.0000x reference)
#include <cuda_runtime.h>
#include <cuda_bf16.h>
#include <math.h>

#define Dd 64
#define Nn 8192
#define Mm 256
#define NH 32
#define DN     0.3535533905932738f   /* 64^-0.25 */
#define RATIO  0.0625f               /* 256^-0.5 */
#define REPS   6.25e-8f              /* RATIO * 1e-6 */
#define DIAGC  0.0625f               /* DN^2 * 0.5 */

typedef unsigned long long u64;

// ---------------- scratch (device globals; no allocation) ----------------
__device__ float g_kbuf[(size_t)NH * Mm * Nn];          // [h][m][n] : u - diag (keys)
__device__ u64   g_q2[(size_t)NH * Nn * 128];           // phi_q (hi,lo) pairs, [h][tok][m/2]
__device__ unsigned g_kmax[NH];                         // per-head max(raw u), ordered key
__device__ float g_kvpart[(size_t)NH * 16 * 80 * 256];  // [h*16+sl][d][m]
__device__ u64   g_kvt2[(size_t)NH * 80 * 128];         // kv^T (hi,lo) pairs, [h][d][m/2]
__device__ u64   g_pb2[256 * 32];                       // proj*DN (hi,lo) pairs, [m][d/2]

// order-preserving float<->uint key
static __device__ __forceinline__ unsigned fkey(float f) {
    unsigned b = __float_as_uint(f);
    return (b & 0x80000000u) ? ~b : (b | 0x80000000u);
}
static __device__ __forceinline__ float finv(unsigned k) {
    return __uint_as_float((k & 0x80000000u) ? (k & 0x7fffffffu) : ~k);
}

// branch-free exp on FMA/ALU pipes. Valid for x <= 0, ~2.4e-6 rel err.
static __device__ __forceinline__ float fexp(float x) {
    float t = x * 1.4426950408889634f;
    t = fmaxf(t, -125.0f);
    float r  = t + 12582912.0f;
    float fi = r - 12582912.0f;
    float f  = t - fi;
    float p = 1.3333558e-3f;
    p = fmaf(p, f, 9.6181291e-3f);
    p = fmaf(p, f, 5.5504109e-2f);
    p = fmaf(p, f, 2.4022651e-1f);
    p = fmaf(p, f, 6.9314718e-1f);
    p = fmaf(p, f, 1.0f);
    int ib = __float_as_int(r) - 0x4B400000;
    float s = __int_as_float((ib + 127) << 23);
    return p * s;
}

// HMMA m16n8k16 bf16 -> fp32 accum
static __device__ __forceinline__ void mma16816(float c[4], const unsigned a[4],
                                                unsigned b0, unsigned b1) {
    asm volatile(
        "mma.sync.aligned.m16n8k16.row.col.f32.bf16.bf16.f32 "
        "{%0,%1,%2,%3}, {%4,%5,%6,%7}, {%8,%9}, {%0,%1,%2,%3};"
        : "+f"(c[0]), "+f"(c[1]), "+f"(c[2]), "+f"(c[3])
        : "r"(a[0]), "r"(a[1]), "r"(a[2]), "r"(a[3]), "r"(b0), "r"(b1));
}

// bf16 hi/lo split, packing pairs (v0,v1) -> (hi-pair, lo-pair)
static __device__ __forceinline__ void split2(float v0, float v1, unsigned& ph, unsigned& pl) {
    __nv_bfloat16 h0 = __float2bfloat16(v0);
    __nv_bfloat16 h1 = __float2bfloat16(v1);
    __nv_bfloat16 l0 = __float2bfloat16(v0 - __bfloat162float(h0));
    __nv_bfloat16 l1 = __float2bfloat16(v1 - __bfloat162float(h1));
    ph = ((unsigned)__bfloat16_as_ushort(h1) << 16) | __bfloat16_as_ushort(h0);
    pl = ((unsigned)__bfloat16_as_ushort(l1) << 16) | __bfloat16_as_ushort(l0);
}
static __device__ __forceinline__ u64 pack64(unsigned ph, unsigned pl) {
    return (u64)ph | ((u64)pl << 32);
}

// ---------------- K0: interleaved bf16-split scaled proj + reset kmax ------
__global__ void k_init(const float* __restrict__ proj)
{
    int idx = blockIdx.x * 256 + threadIdx.x;   // 64 blocks x 256
    if (idx < 256 * 32) {
        int m = idx >> 5, p = idx & 31, d = 2 * p;
        float v0 = proj[m * 64 + d] * DN;
        float v1 = proj[m * 64 + d + 1] * DN;
        unsigned ph, pl;
        split2(v0, v1, ph, pl);
        g_pb2[idx] = pack64(ph, pl);
    }
    if (idx < NH) g_kmax[idx] = 0u;
}

// ---------------- K_proj (HMMA): u = x . P^T per 64-token block ------------
// grid (128, 32), block 256 (8 warps). Warp tile: 16 tokens x 128 features.
// Interleaved hi/lo pairs; row stride 288 B.
#define OFF_A2   0
#define OFF_P2   18432
#define OFF_SQP  92160
#define OFF_SQ   93184
#define OFF_SMAX 93440
#define PROJ_SMEM 94208

template <bool IS_QUERY>
__global__ void __launch_bounds__(256, 2) k_proj_mma(const float* __restrict__ x)
{
    extern __shared__ char smem[];
    char* A2 = smem + OFF_A2;       // [64 tok][32 pairs u64] rows of 288 B
    char* P2 = smem + OFF_P2;       // [256 feat][32 pairs]
    float* sqp  = (float*)(smem + OFF_SQP);   // [64][4]
    float* sq   = (float*)(smem + OFF_SQ);    // [64]
    float* smax = (float*)(smem + OFF_SMAX);  // [2][64]

    const int t = threadIdx.x;
    const int head = blockIdx.y;
    const int n0 = blockIdx.x * 64;

    // ---- stage A: x[d][tok] -> pairs + partial sumsq ----
    {
        const int tok = t & 63, dblk = t >> 6;
        const float* xp = x + (size_t)head * Dd * Nn + n0 + tok;
        float s = 0.0f;
        #pragma unroll
        for (int i = 0; i < 8; i++) {
            int d = dblk * 16 + 2 * i;
            float v0 = xp[(size_t)d * Nn];
            float v1 = xp[(size_t)(d + 1) * Nn];
            s = fmaf(v0, v0, fmaf(v1, v1, s));
            unsigned ph, pl;
            split2(v0, v1, ph, pl);
            *(u64*)(A2 + tok * 288 + d * 4) = pack64(ph, pl);
        }
        sqp[tok * 4 + dblk] = s;
    }
    // ---- stage P from g_pb2 ----
    #pragma unroll
    for (int cc = 0; cc < 16; cc++) {
        int e = t + 256 * cc;           // < 4096 uint4
        int row = e >> 4, j = e & 15;
        *(uint4*)(P2 + row * 288 + j * 16) = ((const uint4*)g_pb2)[e];
    }
    __syncthreads();
    if (t < 64) sq[t] = sqp[4*t] + sqp[4*t+1] + sqp[4*t+2] + sqp[4*t+3];

    const int w = t >> 5, lane = t & 31;
    const int g = lane >> 2, tq = lane & 3;
    const int tb = (w & 3) * 16;            // token base
    const int fb = (w >> 2) * 128;          // feature base

    float c[16][4];
    #pragma unroll
    for (int nt = 0; nt < 16; nt++)
        #pragma unroll
        for (int j = 0; j < 4; j++) c[nt][j] = 0.0f;

    #pragma unroll
    for (int k = 0; k < 4; k++) {
        const int kb = k * 64 + tq * 8;     // byte offset of pair (koff/2 + tq)
        unsigned ah[4], al[4];
        {
            uint2 p0 = *(const uint2*)(A2 + (tb + g)     * 288 + kb);
            uint2 p1 = *(const uint2*)(A2 + (tb + g + 8) * 288 + kb);
            uint2 p2 = *(const uint2*)(A2 + (tb + g)     * 288 + kb + 32);
            uint2 p3 = *(const uint2*)(A2 + (tb + g + 8) * 288 + kb + 32);
            ah[0]=p0.x; al[0]=p0.y; ah[1]=p1.x; al[1]=p1.y;
            ah[2]=p2.x; al[2]=p2.y; ah[3]=p3.x; al[3]=p3.y;
        }
        #pragma unroll
        for (int nt = 0; nt < 16; nt++) {
            const char* pr = P2 + (fb + nt * 8 + g) * 288 + kb;
            uint2 q0 = *(const uint2*)(pr);
            uint2 q1 = *(const uint2*)(pr + 32);
            mma16816(c[nt], ah, q0.x, q1.x);
            mma16816(c[nt], ah, q0.y, q1.y);
            mma16816(c[nt], al, q0.x, q1.x);
        }
    }

    const int tl0 = tb + g, tl1 = tb + g + 8;
    const float dg0 = sq[tl0] * DIAGC;
    const float dg1 = sq[tl1] * DIAGC;

    if (!IS_QUERY) {
        // raw-u max -> per-head atomicMax
        float bm = -3.4e38f;
        #pragma unroll
        for (int nt = 0; nt < 16; nt++)
            bm = fmaxf(bm, fmaxf(fmaxf(c[nt][0], c[nt][1]), fmaxf(c[nt][2], c[nt][3])));
        #pragma unroll
        for (int o = 16; o; o >>= 1) bm = fmaxf(bm, __shfl_xor_sync(0xffffffffu, bm, o));
        if (lane == 0) atomicMax(g_kmax + head, fkey(bm));

        // transpose (u - diag) into smem [256 m][68 tok], then coalesced write [m][n]
        __syncthreads();
        float* Tr = (float*)(smem + OFF_P2);    // [256][68] f32 = 69632 B
        #pragma unroll
        for (int nt = 0; nt < 16; nt++) {
            int m = fb + nt * 8 + 2 * tq;
            Tr[m * 68 + tl0]       = c[nt][0] - dg0;
            Tr[(m + 1) * 68 + tl0] = c[nt][1] - dg0;
            Tr[m * 68 + tl1]       = c[nt][2] - dg1;
            Tr[(m + 1) * 68 + tl1] = c[nt][3] - dg1;
        }
        __syncthreads();
        const int q = t & 3;
        #pragma unroll
        for (int p = 0; p < 4; p++) {
            int m = (t >> 2) + p * 64;
            float* drow = g_kbuf + ((size_t)(head * Mm + m)) * Nn + n0 + q * 16;
            #pragma unroll
            for (int i = 0; i < 4; i++)
                *(float4*)(drow + 4 * i) = *(const float4*)(Tr + m * 68 + q * 16 + 4 * i);
        }
    } else {
        // per-token max over features (two halves combined via smem)
        float m0 = -3.4e38f, m1 = -3.4e38f;
        #pragma unroll
        for (int nt = 0; nt < 16; nt++) {
            m0 = fmaxf(m0, fmaxf(c[nt][0], c[nt][1]));
            m1 = fmaxf(m1, fmaxf(c[nt][2], c[nt][3]));
        }
        m0 = fmaxf(m0, __shfl_xor_sync(0xffffffffu, m0, 1));
        m0 = fmaxf(m0, __shfl_xor_sync(0xffffffffu, m0, 2));
        m1 = fmaxf(m1, __shfl_xor_sync(0xffffffffu, m1, 1));
        m1 = fmaxf(m1, __shfl_xor_sync(0xffffffffu, m1, 2));
        if (tq == 0) {
            smax[(w >> 2) * 64 + tl0] = m0;
            smax[(w >> 2) * 64 + tl1] = m1;
        }
        __syncthreads();
        const float cc0 = -dg0 - fmaxf(smax[tl0], smax[64 + tl0]);
        const float cc1 = -dg1 - fmaxf(smax[tl1], smax[64 + tl1]);
        u64* Tr2 = (u64*)(smem + OFF_P2);   // [64 tok][132 pairs] = 67584 B
        #pragma unroll
        for (int nt = 0; nt < 16; nt++) {
            int m = fb + nt * 8 + 2 * tq;
            float p0 = RATIO * fexp(c[nt][0] + cc0) + REPS;
            float p1 = RATIO * fexp(c[nt][1] + cc0) + REPS;
            float p2 = RATIO * fexp(c[nt][2] + cc1) + REPS;
            float p3 = RATIO * fexp(c[nt][3] + cc1) + REPS;
            unsigned ph, pl;
            split2(p0, p1, ph, pl);
            Tr2[tl0 * 132 + (m >> 1)] = pack64(ph, pl);
            split2(p2, p3, ph, pl);
            Tr2[tl1 * 132 + (m >> 1)] = pack64(ph, pl);
        }
        __syncthreads();
        const int tok = t >> 2, q = t & 3;
        uint4* dst = (uint4*)(g_q2 + ((size_t)head * Nn + n0 + tok) * 128 + q * 32);
        const uint4* src = (const uint4*)(Tr2 + tok * 132 + q * 32);
        #pragma unroll
        for (int j = 0; j < 16; j++) dst[j] = src[j];
    }
}

// ---------------- K2 (HMMA): kv partials = phi_k . V^T (knorm col) ---------
// grid (16 slices, 32 heads), block 512 (16 warps). Warp tile 32m x 40d.
// Interleaved pairs, row stride 288 B. V row 64 = ones -> knorm.
#define KV_A2  0
#define KV_V2  73728
#define KV_SMEM 96768

__global__ void __launch_bounds__(512, 1) k_kv_mma(const float* __restrict__ value)
{
    extern __shared__ char smem[];
    char* A2 = smem + KV_A2;   // [256 m][32 pairs]
    char* V2 = smem + KV_V2;   // [80 d][32 pairs]

    const int t = threadIdx.x;
    const int head = blockIdx.y;
    const int slice = blockIdx.x;
    const float kmax = finv(g_kmax[head]);

    const int w = t >> 5, lane = t & 31;
    const int g = lane >> 2, tq = lane & 3;
    const int mg = (w & 7) * 32;
    const int dgr = (w >> 3) * 40;

    // V pad rows 64..79: row 64 = 1.0 pairs, rest 0
    if (t < 512) {
        int row = 64 + (t >> 5), pair = t & 31;
        *(u64*)(V2 + row * 288 + pair * 8) = (row == 64) ? 0x3F803F80ull : 0ull;
    }

    float c[2][5][4];
    #pragma unroll
    for (int mt = 0; mt < 2; mt++)
        #pragma unroll
        for (int dt = 0; dt < 5; dt++)
            #pragma unroll
            for (int j = 0; j < 4; j++) c[mt][dt][j] = 0.0f;

    const float* vp = value + (size_t)head * Dd * Nn;

    for (int ch = 0; ch < 8; ch++) {
        const int n0 = slice * 512 + ch * 64;
        __syncthreads();   // previous MMA reads complete

        // stage A: phi_k pairs. thread: row = t>>1, half q = t&1 (32 n each)
        {
            int m = t >> 1, q = t & 1;
            const float* src = g_kbuf + ((size_t)(head * Mm + m)) * Nn + n0 + q * 32;
            char* drow = A2 + m * 288 + q * 128;
            #pragma unroll
            for (int i = 0; i < 8; i++) {
                float4 v = *(const float4*)(src + 4 * i);
                float p0 = RATIO * fexp(v.x - kmax) + REPS;
                float p1 = RATIO * fexp(v.y - kmax) + REPS;
                float p2 = RATIO * fexp(v.z - kmax) + REPS;
                float p3 = RATIO * fexp(v.w - kmax) + REPS;
                unsigned ph0, pl0, ph1, pl1;
                split2(p0, p1, ph0, pl0);
                split2(p2, p3, ph1, pl1);
                *(uint4*)(drow + i * 16) = make_uint4(ph0, pl0, ph1, pl1);
            }
        }
        // stage V: row = t>>3, q = t&7 (8 n each)
        {
            int d = t >> 3, q = t & 7;
            const float* src = vp + (size_t)d * Nn + n0 + q * 8;
            char* drow = V2 + d * 288 + q * 32;
            #pragma unroll
            for (int i = 0; i < 2; i++) {
                float4 v = *(const float4*)(src + 4 * i);
                unsigned ph0, pl0, ph1, pl1;
                split2(v.x, v.y, ph0, pl0);
                split2(v.z, v.w, ph1, pl1);
                *(uint4*)(drow + i * 16) = make_uint4(ph0, pl0, ph1, pl1);
            }
        }
        __syncthreads();

        #pragma unroll
        for (int k = 0; k < 4; k++) {
            const int kb = k * 64 + tq * 8;
            unsigned ah[2][4], al[2][4];
            #pragma unroll
            for (int mt = 0; mt < 2; mt++) {
                int r0 = mg + mt * 16 + g, r1 = r0 + 8;
                uint2 p0 = *(const uint2*)(A2 + r0 * 288 + kb);
                uint2 p1 = *(const uint2*)(A2 + r1 * 288 + kb);
                uint2 p2 = *(const uint2*)(A2 + r0 * 288 + kb + 32);
                uint2 p3 = *(const uint2*)(A2 + r1 * 288 + kb + 32);
                ah[mt][0]=p0.x; al[mt][0]=p0.y; ah[mt][1]=p1.x; al[mt][1]=p1.y;
                ah[mt][2]=p2.x; al[mt][2]=p2.y; ah[mt][3]=p3.x; al[mt][3]=p3.y;
            }
            #pragma unroll
            for (int dt = 0; dt < 5; dt++) {
                const char* vr = V2 + (dgr + dt * 8 + g) * 288 + kb;
                uint2 q0 = *(const uint2*)(vr);
                uint2 q1 = *(const uint2*)(vr + 32);
                #pragma unroll
                for (int mt = 0; mt < 2; mt++) {
                    mma16816(c[mt][dt], ah[mt], q0.x, q1.x);
                    mma16816(c[mt][dt], ah[mt], q0.y, q1.y);
                    mma16816(c[mt][dt], al[mt], q0.x, q1.x);
                }
            }
        }
    }

    // write partials [d][m]
    float* dst = g_kvpart + (size_t)(head * 16 + slice) * 20480;
    #pragma unroll
    for (int mt = 0; mt < 2; mt++) {
        int m0 = mg + mt * 16 + g, m1 = m0 + 8;
        #pragma unroll
        for (int dt = 0; dt < 5; dt++) {
            int d0 = dgr + dt * 8 + 2 * tq;
            dst[d0 * 256 + m0]       = c[mt][dt][0];
            dst[(d0 + 1) * 256 + m0] = c[mt][dt][1];
            dst[d0 * 256 + m1]       = c[mt][dt][2];
            dst[(d0 + 1) * 256 + m1] = c[mt][dt][3];
        }
    }
}

// ---------------- K3: reduce partials -> interleaved bf16-split kv^T -------
__global__ void k_reduce()
{
    int idx = blockIdx.x * 256 + threadIdx.x;   // < 32*80*128 = 327680
    int h = idx / 10240;
    int rem = idx - h * 10240;                  // d*128 + m/2
    int off = (rem >> 7) * 256 + 2 * (rem & 127);
    float s0 = 0.0f, s1 = 0.0f;
    #pragma unroll
    for (int sl = 0; sl < 16; sl++) {
        const float* p = g_kvpart + (size_t)(h * 16 + sl) * 20480 + off;
        s0 += p[0];
        s1 += p[1];
    }
    unsigned ph, pl;
    split2(s0, s1, ph, pl);
    g_kvt2[idx] = pack64(ph, pl);
}

// ---------------- K4 (HMMA): out = phi_q . kv, divide by norm col ----------
// grid (128, 32), block 256 (8 warps). 64 tokens x 80 d. Warp: 16 tok x 40 d.
// Interleaved pairs, row stride 1056 B.
#define QO_Q2 0
#define QO_K2 67584
#define QO_SN 152064
#define QO_SMEM 152320

__global__ void __launch_bounds__(256, 1) k_out_mma(float* __restrict__ out)
{
    extern __shared__ char smem[];
    char* Q2 = smem + QO_Q2;   // [64 tok][128 pairs] rows 1056 B
    char* K2 = smem + QO_K2;   // [80 d][128 pairs]
    float* sn = (float*)(smem + QO_SN);   // [64]

    const int t = threadIdx.x;
    const int head = blockIdx.y;
    const int n0 = blockIdx.x * 64;

    // stage phi_q pairs
    {
        int tok = t >> 2, q = t & 3;
        const uint4* src = (const uint4*)(g_q2 + ((size_t)head * Nn + n0 + tok) * 128 + q * 32);
        uint4* dst = (uint4*)(Q2 + tok * 1056 + q * 256);
        #pragma unroll
        for (int j = 0; j < 16; j++) dst[j] = src[j];
    }
    // stage kv^T pairs, 80 rows
    #pragma unroll
    for (int r = 0; r < 2; r++) {
        int e = t + 256 * r;
        if (e < 320) {
            int row = e >> 2, q = e & 3;
            const uint4* src = (const uint4*)(g_kvt2 + ((size_t)head * 80 + row) * 128 + q * 32);
            uint4* dst = (uint4*)(K2 + row * 1056 + q * 256);
            #pragma unroll
            for (int j = 0; j < 16; j++) dst[j] = src[j];
        }
    }
    __syncthreads();

    const int w = t >> 5, lane = t & 31;
    const int g = lane >> 2, tq = lane & 3;
    const int tg = (w & 3) * 16;
    const int dgr = (w >> 2) * 40;

    float c[5][4];
    #pragma unroll
    for (int dt = 0; dt < 5; dt++)
        #pragma unroll
        for (int j = 0; j < 4; j++) c[dt][j] = 0.0f;

    #pragma unroll
    for (int kc = 0; kc < 16; kc++) {
        const int kb = kc * 64 + tq * 8;
        unsigned ah[4], al[4];
        {
            uint2 p0 = *(const uint2*)(Q2 + (tg + g)     * 1056 + kb);
            uint2 p1 = *(const uint2*)(Q2 + (tg + g + 8) * 1056 + kb);
            uint2 p2 = *(const uint2*)(Q2 + (tg + g)     * 1056 + kb + 32);
            uint2 p3 = *(const uint2*)(Q2 + (tg + g + 8) * 1056 + kb + 32);
            ah[0]=p0.x; al[0]=p0.y; ah[1]=p1.x; al[1]=p1.y;
            ah[2]=p2.x; al[2]=p2.y; ah[3]=p3.x; al[3]=p3.y;
        }
        #pragma unroll
        for (int dt = 0; dt < 5; dt++) {
            const char* kr = K2 + (dgr + dt * 8 + g) * 1056 + kb;
            uint2 q0 = *(const uint2*)(kr);
            uint2 q1 = *(const uint2*)(kr + 32);
            mma16816(c[dt], ah, q0.x, q1.x);
            mma16816(c[dt], ah, q0.y, q1.y);
            mma16816(c[dt], al, q0.x, q1.x);
        }
    }

    // norm column (d = 64): warps w>=4 (dgr=40), dt=3, tq==0
    if (w >= 4 && tq == 0) {
        sn[tg + g]     = c[3][0];
        sn[tg + g + 8] = c[3][2];
    }
    __syncthreads();
    const float rn0 = 1.0f / sn[tg + g];
    const float rn1 = 1.0f / sn[tg + g + 8];

    float* op = out + (size_t)head * Dd * Nn + n0;
    #pragma unroll
    for (int dt = 0; dt < 5; dt++) {
        int d0 = dgr + dt * 8 + 2 * tq;
        if (d0 < 64) {
            op[(size_t)d0 * Nn + tg + g]           = c[dt][0] * rn0;
            op[(size_t)(d0 + 1) * Nn + tg + g]     = c[dt][1] * rn0;
            op[(size_t)d0 * Nn + tg + g + 8]       = c[dt][2] * rn1;
            op[(size_t)(d0 + 1) * Nn + tg + g + 8] = c[dt][3] * rn1;
        }
    }
}

// ---------------- launch ----------------
extern "C" void kernel_launch(void* const* d_in, const int* in_sizes, int n_in,
                              void* d_out, int out_size)
{
    const float* query = (const float*)d_in[0];
    const float* key   = (const float*)d_in[1];
    const float* value = (const float*)d_in[2];
    const float* proj  = (const float*)d_in[3];
    float* out = (float*)d_out;

    cudaFuncSetAttribute(k_proj_mma<false>, cudaFuncAttributeMaxDynamicSharedMemorySize, PROJ_SMEM);
    cudaFuncSetAttribute(k_proj_mma<true>,  cudaFuncAttributeMaxDynamicSharedMemorySize, PROJ_SMEM);
    cudaFuncSetAttribute(k_kv_mma,  cudaFuncAttributeMaxDynamicSharedMemorySize, KV_SMEM);
    cudaFuncSetAttribute(k_out_mma, cudaFuncAttributeMaxDynamicSharedMemorySize, QO_SMEM);

    k_init<<<64, 256>>>(proj);
    k_proj_mma<false><<<dim3(128, 32), 256, PROJ_SMEM>>>(key);
    k_proj_mma<true><<<dim3(128, 32), 256, PROJ_SMEM>>>(query);
    k_kv_mma<<<dim3(16, 32), 512, KV_SMEM>>>(value);
    k_reduce<<<1280, 256>>>();
    k_out_mma<<<dim3(128, 32), 256, QO_SMEM>>>(out);
}

// round 9
// speedup vs baseline: 1.1152x; 1.1152x over previous
#include <cuda_runtime.h>
#include <cuda_bf16.h>
#include <math.h>

#define Dd 64
#define Nn 8192
#define Mm 256
#define NH 32
#define DN     0.3535533905932738f   /* 64^-0.25 */
#define RATIO  0.0625f               /* 256^-0.5 */
#define REPS   6.25e-8f              /* RATIO * 1e-6 */
#define DIAGC  0.0625f               /* DN^2 * 0.5 */

typedef unsigned long long u64;

// ---------------- scratch (device globals; no allocation) ----------------
__device__ u64   g_k2[(size_t)NH * Mm * (Nn / 2)];      // e=exp(u-diag-Mblk) (hi,lo) pairs, [h][m][n/2]
__device__ __nv_bfloat16 g_qh[(size_t)NH * Nn * Mm];    // phi_q hi, [h][tok][m]
__device__ __nv_bfloat16 g_ql[(size_t)NH * Nn * Mm];    // phi_q lo
__device__ unsigned g_kmax[NH];                         // per-head max(raw u), ordered key
__device__ float g_bmax[NH * 128];                      // per (head, 64-token block) max raw u
__device__ float g_vsum[NH * 64];                       // R[h][d] = sum_n V
__device__ float g_kvpart[(size_t)NH * 16 * 80 * 256];  // [h*16+sl][d][m]
__device__ __nv_bfloat16 g_kvth[(size_t)NH * 80 * 256]; // kv^T hi, [h][d][m] (d=64 -> knorm)
__device__ __nv_bfloat16 g_kvtl[(size_t)NH * 80 * 256]; // kv^T lo
__device__ __align__(16) __nv_bfloat16 g_pbh[256 * 64]; // proj*DN hi, [m][d]
__device__ __align__(16) __nv_bfloat16 g_pbl[256 * 64]; // proj*DN lo

// order-preserving float<->uint key
static __device__ __forceinline__ unsigned fkey(float f) {
    unsigned b = __float_as_uint(f);
    return (b & 0x80000000u) ? ~b : (b | 0x80000000u);
}
static __device__ __forceinline__ float finv(unsigned k) {
    return __uint_as_float((k & 0x80000000u) ? (k & 0x7fffffffu) : ~k);
}

// branch-free exp on FMA/ALU pipes. Valid for x <= 0, ~2.4e-6 rel err.
static __device__ __forceinline__ float fexp(float x) {
    float t = x * 1.4426950408889634f;
    t = fmaxf(t, -125.0f);
    float r  = t + 12582912.0f;
    float fi = r - 12582912.0f;
    float f  = t - fi;
    float p = 1.3333558e-3f;
    p = fmaf(p, f, 9.6181291e-3f);
    p = fmaf(p, f, 5.5504109e-2f);
    p = fmaf(p, f, 2.4022651e-1f);
    p = fmaf(p, f, 6.9314718e-1f);
    p = fmaf(p, f, 1.0f);
    int ib = __float_as_int(r) - 0x4B400000;
    float s = __int_as_float((ib + 127) << 23);
    return p * s;
}

// HMMA m16n8k16 bf16 -> fp32 accum
static __device__ __forceinline__ void mma16816(float c[4], const unsigned a[4],
                                                unsigned b0, unsigned b1) {
    asm volatile(
        "mma.sync.aligned.m16n8k16.row.col.f32.bf16.bf16.f32 "
        "{%0,%1,%2,%3}, {%4,%5,%6,%7}, {%8,%9}, {%0,%1,%2,%3};"
        : "+f"(c[0]), "+f"(c[1]), "+f"(c[2]), "+f"(c[3])
        : "r"(a[0]), "r"(a[1]), "r"(a[2]), "r"(a[3]), "r"(b0), "r"(b1));
}

// bf16 hi/lo split, packing pairs (v0,v1) -> (hi-pair, lo-pair)
static __device__ __forceinline__ void split2(float v0, float v1, unsigned& ph, unsigned& pl) {
    __nv_bfloat16 h0 = __float2bfloat16(v0);
    __nv_bfloat16 h1 = __float2bfloat16(v1);
    __nv_bfloat16 l0 = __float2bfloat16(v0 - __bfloat162float(h0));
    __nv_bfloat16 l1 = __float2bfloat16(v1 - __bfloat162float(h1));
    ph = ((unsigned)__bfloat16_as_ushort(h1) << 16) | __bfloat16_as_ushort(h0);
    pl = ((unsigned)__bfloat16_as_ushort(l1) << 16) | __bfloat16_as_ushort(l0);
}

// ---------------- K0: bf16-split scaled proj + reset kmax ----------------
__global__ void k_init(const float* __restrict__ proj)
{
    int idx = blockIdx.x * 256 + threadIdx.x;   // 64 blocks x 256
    if (idx < 256 * 64) {
        float v = proj[idx] * DN;               // [m][d] layout preserved
        __nv_bfloat16 h = __float2bfloat16(v);
        g_pbh[idx] = h;
        g_pbl[idx] = __float2bfloat16(v - __bfloat162float(h));
    }
    if (idx < NH) g_kmax[idx] = 0u;
}

// ---------------- K_proj (HMMA): u = x . P^T per 64-token block ------------
// grid (128, 32), block 256 (8 warps). Warp tile: 16 tokens x 128 features.
#define OFF_AH   0
#define OFF_AL   9216
#define OFF_PH   18432
#define OFF_PL   55296
#define OFF_SQP  92160
#define OFF_SQ   93184
#define OFF_SMAX 93440
#define PROJ_SMEM 94208

template <bool IS_QUERY>
__global__ void __launch_bounds__(256, 2) k_proj_mma(const float* __restrict__ x)
{
    extern __shared__ char smem[];
    char* Ah = smem + OFF_AH;       // [64 tok][72 bf16]
    char* Al = smem + OFF_AL;
    char* Ph = smem + OFF_PH;       // [256 feat][72 bf16]
    char* Pl = smem + OFF_PL;
    float* sqp  = (float*)(smem + OFF_SQP);   // [64][4]
    float* sq   = (float*)(smem + OFF_SQ);    // [64]
    float* smax = (float*)(smem + OFF_SMAX);  // [2][64] (query) / red[8] (key)

    const int t = threadIdx.x;
    const int head = blockIdx.y;
    const int n0 = blockIdx.x * 64;

    // ---- stage A: x[d][tok] -> Ah/Al[tok][d] bf16 pairs + partial sumsq ----
    {
        const int tok = t & 63, dblk = t >> 6;
        const float* xp = x + (size_t)head * Dd * Nn + n0 + tok;
        float s = 0.0f;
        #pragma unroll
        for (int i = 0; i < 8; i++) {
            int d = dblk * 16 + 2 * i;
            float v0 = xp[(size_t)d * Nn];
            float v1 = xp[(size_t)(d + 1) * Nn];
            s = fmaf(v0, v0, fmaf(v1, v1, s));
            unsigned ph, pl;
            split2(v0, v1, ph, pl);
            *(unsigned*)(Ah + tok * 144 + d * 2) = ph;
            *(unsigned*)(Al + tok * 144 + d * 2) = pl;
        }
        sqp[tok * 4 + dblk] = s;
    }
    // ---- stage P ----
    #pragma unroll
    for (int cc = 0; cc < 8; cc++) {
        int e = t + 256 * cc;           // < 2048
        int row = e >> 3, j = e & 7;
        *(uint4*)(Ph + row * 144 + j * 16) = ((const uint4*)g_pbh)[e];
        *(uint4*)(Pl + row * 144 + j * 16) = ((const uint4*)g_pbl)[e];
    }
    __syncthreads();
    if (t < 64) sq[t] = sqp[4*t] + sqp[4*t+1] + sqp[4*t+2] + sqp[4*t+3];

    const int w = t >> 5, lane = t & 31;
    const int g = lane >> 2, tq = lane & 3;
    const int tb = (w & 3) * 16;            // token base
    const int fb = (w >> 2) * 128;          // feature base

    float c[16][4];
    #pragma unroll
    for (int nt = 0; nt < 16; nt++)
        #pragma unroll
        for (int j = 0; j < 4; j++) c[nt][j] = 0.0f;

    #pragma unroll
    for (int k = 0; k < 4; k++) {
        const int koff = k * 16;
        unsigned ah[4], al[4];
        ah[0] = *(const unsigned*)(Ah + (tb + g)     * 144 + (koff + 2*tq) * 2);
        ah[1] = *(const unsigned*)(Ah + (tb + g + 8) * 144 + (koff + 2*tq) * 2);
        ah[2] = *(const unsigned*)(Ah + (tb + g)     * 144 + (koff + 8 + 2*tq) * 2);
        ah[3] = *(const unsigned*)(Ah + (tb + g + 8) * 144 + (koff + 8 + 2*tq) * 2);
        al[0] = *(const unsigned*)(Al + (tb + g)     * 144 + (koff + 2*tq) * 2);
        al[1] = *(const unsigned*)(Al + (tb + g + 8) * 144 + (koff + 2*tq) * 2);
        al[2] = *(const unsigned*)(Al + (tb + g)     * 144 + (koff + 8 + 2*tq) * 2);
        al[3] = *(const unsigned*)(Al + (tb + g + 8) * 144 + (koff + 8 + 2*tq) * 2);
        #pragma unroll
        for (int nt = 0; nt < 16; nt++) {
            const char* prow_h = Ph + (fb + nt * 8 + g) * 144 + (koff + 2*tq) * 2;
            const char* prow_l = Pl + (fb + nt * 8 + g) * 144 + (koff + 2*tq) * 2;
            unsigned bh0 = *(const unsigned*)(prow_h);
            unsigned bh1 = *(const unsigned*)(prow_h + 16);
            unsigned bl0 = *(const unsigned*)(prow_l);
            unsigned bl1 = *(const unsigned*)(prow_l + 16);
            mma16816(c[nt], ah, bh0, bh1);
            mma16816(c[nt], ah, bl0, bl1);
            mma16816(c[nt], al, bh0, bh1);
        }
    }

    const int tl0 = tb + g, tl1 = tb + g + 8;
    const float dg0 = sq[tl0] * DIAGC;
    const float dg1 = sq[tl1] * DIAGC;

    if (!IS_QUERY) {
        // block max of raw u
        float bm = -3.4e38f;
        #pragma unroll
        for (int nt = 0; nt < 16; nt++)
            bm = fmaxf(bm, fmaxf(fmaxf(c[nt][0], c[nt][1]), fmaxf(c[nt][2], c[nt][3])));
        #pragma unroll
        for (int o = 16; o; o >>= 1) bm = fmaxf(bm, __shfl_xor_sync(0xffffffffu, bm, o));
        float* red = smax;
        if (lane == 0) red[w] = bm;
        __syncthreads();                 // also: all MMA smem reads done
        float Mb = red[0];
        #pragma unroll
        for (int r2 = 1; r2 < 8; r2++) Mb = fmaxf(Mb, red[r2]);
        if (t == 0) {
            atomicMax(g_kmax + head, fkey(Mb));
            g_bmax[head * 128 + blockIdx.x] = Mb;
        }

        // e = exp(u - diag - Mb) into Tr [256 m][68 tok]
        float* Tr = (float*)(smem + OFF_PH);
        #pragma unroll
        for (int nt = 0; nt < 16; nt++) {
            int m = fb + nt * 8 + 2 * tq;
            Tr[m * 68 + tl0]       = fexp(c[nt][0] - dg0 - Mb);
            Tr[(m + 1) * 68 + tl0] = fexp(c[nt][1] - dg0 - Mb);
            Tr[m * 68 + tl1]       = fexp(c[nt][2] - dg1 - Mb);
            Tr[(m + 1) * 68 + tl1] = fexp(c[nt][3] - dg1 - Mb);
        }
        __syncthreads();
        // writeout: bf16-split pairs along n -> g_k2[h][m][n/2]
        const int q = t & 7;
        #pragma unroll
        for (int p = 0; p < 8; p++) {
            int m = (t >> 3) + 32 * p;
            const float* row = Tr + m * 68 + 8 * q;
            unsigned h0, l0, h1, l1, h2, l2, h3, l3;
            split2(row[0], row[1], h0, l0);
            split2(row[2], row[3], h1, l1);
            split2(row[4], row[5], h2, l2);
            split2(row[6], row[7], h3, l3);
            uint4* dst = (uint4*)(g_k2 + ((size_t)(head * Mm + m)) * (Nn/2) + n0/2 + 4*q);
            dst[0] = make_uint4(h0, l0, h1, l1);
            dst[1] = make_uint4(h2, l2, h3, l3);
        }
    } else {
        // per-token max over features (two halves combined via smem)
        float m0 = -3.4e38f, m1 = -3.4e38f;
        #pragma unroll
        for (int nt = 0; nt < 16; nt++) {
            m0 = fmaxf(m0, fmaxf(c[nt][0], c[nt][1]));
            m1 = fmaxf(m1, fmaxf(c[nt][2], c[nt][3]));
        }
        m0 = fmaxf(m0, __shfl_xor_sync(0xffffffffu, m0, 1));
        m0 = fmaxf(m0, __shfl_xor_sync(0xffffffffu, m0, 2));
        m1 = fmaxf(m1, __shfl_xor_sync(0xffffffffu, m1, 1));
        m1 = fmaxf(m1, __shfl_xor_sync(0xffffffffu, m1, 2));
        if (tq == 0) {
            smax[(w >> 2) * 64 + tl0] = m0;
            smax[(w >> 2) * 64 + tl1] = m1;
        }
        __syncthreads();
        const float cc0 = -dg0 - fmaxf(smax[tl0], smax[64 + tl0]);
        const float cc1 = -dg1 - fmaxf(smax[tl1], smax[64 + tl1]);
        unsigned* Trh = (unsigned*)(smem + OFF_PH);   // [64 tok][132 u32]
        unsigned* Trl = Trh + 64 * 132;
        #pragma unroll
        for (int nt = 0; nt < 16; nt++) {
            int m = fb + nt * 8 + 2 * tq;
            float p0 = RATIO * fexp(c[nt][0] + cc0) + REPS;
            float p1 = RATIO * fexp(c[nt][1] + cc0) + REPS;
            float p2 = RATIO * fexp(c[nt][2] + cc1) + REPS;
            float p3 = RATIO * fexp(c[nt][3] + cc1) + REPS;
            unsigned ph, pl;
            split2(p0, p1, ph, pl);
            Trh[tl0 * 132 + (m >> 1)] = ph;
            Trl[tl0 * 132 + (m >> 1)] = pl;
            split2(p2, p3, ph, pl);
            Trh[tl1 * 132 + (m >> 1)] = ph;
            Trl[tl1 * 132 + (m >> 1)] = pl;
        }
        __syncthreads();
        const int tok = t >> 2, q = t & 3;
        uint4* dh = (uint4*)(g_qh + ((size_t)head * Nn + n0 + tok) * Mm);
        uint4* dl = (uint4*)(g_ql + ((size_t)head * Nn + n0 + tok) * Mm);
        const uint4* sh = (const uint4*)(Trh + tok * 132 + q * 32);
        const uint4* sl = (const uint4*)(Trl + tok * 132 + q * 32);
        #pragma unroll
        for (int j = 0; j < 8; j++) {
            dh[q * 8 + j] = sh[j];
            dl[q * 8 + j] = sl[j];
        }
    }
}

// ---------------- K_vsum: R[h][d] = sum_n V ----------------
__global__ void k_vsum(const float* __restrict__ value)
{
    __shared__ float red[8];
    const int h = blockIdx.y, d = blockIdx.x, t = threadIdx.x;
    const float4* src = (const float4*)(value + ((size_t)h * 64 + d) * Nn);
    float s = 0.0f;
    #pragma unroll
    for (int i = 0; i < 8; i++) {
        float4 v = src[t + 256 * i];
        s += (v.x + v.y) + (v.z + v.w);
    }
    #pragma unroll
    for (int o = 16; o; o >>= 1) s += __shfl_xor_sync(0xffffffffu, s, o);
    if ((t & 31) == 0) red[t >> 5] = s;
    __syncthreads();
    if (t == 0) {
        float r = 0.0f;
        #pragma unroll
        for (int w2 = 0; w2 < 8; w2++) r += red[w2];
        g_vsum[h * 64 + d] = r;
    }
}

// ---------------- K2 (HMMA): kv partials = E . V'^T (knorm col) ------------
// grid (16 slices, 32 heads), block 256 (8 warps). Warp tile 64m x 40d.
// A staging = pure pair copy; scale s folded into V.
#define KV_AH  0
#define KV_AL  36864
#define KV_VH  73728
#define KV_VL  85248
#define KV_SMEM 96768

__global__ void __launch_bounds__(256, 1) k_kv_mma(const float* __restrict__ value)
{
    extern __shared__ char smem[];
    char* Ah = smem + KV_AH;   // [256 m][72 bf16] (144 B rows)
    char* Al = smem + KV_AL;
    char* Vh = smem + KV_VH;   // [80 d][72 bf16]
    char* Vl = smem + KV_VL;

    const int t = threadIdx.x;
    const int head = blockIdx.y;
    const int slice = blockIdx.x;
    const float kmax = finv(g_kmax[head]);

    const int w = t >> 5, lane = t & 31;
    const int g = lane >> 2, tq = lane & 3;
    const int mg = (w & 3) * 64;
    const int dgr = (w >> 2) * 40;

    // V pad rows 65..79 = 0 (row 64 set per chunk)
    for (int e = t; e < 540; e += 256) {
        int row = 65 + e / 36, col = e % 36;
        ((unsigned*)(Vh + row * 144))[col] = 0u;
        ((unsigned*)(Vl + row * 144))[col] = 0u;
    }

    float c[4][5][4];
    #pragma unroll
    for (int mt = 0; mt < 4; mt++)
        #pragma unroll
        for (int dt = 0; dt < 5; dt++)
            #pragma unroll
            for (int j = 0; j < 4; j++) c[mt][dt][j] = 0.0f;

    const float* vp = value + (size_t)head * Dd * Nn;

    for (int ch = 0; ch < 8; ch++) {
        const int n0 = slice * 512 + ch * 64;
        const float s_ch = fexp(g_bmax[head * 128 + slice * 8 + ch] - kmax);
        __syncthreads();   // previous MMA reads complete

        // stage A: straight pair copy from g_k2
        {
            const int q = t & 7;
            const u64* kb = g_k2 + (size_t)(head * Mm) * (Nn/2) + n0/2;
            #pragma unroll
            for (int r = 0; r < 8; r++) {
                int m = (t >> 3) + 32 * r;
                const uint4* src = (const uint4*)(kb + (size_t)m * (Nn/2) + 4 * q);
                uint4 a = src[0], b = src[1];
                *(uint2*)(Ah + m * 144 + 16*q)     = make_uint2(a.x, a.z);
                *(uint2*)(Al + m * 144 + 16*q)     = make_uint2(a.y, a.w);
                *(uint2*)(Ah + m * 144 + 16*q + 8) = make_uint2(b.x, b.z);
                *(uint2*)(Al + m * 144 + 16*q + 8) = make_uint2(b.y, b.w);
            }
        }
        // row 64 = s_ch (scaled ones -> knorm)
        if (t < 36) {
            unsigned shh, sll;
            split2(s_ch, s_ch, shh, sll);
            ((unsigned*)(Vh + 64 * 144))[t] = shh;
            ((unsigned*)(Vl + 64 * 144))[t] = sll;
        }
        // stage V: [d][n] rows scaled by s_ch
        {
            int d = t >> 2, q = t & 3;
            const float* src = vp + (size_t)d * Nn + n0 + q * 16;
            unsigned* rowh = (unsigned*)(Vh + d * 144 + q * 32);
            unsigned* rowl = (unsigned*)(Vl + d * 144 + q * 32);
            #pragma unroll
            for (int i = 0; i < 4; i++) {
                float4 v = *(const float4*)(src + 4 * i);
                unsigned ph, pl;
                split2(v.x * s_ch, v.y * s_ch, ph, pl);
                rowh[2 * i] = ph;  rowl[2 * i] = pl;
                split2(v.z * s_ch, v.w * s_ch, ph, pl);
                rowh[2 * i + 1] = ph;  rowl[2 * i + 1] = pl;
            }
        }
        __syncthreads();

        #pragma unroll
        for (int k = 0; k < 4; k++) {
            const int koff = k * 16;
            unsigned ah[4][4], al[4][4];
            #pragma unroll
            for (int mt = 0; mt < 4; mt++) {
                int r0 = mg + mt * 16 + g, r1 = r0 + 8;
                ah[mt][0] = *(const unsigned*)(Ah + r0 * 144 + (koff + 2*tq) * 2);
                ah[mt][1] = *(const unsigned*)(Ah + r1 * 144 + (koff + 2*tq) * 2);
                ah[mt][2] = *(const unsigned*)(Ah + r0 * 144 + (koff + 8 + 2*tq) * 2);
                ah[mt][3] = *(const unsigned*)(Ah + r1 * 144 + (koff + 8 + 2*tq) * 2);
                al[mt][0] = *(const unsigned*)(Al + r0 * 144 + (koff + 2*tq) * 2);
                al[mt][1] = *(const unsigned*)(Al + r1 * 144 + (koff + 2*tq) * 2);
                al[mt][2] = *(const unsigned*)(Al + r0 * 144 + (koff + 8 + 2*tq) * 2);
                al[mt][3] = *(const unsigned*)(Al + r1 * 144 + (koff + 8 + 2*tq) * 2);
            }
            #pragma unroll
            for (int dt = 0; dt < 5; dt++) {
                const char* rh = Vh + (dgr + dt * 8 + g) * 144 + (koff + 2*tq) * 2;
                const char* rl = Vl + (dgr + dt * 8 + g) * 144 + (koff + 2*tq) * 2;
                unsigned bh0 = *(const unsigned*)(rh);
                unsigned bh1 = *(const unsigned*)(rh + 16);
                unsigned bl0 = *(const unsigned*)(rl);
                unsigned bl1 = *(const unsigned*)(rl + 16);
                #pragma unroll
                for (int mt = 0; mt < 4; mt++) {
                    mma16816(c[mt][dt], ah[mt], bh0, bh1);
                    mma16816(c[mt][dt], ah[mt], bl0, bl1);
                    mma16816(c[mt][dt], al[mt], bh0, bh1);
                }
            }
        }
    }

    // write partials [d][m]
    float* dst = g_kvpart + (size_t)(head * 16 + slice) * 20480;
    #pragma unroll
    for (int mt = 0; mt < 4; mt++) {
        int m0 = mg + mt * 16 + g, m1 = m0 + 8;
        #pragma unroll
        for (int dt = 0; dt < 5; dt++) {
            int d0 = dgr + dt * 8 + 2 * tq;
            dst[d0 * 256 + m0]       = c[mt][dt][0];
            dst[(d0 + 1) * 256 + m0] = c[mt][dt][1];
            dst[d0 * 256 + m1]       = c[mt][dt][2];
            dst[(d0 + 1) * 256 + m1] = c[mt][dt][3];
        }
    }
}

// ---------------- K3: reduce partials -> bf16-split kv^T (with eps corr) ---
__global__ void k_reduce()
{
    int idx = blockIdx.x * 256 + threadIdx.x;   // < 32*80*256 = 655360
    int h = idx / 20480;
    int rem = idx - h * 20480;
    int d = rem >> 8;
    float s = 0.0f;
    #pragma unroll
    for (int sl = 0; sl < 16; sl++)
        s += g_kvpart[(size_t)(h * 16 + sl) * 20480 + rem];
    float corr = (d < 64) ? REPS * g_vsum[h * 64 + d]
               : (d == 64 ? REPS * 8192.0f : 0.0f);
    float val = fmaf(RATIO, s, corr);
    __nv_bfloat16 hi = __float2bfloat16(val);
    g_kvth[idx] = hi;
    g_kvtl[idx] = __float2bfloat16(val - __bfloat162float(hi));
}

// ---------------- K4 (HMMA): out = phi_q . kv, divide by norm col ----------
// grid (128, 32), block 256 (8 warps). 64 tokens x 80 d. Warp: 16 tok x 40 d.
#define QO_QH 0
#define QO_QL 33792
#define QO_KH 67584
#define QO_KL 109824
#define QO_SN 152064
#define QO_SMEM 152320

__global__ void __launch_bounds__(256, 1) k_out_mma(float* __restrict__ out)
{
    extern __shared__ char smem[];
    char* Qh = smem + QO_QH;   // [64 tok][264 bf16] (528 B rows)
    char* Ql = smem + QO_QL;
    char* Kh = smem + QO_KH;   // [80 d][264 bf16]
    char* Kl = smem + QO_KL;
    float* sn = (float*)(smem + QO_SN);   // [64]

    const int t = threadIdx.x;
    const int head = blockIdx.y;
    const int n0 = blockIdx.x * 64;

    // stage phi_q (hi/lo)
    {
        int tok = t >> 2, q = t & 3;
        const uint4* sh = (const uint4*)(g_qh + ((size_t)head * Nn + n0 + tok) * Mm + q * 64);
        const uint4* sl = (const uint4*)(g_ql + ((size_t)head * Nn + n0 + tok) * Mm + q * 64);
        uint4* dh = (uint4*)(Qh + tok * 528 + q * 128);
        uint4* dl = (uint4*)(Ql + tok * 528 + q * 128);
        #pragma unroll
        for (int j = 0; j < 8; j++) { dh[j] = sh[j]; dl[j] = sl[j]; }
    }
    // stage kv^T (hi/lo), 80 rows
    #pragma unroll
    for (int r = 0; r < 2; r++) {
        int e = t + 256 * r;
        if (e < 320) {
            int row = e >> 2, q = e & 3;
            const uint4* sh = (const uint4*)(g_kvth + ((size_t)head * 80 + row) * 256 + q * 64);
            const uint4* sl = (const uint4*)(g_kvtl + ((size_t)head * 80 + row) * 256 + q * 64);
            uint4* dh = (uint4*)(Kh + row * 528 + q * 128);
            uint4* dl = (uint4*)(Kl + row * 528 + q * 128);
            #pragma unroll
            for (int j = 0; j < 8; j++) { dh[j] = sh[j]; dl[j] = sl[j]; }
        }
    }
    __syncthreads();

    const int w = t >> 5, lane = t & 31;
    const int g = lane >> 2, tq = lane & 3;
    const int tg = (w & 3) * 16;
    const int dgr = (w >> 2) * 40;

    float c[5][4];
    #pragma unroll
    for (int dt = 0; dt < 5; dt++)
        #pragma unroll
        for (int j = 0; j < 4; j++) c[dt][j] = 0.0f;

    #pragma unroll
    for (int kc = 0; kc < 16; kc++) {
        const int koff = kc * 16;
        unsigned ah[4], al[4];
        ah[0] = *(const unsigned*)(Qh + (tg + g)     * 528 + (koff + 2*tq) * 2);
        ah[1] = *(const unsigned*)(Qh + (tg + g + 8) * 528 + (koff + 2*tq) * 2);
        ah[2] = *(const unsigned*)(Qh + (tg + g)     * 528 + (koff + 8 + 2*tq) * 2);
        ah[3] = *(const unsigned*)(Qh + (tg + g + 8) * 528 + (koff + 8 + 2*tq) * 2);
        al[0] = *(const unsigned*)(Ql + (tg + g)     * 528 + (koff + 2*tq) * 2);
        al[1] = *(const unsigned*)(Ql + (tg + g + 8) * 528 + (koff + 2*tq) * 2);
        al[2] = *(const unsigned*)(Ql + (tg + g)     * 528 + (koff + 8 + 2*tq) * 2);
        al[3] = *(const unsigned*)(Ql + (tg + g + 8) * 528 + (koff + 8 + 2*tq) * 2);
        #pragma unroll
        for (int dt = 0; dt < 5; dt++) {
            const char* rh = Kh + (dgr + dt * 8 + g) * 528 + (koff + 2*tq) * 2;
            const char* rl = Kl + (dgr + dt * 8 + g) * 528 + (koff + 2*tq) * 2;
            unsigned bh0 = *(const unsigned*)(rh);
            unsigned bh1 = *(const unsigned*)(rh + 16);
            unsigned bl0 = *(const unsigned*)(rl);
            unsigned bl1 = *(const unsigned*)(rl + 16);
            mma16816(c[dt], ah, bh0, bh1);
            mma16816(c[dt], ah, bl0, bl1);
            mma16816(c[dt], al, bh0, bh1);
        }
    }

    // norm column (d = 64) held by warps w>=4, dt=3, tq==0
    if (w >= 4 && tq == 0) {
        sn[tg + g]     = c[3][0];
        sn[tg + g + 8] = c[3][2];
    }
    __syncthreads();
    const float rn0 = 1.0f / sn[tg + g];
    const float rn1 = 1.0f / sn[tg + g + 8];

    float* op = out + (size_t)head * Dd * Nn + n0;
    #pragma unroll
    for (int dt = 0; dt < 5; dt++) {
        int d0 = dgr + dt * 8 + 2 * tq;
        if (d0 < 64) {
            op[(size_t)d0 * Nn + tg + g]           = c[dt][0] * rn0;
            op[(size_t)(d0 + 1) * Nn + tg + g]     = c[dt][1] * rn0;
            op[(size_t)d0 * Nn + tg + g + 8]       = c[dt][2] * rn1;
            op[(size_t)(d0 + 1) * Nn + tg + g + 8] = c[dt][3] * rn1;
        }
    }
}

// ---------------- launch ----------------
extern "C" void kernel_launch(void* const* d_in, const int* in_sizes, int n_in,
                              void* d_out, int out_size)
{
    const float* query = (const float*)d_in[0];
    const float* key   = (const float*)d_in[1];
    const float* value = (const float*)d_in[2];
    const float* proj  = (const float*)d_in[3];
    float* out = (float*)d_out;

    cudaFuncSetAttribute(k_proj_mma<false>, cudaFuncAttributeMaxDynamicSharedMemorySize, PROJ_SMEM);
    cudaFuncSetAttribute(k_proj_mma<true>,  cudaFuncAttributeMaxDynamicSharedMemorySize, PROJ_SMEM);
    cudaFuncSetAttribute(k_kv_mma,  cudaFuncAttributeMaxDynamicSharedMemorySize, KV_SMEM);
    cudaFuncSetAttribute(k_out_mma, cudaFuncAttributeMaxDynamicSharedMemorySize, QO_SMEM);

    k_init<<<64, 256>>>(proj);
    k_proj_mma<false><<<dim3(128, 32), 256, PROJ_SMEM>>>(key);
    k_proj_mma<true><<<dim3(128, 32), 256, PROJ_SMEM>>>(query);
    k_vsum<<<dim3(64, 32), 256>>>(value);
    k_kv_mma<<<dim3(16, 32), 256, KV_SMEM>>>(value);
    k_reduce<<<2560, 256>>>();
    k_out_mma<<<dim3(128, 32), 256, QO_SMEM>>>(out);
}

// round 10
// speedup vs baseline: 1.1198x; 1.0041x over previous
#include <cuda_runtime.h>
#include <cuda_bf16.h>
#include <math.h>

#define Dd 64
#define Nn 8192
#define Mm 256
#define NH 32
#define DN     0.3535533905932738f   /* 64^-0.25 */
#define RATIO  0.0625f               /* 256^-0.5 */
#define REPS   6.25e-8f              /* RATIO * 1e-6 */
#define DIAGC  0.0625f               /* DN^2 * 0.5 */

typedef unsigned long long u64;

// ---------------- scratch (device globals; no allocation) ----------------
__device__ u64   g_k2[(size_t)NH * Mm * (Nn / 2)];      // e=exp(u-diag-Mblk) (hi,lo) pairs, [h][m][n/2]
__device__ __nv_bfloat16 g_qh[(size_t)NH * Nn * Mm];    // phi_q hi, [h][tok][m]
__device__ __nv_bfloat16 g_ql[(size_t)NH * Nn * Mm];    // phi_q lo
__device__ unsigned g_kmax[NH];                         // per-head max(raw u), ordered key
__device__ float g_bmax[NH * 128];                      // per (head, 64-token block) max raw u
__device__ float g_vsum[NH * 64];                       // R[h][d] = sum_n V
__device__ float g_kvpart[(size_t)NH * 16 * 80 * 256];  // [h*16+sl][d][m]
__device__ __nv_bfloat16 g_kvth[(size_t)NH * 80 * 256]; // kv^T hi, [h][d][m] (d=64 -> knorm)
__device__ __nv_bfloat16 g_kvtl[(size_t)NH * 80 * 256]; // kv^T lo
__device__ __align__(16) __nv_bfloat16 g_pbh[256 * 64]; // proj*DN hi, [m][d]
__device__ __align__(16) __nv_bfloat16 g_pbl[256 * 64]; // proj*DN lo

// order-preserving float<->uint key
static __device__ __forceinline__ unsigned fkey(float f) {
    unsigned b = __float_as_uint(f);
    return (b & 0x80000000u) ? ~b : (b | 0x80000000u);
}
static __device__ __forceinline__ float finv(unsigned k) {
    return __uint_as_float((k & 0x80000000u) ? (k & 0x7fffffffu) : ~k);
}

// branch-free exp on FMA/ALU pipes. Valid for x <= 0, ~2.4e-6 rel err.
static __device__ __forceinline__ float fexp(float x) {
    float t = x * 1.4426950408889634f;
    t = fmaxf(t, -125.0f);
    float r  = t + 12582912.0f;
    float fi = r - 12582912.0f;
    float f  = t - fi;
    float p = 1.3333558e-3f;
    p = fmaf(p, f, 9.6181291e-3f);
    p = fmaf(p, f, 5.5504109e-2f);
    p = fmaf(p, f, 2.4022651e-1f);
    p = fmaf(p, f, 6.9314718e-1f);
    p = fmaf(p, f, 1.0f);
    int ib = __float_as_int(r) - 0x4B400000;
    float s = __int_as_float((ib + 127) << 23);
    return p * s;
}

// HMMA m16n8k16 bf16 -> fp32 accum
static __device__ __forceinline__ void mma16816(float c[4], const unsigned a[4],
                                                unsigned b0, unsigned b1) {
    asm volatile(
        "mma.sync.aligned.m16n8k16.row.col.f32.bf16.bf16.f32 "
        "{%0,%1,%2,%3}, {%4,%5,%6,%7}, {%8,%9}, {%0,%1,%2,%3};"
        : "+f"(c[0]), "+f"(c[1]), "+f"(c[2]), "+f"(c[3])
        : "r"(a[0]), "r"(a[1]), "r"(a[2]), "r"(a[3]), "r"(b0), "r"(b1));
}

// bf16 hi/lo split, packing pairs (v0,v1) -> (hi-pair, lo-pair)
static __device__ __forceinline__ void split2(float v0, float v1, unsigned& ph, unsigned& pl) {
    __nv_bfloat16 h0 = __float2bfloat16(v0);
    __nv_bfloat16 h1 = __float2bfloat16(v1);
    __nv_bfloat16 l0 = __float2bfloat16(v0 - __bfloat162float(h0));
    __nv_bfloat16 l1 = __float2bfloat16(v1 - __bfloat162float(h1));
    ph = ((unsigned)__bfloat16_as_ushort(h1) << 16) | __bfloat16_as_ushort(h0);
    pl = ((unsigned)__bfloat16_as_ushort(l1) << 16) | __bfloat16_as_ushort(l0);
}

// ---------------- K0: bf16-split scaled proj + reset kmax ----------------
__global__ void k_init(const float* __restrict__ proj)
{
    int idx = blockIdx.x * 256 + threadIdx.x;   // 64 blocks x 256
    if (idx < 256 * 64) {
        float v = proj[idx] * DN;               // [m][d] layout preserved
        __nv_bfloat16 h = __float2bfloat16(v);
        g_pbh[idx] = h;
        g_pbl[idx] = __float2bfloat16(v - __bfloat162float(h));
    }
    if (idx < NH) g_kmax[idx] = 0u;
}

// ---------------- K_proj (HMMA): u = x . P^T per 64-token block ------------
// grid (128, 32), block 256 (8 warps). Warp tile: 16 tokens x 128 features.
#define OFF_AH   0
#define OFF_AL   9216
#define OFF_PH   18432
#define OFF_PL   55296
#define OFF_SQP  92160
#define OFF_SQ   93184
#define OFF_SMAX 93440
#define PROJ_SMEM 94208

template <bool IS_QUERY>
__global__ void __launch_bounds__(256, 2) k_proj_mma(const float* __restrict__ x)
{
    extern __shared__ char smem[];
    char* Ah = smem + OFF_AH;       // [64 tok][72 bf16]
    char* Al = smem + OFF_AL;
    char* Ph = smem + OFF_PH;       // [256 feat][72 bf16]
    char* Pl = smem + OFF_PL;
    float* sqp  = (float*)(smem + OFF_SQP);   // [64][4]
    float* sq   = (float*)(smem + OFF_SQ);    // [64]
    float* smax = (float*)(smem + OFF_SMAX);  // [2][64] (query) / red[8] (key)

    const int t = threadIdx.x;
    const int head = blockIdx.y;
    const int n0 = blockIdx.x * 64;

    // ---- stage A: x[d][tok] -> Ah/Al[tok][d] bf16 pairs + partial sumsq ----
    {
        const int tok = t & 63, dblk = t >> 6;
        const float* xp = x + (size_t)head * Dd * Nn + n0 + tok;
        float s = 0.0f;
        #pragma unroll
        for (int i = 0; i < 8; i++) {
            int d = dblk * 16 + 2 * i;
            float v0 = xp[(size_t)d * Nn];
            float v1 = xp[(size_t)(d + 1) * Nn];
            s = fmaf(v0, v0, fmaf(v1, v1, s));
            unsigned ph, pl;
            split2(v0, v1, ph, pl);
            *(unsigned*)(Ah + tok * 144 + d * 2) = ph;
            *(unsigned*)(Al + tok * 144 + d * 2) = pl;
        }
        sqp[tok * 4 + dblk] = s;
    }
    // ---- stage P ----
    #pragma unroll
    for (int cc = 0; cc < 8; cc++) {
        int e = t + 256 * cc;           // < 2048
        int row = e >> 3, j = e & 7;
        *(uint4*)(Ph + row * 144 + j * 16) = ((const uint4*)g_pbh)[e];
        *(uint4*)(Pl + row * 144 + j * 16) = ((const uint4*)g_pbl)[e];
    }
    __syncthreads();
    if (t < 64) sq[t] = sqp[4*t] + sqp[4*t+1] + sqp[4*t+2] + sqp[4*t+3];

    const int w = t >> 5, lane = t & 31;
    const int g = lane >> 2, tq = lane & 3;
    const int tb = (w & 3) * 16;            // token base
    const int fb = (w >> 2) * 128;          // feature base

    float c[16][4];
    #pragma unroll
    for (int nt = 0; nt < 16; nt++)
        #pragma unroll
        for (int j = 0; j < 4; j++) c[nt][j] = 0.0f;

    #pragma unroll
    for (int k = 0; k < 4; k++) {
        const int koff = k * 16;
        unsigned ah[4], al[4];
        ah[0] = *(const unsigned*)(Ah + (tb + g)     * 144 + (koff + 2*tq) * 2);
        ah[1] = *(const unsigned*)(Ah + (tb + g + 8) * 144 + (koff + 2*tq) * 2);
        ah[2] = *(const unsigned*)(Ah + (tb + g)     * 144 + (koff + 8 + 2*tq) * 2);
        ah[3] = *(const unsigned*)(Ah + (tb + g + 8) * 144 + (koff + 8 + 2*tq) * 2);
        al[0] = *(const unsigned*)(Al + (tb + g)     * 144 + (koff + 2*tq) * 2);
        al[1] = *(const unsigned*)(Al + (tb + g + 8) * 144 + (koff + 2*tq) * 2);
        al[2] = *(const unsigned*)(Al + (tb + g)     * 144 + (koff + 8 + 2*tq) * 2);
        al[3] = *(const unsigned*)(Al + (tb + g + 8) * 144 + (koff + 8 + 2*tq) * 2);
        #pragma unroll
        for (int nt = 0; nt < 16; nt++) {
            const char* prow_h = Ph + (fb + nt * 8 + g) * 144 + (koff + 2*tq) * 2;
            const char* prow_l = Pl + (fb + nt * 8 + g) * 144 + (koff + 2*tq) * 2;
            unsigned bh0 = *(const unsigned*)(prow_h);
            unsigned bh1 = *(const unsigned*)(prow_h + 16);
            unsigned bl0 = *(const unsigned*)(prow_l);
            unsigned bl1 = *(const unsigned*)(prow_l + 16);
            mma16816(c[nt], ah, bh0, bh1);
            mma16816(c[nt], ah, bl0, bl1);
            mma16816(c[nt], al, bh0, bh1);
        }
    }

    const int tl0 = tb + g, tl1 = tb + g + 8;
    const float dg0 = sq[tl0] * DIAGC;
    const float dg1 = sq[tl1] * DIAGC;

    if (!IS_QUERY) {
        // block max of raw u
        float bm = -3.4e38f;
        #pragma unroll
        for (int nt = 0; nt < 16; nt++)
            bm = fmaxf(bm, fmaxf(fmaxf(c[nt][0], c[nt][1]), fmaxf(c[nt][2], c[nt][3])));
        #pragma unroll
        for (int o = 16; o; o >>= 1) bm = fmaxf(bm, __shfl_xor_sync(0xffffffffu, bm, o));
        float* red = smax;
        if (lane == 0) red[w] = bm;
        __syncthreads();                 // also: all MMA smem reads done
        float Mb = red[0];
        #pragma unroll
        for (int r2 = 1; r2 < 8; r2++) Mb = fmaxf(Mb, red[r2]);
        if (t == 0) {
            atomicMax(g_kmax + head, fkey(Mb));
            g_bmax[head * 128 + blockIdx.x] = Mb;
        }

        // e = exp(u - diag - Mb) into Tr [256 m][68 tok]
        float* Tr = (float*)(smem + OFF_PH);
        #pragma unroll
        for (int nt = 0; nt < 16; nt++) {
            int m = fb + nt * 8 + 2 * tq;
            Tr[m * 68 + tl0]       = fexp(c[nt][0] - dg0 - Mb);
            Tr[(m + 1) * 68 + tl0] = fexp(c[nt][1] - dg0 - Mb);
            Tr[m * 68 + tl1]       = fexp(c[nt][2] - dg1 - Mb);
            Tr[(m + 1) * 68 + tl1] = fexp(c[nt][3] - dg1 - Mb);
        }
        __syncthreads();
        // writeout: bf16-split pairs along n -> g_k2[h][m][n/2]
        const int q = t & 7;
        #pragma unroll
        for (int p = 0; p < 8; p++) {
            int m = (t >> 3) + 32 * p;
            const float* row = Tr + m * 68 + 8 * q;
            unsigned h0, l0, h1, l1, h2, l2, h3, l3;
            split2(row[0], row[1], h0, l0);
            split2(row[2], row[3], h1, l1);
            split2(row[4], row[5], h2, l2);
            split2(row[6], row[7], h3, l3);
            uint4* dst = (uint4*)(g_k2 + ((size_t)(head * Mm + m)) * (Nn/2) + n0/2 + 4*q);
            dst[0] = make_uint4(h0, l0, h1, l1);
            dst[1] = make_uint4(h2, l2, h3, l3);
        }
    } else {
        // per-token max over features (two halves combined via smem)
        float m0 = -3.4e38f, m1 = -3.4e38f;
        #pragma unroll
        for (int nt = 0; nt < 16; nt++) {
            m0 = fmaxf(m0, fmaxf(c[nt][0], c[nt][1]));
            m1 = fmaxf(m1, fmaxf(c[nt][2], c[nt][3]));
        }
        m0 = fmaxf(m0, __shfl_xor_sync(0xffffffffu, m0, 1));
        m0 = fmaxf(m0, __shfl_xor_sync(0xffffffffu, m0, 2));
        m1 = fmaxf(m1, __shfl_xor_sync(0xffffffffu, m1, 1));
        m1 = fmaxf(m1, __shfl_xor_sync(0xffffffffu, m1, 2));
        if (tq == 0) {
            smax[(w >> 2) * 64 + tl0] = m0;
            smax[(w >> 2) * 64 + tl1] = m1;
        }
        __syncthreads();
        const float cc0 = -dg0 - fmaxf(smax[tl0], smax[64 + tl0]);
        const float cc1 = -dg1 - fmaxf(smax[tl1], smax[64 + tl1]);
        unsigned* Trh = (unsigned*)(smem + OFF_PH);   // [64 tok][132 u32]
        unsigned* Trl = Trh + 64 * 132;
        #pragma unroll
        for (int nt = 0; nt < 16; nt++) {
            int m = fb + nt * 8 + 2 * tq;
            float p0 = RATIO * fexp(c[nt][0] + cc0) + REPS;
            float p1 = RATIO * fexp(c[nt][1] + cc0) + REPS;
            float p2 = RATIO * fexp(c[nt][2] + cc1) + REPS;
            float p3 = RATIO * fexp(c[nt][3] + cc1) + REPS;
            unsigned ph, pl;
            split2(p0, p1, ph, pl);
            Trh[tl0 * 132 + (m >> 1)] = ph;
            Trl[tl0 * 132 + (m >> 1)] = pl;
            split2(p2, p3, ph, pl);
            Trh[tl1 * 132 + (m >> 1)] = ph;
            Trl[tl1 * 132 + (m >> 1)] = pl;
        }
        __syncthreads();
        const int tok = t >> 2, q = t & 3;
        uint4* dh = (uint4*)(g_qh + ((size_t)head * Nn + n0 + tok) * Mm);
        uint4* dl = (uint4*)(g_ql + ((size_t)head * Nn + n0 + tok) * Mm);
        const uint4* sh = (const uint4*)(Trh + tok * 132 + q * 32);
        const uint4* sl = (const uint4*)(Trl + tok * 132 + q * 32);
        #pragma unroll
        for (int j = 0; j < 8; j++) {
            dh[q * 8 + j] = sh[j];
            dl[q * 8 + j] = sl[j];
        }
    }
}

// ---------------- K_vsum: R[h][d] = sum_n V ----------------
__global__ void k_vsum(const float* __restrict__ value)
{
    __shared__ float red[8];
    const int h = blockIdx.y, d = blockIdx.x, t = threadIdx.x;
    const float4* src = (const float4*)(value + ((size_t)h * 64 + d) * Nn);
    float s = 0.0f;
    #pragma unroll
    for (int i = 0; i < 8; i++) {
        float4 v = src[t + 256 * i];
        s += (v.x + v.y) + (v.z + v.w);
    }
    #pragma unroll
    for (int o = 16; o; o >>= 1) s += __shfl_xor_sync(0xffffffffu, s, o);
    if ((t & 31) == 0) red[t >> 5] = s;
    __syncthreads();
    if (t == 0) {
        float r = 0.0f;
        #pragma unroll
        for (int w2 = 0; w2 < 8; w2++) r += red[w2];
        g_vsum[h * 64 + d] = r;
    }
}

// ---------------- K2 (HMMA): kv partials = E . V'^T (knorm col) ------------
// grid (32, 32): x = slice*2 + mhalf. block 256 (8 warps), 2 CTAs/SM.
// Each block: 128 m-rows, 512 tokens. Warp tile 32m x 40d.
#define KV_AH  0
#define KV_AL  18432
#define KV_VH  36864
#define KV_VL  48384
#define KV_SMEM 59904

__global__ void __launch_bounds__(256, 2) k_kv_mma(const float* __restrict__ value)
{
    extern __shared__ char smem[];
    char* Ah = smem + KV_AH;   // [128 m][72 bf16] (144 B rows)
    char* Al = smem + KV_AL;
    char* Vh = smem + KV_VH;   // [80 d][72 bf16]
    char* Vl = smem + KV_VL;

    const int t = threadIdx.x;
    const int head = blockIdx.y;
    const int slice = blockIdx.x >> 1;
    const int mbase = (blockIdx.x & 1) * 128;
    const float kmax = finv(g_kmax[head]);

    const int w = t >> 5, lane = t & 31;
    const int g = lane >> 2, tq = lane & 3;
    const int mg = (w & 3) * 32;            // local m base
    const int dgr = (w >> 2) * 40;

    // V pad rows 65..79 = 0 (row 64 set per chunk)
    for (int e = t; e < 540; e += 256) {
        int row = 65 + e / 36, col = e % 36;
        ((unsigned*)(Vh + row * 144))[col] = 0u;
        ((unsigned*)(Vl + row * 144))[col] = 0u;
    }

    float c[2][5][4];
    #pragma unroll
    for (int mt = 0; mt < 2; mt++)
        #pragma unroll
        for (int dt = 0; dt < 5; dt++)
            #pragma unroll
            for (int j = 0; j < 4; j++) c[mt][dt][j] = 0.0f;

    const float* vp = value + (size_t)head * Dd * Nn;

    for (int ch = 0; ch < 8; ch++) {
        const int n0 = slice * 512 + ch * 64;
        const float s_ch = fexp(g_bmax[head * 128 + slice * 8 + ch] - kmax);
        __syncthreads();   // previous MMA reads complete

        // stage A: straight pair copy from g_k2 (128 local m rows)
        {
            const int q = t & 7;
            const u64* kb = g_k2 + (size_t)(head * Mm + mbase) * (Nn/2) + n0/2;
            #pragma unroll
            for (int r = 0; r < 4; r++) {
                int m = (t >> 3) + 32 * r;
                const uint4* src = (const uint4*)(kb + (size_t)m * (Nn/2) + 4 * q);
                uint4 a = src[0], b = src[1];
                *(uint2*)(Ah + m * 144 + 16*q)     = make_uint2(a.x, a.z);
                *(uint2*)(Al + m * 144 + 16*q)     = make_uint2(a.y, a.w);
                *(uint2*)(Ah + m * 144 + 16*q + 8) = make_uint2(b.x, b.z);
                *(uint2*)(Al + m * 144 + 16*q + 8) = make_uint2(b.y, b.w);
            }
        }
        // row 64 = s_ch (scaled ones -> knorm)
        if (t < 36) {
            unsigned shh, sll;
            split2(s_ch, s_ch, shh, sll);
            ((unsigned*)(Vh + 64 * 144))[t] = shh;
            ((unsigned*)(Vl + 64 * 144))[t] = sll;
        }
        // stage V: [d][n] rows scaled by s_ch
        {
            int d = t >> 2, q = t & 3;
            const float* src = vp + (size_t)d * Nn + n0 + q * 16;
            unsigned* rowh = (unsigned*)(Vh + d * 144 + q * 32);
            unsigned* rowl = (unsigned*)(Vl + d * 144 + q * 32);
            #pragma unroll
            for (int i = 0; i < 4; i++) {
                float4 v = *(const float4*)(src + 4 * i);
                unsigned ph, pl;
                split2(v.x * s_ch, v.y * s_ch, ph, pl);
                rowh[2 * i] = ph;  rowl[2 * i] = pl;
                split2(v.z * s_ch, v.w * s_ch, ph, pl);
                rowh[2 * i + 1] = ph;  rowl[2 * i + 1] = pl;
            }
        }
        __syncthreads();

        #pragma unroll
        for (int k = 0; k < 4; k++) {
            const int koff = k * 16;
            unsigned ah[2][4], al[2][4];
            #pragma unroll
            for (int mt = 0; mt < 2; mt++) {
                int r0 = mg + mt * 16 + g, r1 = r0 + 8;
                ah[mt][0] = *(const unsigned*)(Ah + r0 * 144 + (koff + 2*tq) * 2);
                ah[mt][1] = *(const unsigned*)(Ah + r1 * 144 + (koff + 2*tq) * 2);
                ah[mt][2] = *(const unsigned*)(Ah + r0 * 144 + (koff + 8 + 2*tq) * 2);
                ah[mt][3] = *(const unsigned*)(Ah + r1 * 144 + (koff + 8 + 2*tq) * 2);
                al[mt][0] = *(const unsigned*)(Al + r0 * 144 + (koff + 2*tq) * 2);
                al[mt][1] = *(const unsigned*)(Al + r1 * 144 + (koff + 2*tq) * 2);
                al[mt][2] = *(const unsigned*)(Al + r0 * 144 + (koff + 8 + 2*tq) * 2);
                al[mt][3] = *(const unsigned*)(Al + r1 * 144 + (koff + 8 + 2*tq) * 2);
            }
            #pragma unroll
            for (int dt = 0; dt < 5; dt++) {
                const char* rh = Vh + (dgr + dt * 8 + g) * 144 + (koff + 2*tq) * 2;
                const char* rl = Vl + (dgr + dt * 8 + g) * 144 + (koff + 2*tq) * 2;
                unsigned bh0 = *(const unsigned*)(rh);
                unsigned bh1 = *(const unsigned*)(rh + 16);
                unsigned bl0 = *(const unsigned*)(rl);
                unsigned bl1 = *(const unsigned*)(rl + 16);
                #pragma unroll
                for (int mt = 0; mt < 2; mt++) {
                    mma16816(c[mt][dt], ah[mt], bh0, bh1);
                    mma16816(c[mt][dt], ah[mt], bl0, bl1);
                    mma16816(c[mt][dt], al[mt], bh0, bh1);
                }
            }
        }
    }

    // write partials [d][m] (global m = mbase + local)
    float* dst = g_kvpart + (size_t)(head * 16 + slice) * 20480 + mbase;
    #pragma unroll
    for (int mt = 0; mt < 2; mt++) {
        int m0 = mg + mt * 16 + g, m1 = m0 + 8;
        #pragma unroll
        for (int dt = 0; dt < 5; dt++) {
            int d0 = dgr + dt * 8 + 2 * tq;
            dst[d0 * 256 + m0]       = c[mt][dt][0];
            dst[(d0 + 1) * 256 + m0] = c[mt][dt][1];
            dst[d0 * 256 + m1]       = c[mt][dt][2];
            dst[(d0 + 1) * 256 + m1] = c[mt][dt][3];
        }
    }
}

// ---------------- K3: reduce partials -> bf16-split kv^T (with eps corr) ---
__global__ void k_reduce()
{
    int idx = blockIdx.x * 256 + threadIdx.x;   // < 32*80*256 = 655360
    int h = idx / 20480;
    int rem = idx - h * 20480;
    int d = rem >> 8;
    float s = 0.0f;
    #pragma unroll
    for (int sl = 0; sl < 16; sl++)
        s += g_kvpart[(size_t)(h * 16 + sl) * 20480 + rem];
    float corr = (d < 64) ? REPS * g_vsum[h * 64 + d]
               : (d == 64 ? REPS * 8192.0f : 0.0f);
    float val = fmaf(RATIO, s, corr);
    __nv_bfloat16 hi = __float2bfloat16(val);
    g_kvth[idx] = hi;
    g_kvtl[idx] = __float2bfloat16(val - __bfloat162float(hi));
}

// ---------------- K4 (HMMA): out = phi_q . kv, divide by norm col ----------
// grid (64, 32), block 512 (16 warps). 128 tokens x 80 d. Warp: 16 tok x 40 d.
#define QO_QH 0
#define QO_QL 67584
#define QO_KH 135168
#define QO_KL 177408
#define QO_SN 219648
#define QO_SMEM 220160

__global__ void __launch_bounds__(512, 1) k_out_mma(float* __restrict__ out)
{
    extern __shared__ char smem[];
    char* Qh = smem + QO_QH;   // [128 tok][264 bf16] (528 B rows)
    char* Ql = smem + QO_QL;
    char* Kh = smem + QO_KH;   // [80 d][264 bf16]
    char* Kl = smem + QO_KL;
    float* sn = (float*)(smem + QO_SN);   // [128]

    const int t = threadIdx.x;
    const int head = blockIdx.y;
    const int n0 = blockIdx.x * 128;

    // stage phi_q (hi/lo): 128 tokens
    {
        int tok = t >> 2, q = t & 3;
        const uint4* sh = (const uint4*)(g_qh + ((size_t)head * Nn + n0 + tok) * Mm + q * 64);
        const uint4* sl = (const uint4*)(g_ql + ((size_t)head * Nn + n0 + tok) * Mm + q * 64);
        uint4* dh = (uint4*)(Qh + tok * 528 + q * 128);
        uint4* dl = (uint4*)(Ql + tok * 528 + q * 128);
        #pragma unroll
        for (int j = 0; j < 8; j++) { dh[j] = sh[j]; dl[j] = sl[j]; }
    }
    // stage kv^T (hi/lo), 80 rows (single pass over 512 threads)
    if (t < 320) {
        int row = t >> 2, q = t & 3;
        const uint4* sh = (const uint4*)(g_kvth + ((size_t)head * 80 + row) * 256 + q * 64);
        const uint4* sl = (const uint4*)(g_kvtl + ((size_t)head * 80 + row) * 256 + q * 64);
        uint4* dh = (uint4*)(Kh + row * 528 + q * 128);
        uint4* dl = (uint4*)(Kl + row * 528 + q * 128);
        #pragma unroll
        for (int j = 0; j < 8; j++) { dh[j] = sh[j]; dl[j] = sl[j]; }
    }
    __syncthreads();

    const int w = t >> 5, lane = t & 31;
    const int g = lane >> 2, tq = lane & 3;
    const int tg = (w & 7) * 16;        // token base: 0..112
    const int dgr = (w >> 3) * 40;      // d base: 0 or 40

    float c[5][4];
    #pragma unroll
    for (int dt = 0; dt < 5; dt++)
        #pragma unroll
        for (int j = 0; j < 4; j++) c[dt][j] = 0.0f;

    #pragma unroll
    for (int kc = 0; kc < 16; kc++) {
        const int koff = kc * 16;
        unsigned ah[4], al[4];
        ah[0] = *(const unsigned*)(Qh + (tg + g)     * 528 + (koff + 2*tq) * 2);
        ah[1] = *(const unsigned*)(Qh + (tg + g + 8) * 528 + (koff + 2*tq) * 2);
        ah[2] = *(const unsigned*)(Qh + (tg + g)     * 528 + (koff + 8 + 2*tq) * 2);
        ah[3] = *(const unsigned*)(Qh + (tg + g + 8) * 528 + (koff + 8 + 2*tq) * 2);
        al[0] = *(const unsigned*)(Ql + (tg + g)     * 528 + (koff + 2*tq) * 2);
        al[1] = *(const unsigned*)(Ql + (tg + g + 8) * 528 + (koff + 2*tq) * 2);
        al[2] = *(const unsigned*)(Ql + (tg + g)     * 528 + (koff + 8 + 2*tq) * 2);
        al[3] = *(const unsigned*)(Ql + (tg + g + 8) * 528 + (koff + 8 + 2*tq) * 2);
        #pragma unroll
        for (int dt = 0; dt < 5; dt++) {
            const char* rh = Kh + (dgr + dt * 8 + g) * 528 + (koff + 2*tq) * 2;
            const char* rl = Kl + (dgr + dt * 8 + g) * 528 + (koff + 2*tq) * 2;
            unsigned bh0 = *(const unsigned*)(rh);
            unsigned bh1 = *(const unsigned*)(rh + 16);
            unsigned bl0 = *(const unsigned*)(rl);
            unsigned bl1 = *(const unsigned*)(rl + 16);
            mma16816(c[dt], ah, bh0, bh1);
            mma16816(c[dt], ah, bl0, bl1);
            mma16816(c[dt], al, bh0, bh1);
        }
    }

    // norm column (d = 64): warps with dgr=40, dt=3, tq==0
    if (dgr == 40 && tq == 0) {
        sn[tg + g]     = c[3][0];
        sn[tg + g + 8] = c[3][2];
    }
    __syncthreads();
    const float rn0 = 1.0f / sn[tg + g];
    const float rn1 = 1.0f / sn[tg + g + 8];

    float* op = out + (size_t)head * Dd * Nn + n0;
    #pragma unroll
    for (int dt = 0; dt < 5; dt++) {
        int d0 = dgr + dt * 8 + 2 * tq;
        if (d0 < 64) {
            op[(size_t)d0 * Nn + tg + g]           = c[dt][0] * rn0;
            op[(size_t)(d0 + 1) * Nn + tg + g]     = c[dt][1] * rn0;
            op[(size_t)d0 * Nn + tg + g + 8]       = c[dt][2] * rn1;
            op[(size_t)(d0 + 1) * Nn + tg + g + 8] = c[dt][3] * rn1;
        }
    }
}

// ---------------- launch ----------------
extern "C" void kernel_launch(void* const* d_in, const int* in_sizes, int n_in,
                              void* d_out, int out_size)
{
    const float* query = (const float*)d_in[0];
    const float* key   = (const float*)d_in[1];
    const float* value = (const float*)d_in[2];
    const float* proj  = (const float*)d_in[3];
    float* out = (float*)d_out;

    cudaFuncSetAttribute(k_proj_mma<false>, cudaFuncAttributeMaxDynamicSharedMemorySize, PROJ_SMEM);
    cudaFuncSetAttribute(k_proj_mma<true>,  cudaFuncAttributeMaxDynamicSharedMemorySize, PROJ_SMEM);
    cudaFuncSetAttribute(k_kv_mma,  cudaFuncAttributeMaxDynamicSharedMemorySize, KV_SMEM);
    cudaFuncSetAttribute(k_out_mma, cudaFuncAttributeMaxDynamicSharedMemorySize, QO_SMEM);

    k_init<<<64, 256>>>(proj);
    k_proj_mma<false><<<dim3(128, 32), 256, PROJ_SMEM>>>(key);
    k_proj_mma<true><<<dim3(128, 32), 256, PROJ_SMEM>>>(query);
    k_vsum<<<dim3(64, 32), 256>>>(value);
    k_kv_mma<<<dim3(32, 32), 256, KV_SMEM>>>(value);
    k_reduce<<<2560, 256>>>();
    k_out_mma<<<dim3(64, 32), 512, QO_SMEM>>>(out);
}

// round 11
// speedup vs baseline: 1.7103x; 1.5273x over previous
#include <cuda_runtime.h>
#include <cuda_bf16.h>
#include <math.h>

#define Dd 64
#define Nn 8192
#define Mm 256
#define NH 32
#define DN     0.3535533905932738f   /* 64^-0.25 */
#define RATIO  0.0625f               /* 256^-0.5 */
#define REPS   6.25e-8f              /* RATIO * 1e-6 */
#define DIAGC  0.0625f               /* DN^2 * 0.5 */

typedef unsigned long long u64;

// ---------------- scratch (device globals; no allocation) ----------------
__device__ float g_smax[NH * 16];                       // per (head, slice) max raw u
__device__ float g_vsum[NH * 64];                       // R[h][d] = sum_n V
__device__ float g_kvpart[(size_t)NH * 16 * 80 * 256];  // [h*16+sl][d][m], scale exp(-Mr_sl)
__device__ __nv_bfloat16 g_kvth[(size_t)NH * 80 * 256]; // kv^T hi, [h][d][m] (d=64 -> knorm)
__device__ __nv_bfloat16 g_kvtl[(size_t)NH * 80 * 256]; // kv^T lo
__device__ __align__(16) __nv_bfloat16 g_pbh[256 * 64]; // proj*DN hi, [m][d]
__device__ __align__(16) __nv_bfloat16 g_pbl[256 * 64]; // proj*DN lo

// branch-free exp on FMA/ALU pipes. Valid for x <= 0, ~2.4e-6 rel err.
static __device__ __forceinline__ float fexp(float x) {
    float t = x * 1.4426950408889634f;
    t = fmaxf(t, -125.0f);
    float r  = t + 12582912.0f;
    float fi = r - 12582912.0f;
    float f  = t - fi;
    float p = 1.3333558e-3f;
    p = fmaf(p, f, 9.6181291e-3f);
    p = fmaf(p, f, 5.5504109e-2f);
    p = fmaf(p, f, 2.4022651e-1f);
    p = fmaf(p, f, 6.9314718e-1f);
    p = fmaf(p, f, 1.0f);
    int ib = __float_as_int(r) - 0x4B400000;
    float s = __int_as_float((ib + 127) << 23);
    return p * s;
}

// HMMA m16n8k16 bf16 -> fp32 accum
static __device__ __forceinline__ void mma16816(float c[4], const unsigned a[4],
                                                unsigned b0, unsigned b1) {
    asm volatile(
        "mma.sync.aligned.m16n8k16.row.col.f32.bf16.bf16.f32 "
        "{%0,%1,%2,%3}, {%4,%5,%6,%7}, {%8,%9}, {%0,%1,%2,%3};"
        : "+f"(c[0]), "+f"(c[1]), "+f"(c[2]), "+f"(c[3])
        : "r"(a[0]), "r"(a[1]), "r"(a[2]), "r"(a[3]), "r"(b0), "r"(b1));
}

// bf16 hi/lo split, packing pairs (v0,v1) -> (hi-pair, lo-pair)
static __device__ __forceinline__ void split2(float v0, float v1, unsigned& ph, unsigned& pl) {
    __nv_bfloat16 h0 = __float2bfloat16(v0);
    __nv_bfloat16 h1 = __float2bfloat16(v1);
    __nv_bfloat16 l0 = __float2bfloat16(v0 - __bfloat162float(h0));
    __nv_bfloat16 l1 = __float2bfloat16(v1 - __bfloat162float(h1));
    ph = ((unsigned)__bfloat16_as_ushort(h1) << 16) | __bfloat16_as_ushort(h0);
    pl = ((unsigned)__bfloat16_as_ushort(l1) << 16) | __bfloat16_as_ushort(l0);
}

// single-value bf16 split stored as 16-bit into hi/lo smem planes (144 B rows)
static __device__ __forceinline__ void sts_split(char* H, char* L, int m, int tok, float v) {
    __nv_bfloat16 h = __float2bfloat16(v);
    __nv_bfloat16 l = __float2bfloat16(v - __bfloat162float(h));
    *(unsigned short*)(H + m * 144 + tok * 2) = __bfloat16_as_ushort(h);
    *(unsigned short*)(L + m * 144 + tok * 2) = __bfloat16_as_ushort(l);
}

// ---------------- K0: bf16-split scaled proj ----------------
__global__ void k_init(const float* __restrict__ proj)
{
    int idx = blockIdx.x * 256 + threadIdx.x;   // 64 blocks x 256
    if (idx < 256 * 64) {
        float v = proj[idx] * DN;               // [m][d] layout preserved
        __nv_bfloat16 h = __float2bfloat16(v);
        g_pbh[idx] = h;
        g_pbl[idx] = __float2bfloat16(v - __bfloat162float(h));
    }
}

// ---------------- K_vsum: R[h][d] = sum_n V ----------------
__global__ void k_vsum(const float* __restrict__ value)
{
    __shared__ float red[8];
    const int h = blockIdx.y, d = blockIdx.x, t = threadIdx.x;
    const float4* src = (const float4*)(value + ((size_t)h * 64 + d) * Nn);
    float s = 0.0f;
    #pragma unroll
    for (int i = 0; i < 8; i++) {
        float4 v = src[t + 256 * i];
        s += (v.x + v.y) + (v.z + v.w);
    }
    #pragma unroll
    for (int o = 16; o; o >>= 1) s += __shfl_xor_sync(0xffffffffu, s, o);
    if ((t & 31) == 0) red[t >> 5] = s;
    __syncthreads();
    if (t == 0) {
        float r = 0.0f;
        #pragma unroll
        for (int w2 = 0; w2 < 8; w2++) r += red[w2];
        g_vsum[h * 64 + d] = r;
    }
}

// ---------------- K1 (fused): key proj + exp + kv accumulation -------------
// grid (16 slices, 32 heads), block 256 (8 warps).
// Per chunk of 64 tokens: proj MMA (warp 16tok x 128feat) -> online-max rescale
// -> E = exp(u - diag - Mr) into smem bf16 planes -> kv MMA (warp 64m x 40d).
#define KF_AH   0
#define KF_AL   9216
#define KF_PH   18432
#define KF_PL   55296
#define KF_EH   92160
#define KF_EL   129024
#define KF_VH   165888
#define KF_VL   177408
#define KF_SQP  188928
#define KF_SQ   189952
#define KF_RED  190208
#define KF_SMEM 190464

__global__ void __launch_bounds__(256, 1) k_kv_fused(const float* __restrict__ key,
                                                     const float* __restrict__ value)
{
    extern __shared__ char smem[];
    char* Ah = smem + KF_AH;   // [64 tok][72 bf16] (144 B rows)
    char* Al = smem + KF_AL;
    char* Ph = smem + KF_PH;   // [256 feat][72 bf16]
    char* Pl = smem + KF_PL;
    char* Eh = smem + KF_EH;   // [256 m][64 tok as k] hi
    char* El = smem + KF_EL;
    char* Vh = smem + KF_VH;   // [80 d][64 tok as k] hi
    char* Vl = smem + KF_VL;
    float* sqp = (float*)(smem + KF_SQP);   // [64][4]
    float* sq  = (float*)(smem + KF_SQ);    // [64]
    float* red = (float*)(smem + KF_RED);   // [8]

    const int t = threadIdx.x;
    const int head = blockIdx.y;
    const int slice = blockIdx.x;

    // stage P once
    #pragma unroll
    for (int cc = 0; cc < 8; cc++) {
        int e = t + 256 * cc;           // < 2048
        int row = e >> 3, j = e & 7;
        *(uint4*)(Ph + row * 144 + j * 16) = ((const uint4*)g_pbh)[e];
        *(uint4*)(Pl + row * 144 + j * 16) = ((const uint4*)g_pbl)[e];
    }
    // V const rows: row 64 = 1.0 (knorm via ones), rows 65..79 = 0
    for (int e = t; e < 576; e += 256) {
        int row = 64 + e / 36, col = e % 36;
        ((unsigned*)(Vh + row * 144))[col] = (row == 64) ? 0x3F803F80u : 0u;
        ((unsigned*)(Vl + row * 144))[col] = 0u;
    }

    const int w = t >> 5, lane = t & 31;
    const int g = lane >> 2, tq = lane & 3;
    const int tb = (w & 3) * 16;            // proj: token base
    const int fb = (w >> 2) * 128;          // proj: feature base
    const int mg = (w & 3) * 64;            // kv: m base
    const int dgr = (w >> 2) * 40;          // kv: d base
    const int tl0 = tb + g, tl1 = tb + g + 8;

    float Mr = -3.0e38f;                    // running slice max of raw u
    float c2[4][5][4];
    #pragma unroll
    for (int mt = 0; mt < 4; mt++)
        #pragma unroll
        for (int dt = 0; dt < 5; dt++)
            #pragma unroll
            for (int j = 0; j < 4; j++) c2[mt][dt][j] = 0.0f;

    const float* kp = key + (size_t)head * Dd * Nn;
    const float* vp = value + (size_t)head * Dd * Nn;

    for (int ch = 0; ch < 8; ch++) {
        const int n0 = slice * 512 + ch * 64;
        __syncthreads();   // prior kv MMA reads of E/V done; prior proj reads of A done

        // stage key chunk -> Ah/Al + partial sumsq
        {
            const int tok = t & 63, dblk = t >> 6;
            const float* xp = kp + n0 + tok;
            float s = 0.0f;
            #pragma unroll
            for (int i = 0; i < 8; i++) {
                int d = dblk * 16 + 2 * i;
                float v0 = xp[(size_t)d * Nn];
                float v1 = xp[(size_t)(d + 1) * Nn];
                s = fmaf(v0, v0, fmaf(v1, v1, s));
                unsigned ph, pl;
                split2(v0, v1, ph, pl);
                *(unsigned*)(Ah + tok * 144 + d * 2) = ph;
                *(unsigned*)(Al + tok * 144 + d * 2) = pl;
            }
            sqp[tok * 4 + dblk] = s;
        }
        // stage V chunk rows 0..63 (unscaled; scale lives in E)
        {
            int d = t >> 2, q = t & 3;
            const float* src = vp + (size_t)d * Nn + n0 + q * 16;
            unsigned* rowh = (unsigned*)(Vh + d * 144 + q * 32);
            unsigned* rowl = (unsigned*)(Vl + d * 144 + q * 32);
            #pragma unroll
            for (int i = 0; i < 4; i++) {
                float4 v = *(const float4*)(src + 4 * i);
                unsigned ph, pl;
                split2(v.x, v.y, ph, pl);
                rowh[2 * i] = ph;  rowl[2 * i] = pl;
                split2(v.z, v.w, ph, pl);
                rowh[2 * i + 1] = ph;  rowl[2 * i + 1] = pl;
            }
        }
        __syncthreads();
        if (t < 64) sq[t] = sqp[4*t] + sqp[4*t+1] + sqp[4*t+2] + sqp[4*t+3];

        // proj MMA: u[tok][feat]
        float c[16][4];
        #pragma unroll
        for (int nt = 0; nt < 16; nt++)
            #pragma unroll
            for (int j = 0; j < 4; j++) c[nt][j] = 0.0f;

        #pragma unroll
        for (int k = 0; k < 4; k++) {
            const int koff = k * 16;
            unsigned ah[4], al[4];
            ah[0] = *(const unsigned*)(Ah + (tb + g)     * 144 + (koff + 2*tq) * 2);
            ah[1] = *(const unsigned*)(Ah + (tb + g + 8) * 144 + (koff + 2*tq) * 2);
            ah[2] = *(const unsigned*)(Ah + (tb + g)     * 144 + (koff + 8 + 2*tq) * 2);
            ah[3] = *(const unsigned*)(Ah + (tb + g + 8) * 144 + (koff + 8 + 2*tq) * 2);
            al[0] = *(const unsigned*)(Al + (tb + g)     * 144 + (koff + 2*tq) * 2);
            al[1] = *(const unsigned*)(Al + (tb + g + 8) * 144 + (koff + 2*tq) * 2);
            al[2] = *(const unsigned*)(Al + (tb + g)     * 144 + (koff + 8 + 2*tq) * 2);
            al[3] = *(const unsigned*)(Al + (tb + g + 8) * 144 + (koff + 8 + 2*tq) * 2);
            #pragma unroll
            for (int nt = 0; nt < 16; nt++) {
                const char* prow_h = Ph + (fb + nt * 8 + g) * 144 + (koff + 2*tq) * 2;
                const char* prow_l = Pl + (fb + nt * 8 + g) * 144 + (koff + 2*tq) * 2;
                unsigned bh0 = *(const unsigned*)(prow_h);
                unsigned bh1 = *(const unsigned*)(prow_h + 16);
                unsigned bl0 = *(const unsigned*)(prow_l);
                unsigned bl1 = *(const unsigned*)(prow_l + 16);
                mma16816(c[nt], ah, bh0, bh1);
                mma16816(c[nt], ah, bl0, bl1);
                mma16816(c[nt], al, bh0, bh1);
            }
        }

        // chunk max of raw u
        float bm = -3.4e38f;
        #pragma unroll
        for (int nt = 0; nt < 16; nt++)
            bm = fmaxf(bm, fmaxf(fmaxf(c[nt][0], c[nt][1]), fmaxf(c[nt][2], c[nt][3])));
        #pragma unroll
        for (int o = 16; o; o >>= 1) bm = fmaxf(bm, __shfl_xor_sync(0xffffffffu, bm, o));
        if (lane == 0) red[w] = bm;
        __syncthreads();                 // also guards sq + proj MMA smem reads
        float Mb = red[0];
        #pragma unroll
        for (int r2 = 1; r2 < 8; r2++) Mb = fmaxf(Mb, red[r2]);

        // online rescale
        float Mn = fmaxf(Mr, Mb);
        float rsc = fexp(Mr - Mn);
        #pragma unroll
        for (int mt = 0; mt < 4; mt++)
            #pragma unroll
            for (int dt = 0; dt < 5; dt++)
                #pragma unroll
                for (int j = 0; j < 4; j++) c2[mt][dt][j] *= rsc;
        Mr = Mn;

        // epilogue: E = exp(u - diag - Mr) -> Eh/El (16-bit scatter)
        const float dg0 = sq[tl0] * DIAGC;
        const float dg1 = sq[tl1] * DIAGC;
        #pragma unroll
        for (int nt = 0; nt < 16; nt++) {
            int m = fb + nt * 8 + 2 * tq;
            sts_split(Eh, El, m,     tl0, fexp(c[nt][0] - dg0 - Mr));
            sts_split(Eh, El, m + 1, tl0, fexp(c[nt][1] - dg0 - Mr));
            sts_split(Eh, El, m,     tl1, fexp(c[nt][2] - dg1 - Mr));
            sts_split(Eh, El, m + 1, tl1, fexp(c[nt][3] - dg1 - Mr));
        }
        __syncthreads();

        // kv MMA: c2[m][d] += E[m][n] * V[d][n], k = 64 tokens
        #pragma unroll
        for (int k = 0; k < 4; k++) {
            const int koff = k * 16;
            unsigned ah[4][4], al[4][4];
            #pragma unroll
            for (int mt = 0; mt < 4; mt++) {
                int r0 = mg + mt * 16 + g, r1 = r0 + 8;
                ah[mt][0] = *(const unsigned*)(Eh + r0 * 144 + (koff + 2*tq) * 2);
                ah[mt][1] = *(const unsigned*)(Eh + r1 * 144 + (koff + 2*tq) * 2);
                ah[mt][2] = *(const unsigned*)(Eh + r0 * 144 + (koff + 8 + 2*tq) * 2);
                ah[mt][3] = *(const unsigned*)(Eh + r1 * 144 + (koff + 8 + 2*tq) * 2);
                al[mt][0] = *(const unsigned*)(El + r0 * 144 + (koff + 2*tq) * 2);
                al[mt][1] = *(const unsigned*)(El + r1 * 144 + (koff + 2*tq) * 2);
                al[mt][2] = *(const unsigned*)(El + r0 * 144 + (koff + 8 + 2*tq) * 2);
                al[mt][3] = *(const unsigned*)(El + r1 * 144 + (koff + 8 + 2*tq) * 2);
            }
            #pragma unroll
            for (int dt = 0; dt < 5; dt++) {
                const char* rh = Vh + (dgr + dt * 8 + g) * 144 + (koff + 2*tq) * 2;
                const char* rl = Vl + (dgr + dt * 8 + g) * 144 + (koff + 2*tq) * 2;
                unsigned bh0 = *(const unsigned*)(rh);
                unsigned bh1 = *(const unsigned*)(rh + 16);
                unsigned bl0 = *(const unsigned*)(rl);
                unsigned bl1 = *(const unsigned*)(rl + 16);
                #pragma unroll
                for (int mt = 0; mt < 4; mt++) {
                    mma16816(c2[mt][dt], ah[mt], bh0, bh1);
                    mma16816(c2[mt][dt], ah[mt], bl0, bl1);
                    mma16816(c2[mt][dt], al[mt], bh0, bh1);
                }
            }
        }
    }

    if (t == 0) g_smax[head * 16 + slice] = Mr;

    // write partials [d][m]
    float* dst = g_kvpart + (size_t)(head * 16 + slice) * 20480;
    #pragma unroll
    for (int mt = 0; mt < 4; mt++) {
        int m0 = mg + mt * 16 + g, m1 = m0 + 8;
        #pragma unroll
        for (int dt = 0; dt < 5; dt++) {
            int d0 = dgr + dt * 8 + 2 * tq;
            dst[d0 * 256 + m0]       = c2[mt][dt][0];
            dst[(d0 + 1) * 256 + m0] = c2[mt][dt][1];
            dst[d0 * 256 + m1]       = c2[mt][dt][2];
            dst[(d0 + 1) * 256 + m1] = c2[mt][dt][3];
        }
    }
}

// ---------------- K2: reduce partials (rescale per slice) -> bf16 kv^T -----
__global__ void k_reduce()
{
    int idx = blockIdx.x * 256 + threadIdx.x;   // < 32*80*256 = 655360
    int h = idx / 20480;
    int rem = idx - h * 20480;
    int d = rem >> 8;
    float Mh = g_smax[h * 16];
    #pragma unroll
    for (int sl = 1; sl < 16; sl++) Mh = fmaxf(Mh, g_smax[h * 16 + sl]);
    float s = 0.0f;
    #pragma unroll
    for (int sl = 0; sl < 16; sl++) {
        float sc = fexp(g_smax[h * 16 + sl] - Mh);
        s = fmaf(g_kvpart[(size_t)(h * 16 + sl) * 20480 + rem], sc, s);
    }
    float corr = (d < 64) ? REPS * g_vsum[h * 64 + d]
               : (d == 64 ? REPS * 8192.0f : 0.0f);
    float val = fmaf(RATIO, s, corr);
    __nv_bfloat16 hi = __float2bfloat16(val);
    g_kvth[idx] = hi;
    g_kvtl[idx] = __float2bfloat16(val - __bfloat162float(hi));
}

// ---------------- K3 (fused): query proj + phi + out GEMM + divide ---------
// grid (64, 32), block 512 (16 warps). 128 tokens per block.
#define QF_AH   0
#define QF_AL   18432
#define QF_PH   36864
#define QF_PL   73728
#define QF_QH   0          /* phase B: [128 tok][264 bf16] 528 B rows (reuses A/P) */
#define QF_QL   67584
#define QF_KH   135168     /* [80 d][264 bf16] */
#define QF_KL   177408
#define QF_SQP  219648
#define QF_SQ   221696
#define QF_SMAX 222208
#define QF_SN   223232
#define QF_SMEM 223744

__global__ void __launch_bounds__(512, 1) k_out_fused(const float* __restrict__ query,
                                                      float* __restrict__ out)
{
    extern __shared__ char smem[];
    char* Ah = smem + QF_AH;    // [128 tok][72 bf16] (144 B rows)
    char* Al = smem + QF_AL;
    char* Ph = smem + QF_PH;    // [256 feat][72 bf16]
    char* Pl = smem + QF_PL;
    char* Qh = smem + QF_QH;    // phase B
    char* Ql = smem + QF_QL;
    char* Kh = smem + QF_KH;
    char* Kl = smem + QF_KL;
    float* sqp  = (float*)(smem + QF_SQP);   // [128][4]
    float* sq   = (float*)(smem + QF_SQ);    // [128]
    float* smax = (float*)(smem + QF_SMAX);  // [2][128]
    float* sn   = (float*)(smem + QF_SN);    // [128]

    const int t = threadIdx.x;
    const int head = blockIdx.y;
    const int n0 = blockIdx.x * 128;

    // stage query chunk -> Ah/Al + partial sumsq
    {
        const int tok = t & 127, dblk = t >> 7;   // 4 dblks of 16 d
        const float* xp = query + (size_t)head * Dd * Nn + n0 + tok;
        float s = 0.0f;
        #pragma unroll
        for (int i = 0; i < 8; i++) {
            int d = dblk * 16 + 2 * i;
            float v0 = xp[(size_t)d * Nn];
            float v1 = xp[(size_t)(d + 1) * Nn];
            s = fmaf(v0, v0, fmaf(v1, v1, s));
            unsigned ph, pl;
            split2(v0, v1, ph, pl);
            *(unsigned*)(Ah + tok * 144 + d * 2) = ph;
            *(unsigned*)(Al + tok * 144 + d * 2) = pl;
        }
        sqp[tok * 4 + dblk] = s;
    }
    // stage P
    #pragma unroll
    for (int cc = 0; cc < 4; cc++) {
        int e = t + 512 * cc;           // < 2048
        int row = e >> 3, j = e & 7;
        *(uint4*)(Ph + row * 144 + j * 16) = ((const uint4*)g_pbh)[e];
        *(uint4*)(Pl + row * 144 + j * 16) = ((const uint4*)g_pbl)[e];
    }
    // stage kv^T pairs (region disjoint from phase A)
    if (t < 320) {
        int row = t >> 2, q = t & 3;
        const uint4* sh = (const uint4*)(g_kvth + ((size_t)head * 80 + row) * 256 + q * 64);
        const uint4* sl = (const uint4*)(g_kvtl + ((size_t)head * 80 + row) * 256 + q * 64);
        uint4* dh = (uint4*)(Kh + row * 528 + q * 128);
        uint4* dl = (uint4*)(Kl + row * 528 + q * 128);
        #pragma unroll
        for (int j = 0; j < 8; j++) { dh[j] = sh[j]; dl[j] = sl[j]; }
    }
    __syncthreads();
    if (t < 128) sq[t] = sqp[4*t] + sqp[4*t+1] + sqp[4*t+2] + sqp[4*t+3];

    const int w = t >> 5, lane = t & 31;
    const int g = lane >> 2, tq = lane & 3;
    const int tb = (w & 7) * 16;            // proj: token base (0..112)
    const int fb = (w >> 3) * 128;          // proj: feature base
    const int tl0 = tb + g, tl1 = tb + g + 8;

    // proj MMA
    float c[16][4];
    #pragma unroll
    for (int nt = 0; nt < 16; nt++)
        #pragma unroll
        for (int j = 0; j < 4; j++) c[nt][j] = 0.0f;

    #pragma unroll
    for (int k = 0; k < 4; k++) {
        const int koff = k * 16;
        unsigned ah[4], al[4];
        ah[0] = *(const unsigned*)(Ah + (tb + g)     * 144 + (koff + 2*tq) * 2);
        ah[1] = *(const unsigned*)(Ah + (tb + g + 8) * 144 + (koff + 2*tq) * 2);
        ah[2] = *(const unsigned*)(Ah + (tb + g)     * 144 + (koff + 8 + 2*tq) * 2);
        ah[3] = *(const unsigned*)(Ah + (tb + g + 8) * 144 + (koff + 8 + 2*tq) * 2);
        al[0] = *(const unsigned*)(Al + (tb + g)     * 144 + (koff + 2*tq) * 2);
        al[1] = *(const unsigned*)(Al + (tb + g + 8) * 144 + (koff + 2*tq) * 2);
        al[2] = *(const unsigned*)(Al + (tb + g)     * 144 + (koff + 8 + 2*tq) * 2);
        al[3] = *(const unsigned*)(Al + (tb + g + 8) * 144 + (koff + 8 + 2*tq) * 2);
        #pragma unroll
        for (int nt = 0; nt < 16; nt++) {
            const char* prow_h = Ph + (fb + nt * 8 + g) * 144 + (koff + 2*tq) * 2;
            const char* prow_l = Pl + (fb + nt * 8 + g) * 144 + (koff + 2*tq) * 2;
            unsigned bh0 = *(const unsigned*)(prow_h);
            unsigned bh1 = *(const unsigned*)(prow_h + 16);
            unsigned bl0 = *(const unsigned*)(prow_l);
            unsigned bl1 = *(const unsigned*)(prow_l + 16);
            mma16816(c[nt], ah, bh0, bh1);
            mma16816(c[nt], ah, bl0, bl1);
            mma16816(c[nt], al, bh0, bh1);
        }
    }

    // per-token max over features (two feature-halves combined via smem)
    {
        float m0 = -3.4e38f, m1 = -3.4e38f;
        #pragma unroll
        for (int nt = 0; nt < 16; nt++) {
            m0 = fmaxf(m0, fmaxf(c[nt][0], c[nt][1]));
            m1 = fmaxf(m1, fmaxf(c[nt][2], c[nt][3]));
        }
        m0 = fmaxf(m0, __shfl_xor_sync(0xffffffffu, m0, 1));
        m0 = fmaxf(m0, __shfl_xor_sync(0xffffffffu, m0, 2));
        m1 = fmaxf(m1, __shfl_xor_sync(0xffffffffu, m1, 1));
        m1 = fmaxf(m1, __shfl_xor_sync(0xffffffffu, m1, 2));
        if (tq == 0) {
            smax[(w >> 3) * 128 + tl0] = m0;
            smax[(w >> 3) * 128 + tl1] = m1;
        }
    }
    __syncthreads();   // proj MMA smem reads done; smax/sq ready

    // epilogue: phi_q -> Qh/Ql (pairs along m)
    {
        const float dg0 = sq[tl0] * DIAGC;
        const float dg1 = sq[tl1] * DIAGC;
        const float cc0 = -dg0 - fmaxf(smax[tl0], smax[128 + tl0]);
        const float cc1 = -dg1 - fmaxf(smax[tl1], smax[128 + tl1]);
        unsigned* Qh32 = (unsigned*)Qh;   // rows of 132 u32 (528 B)
        unsigned* Ql32 = (unsigned*)Ql;
        #pragma unroll
        for (int nt = 0; nt < 16; nt++) {
            int m = fb + nt * 8 + 2 * tq;
            float p0 = RATIO * fexp(c[nt][0] + cc0) + REPS;
            float p1 = RATIO * fexp(c[nt][1] + cc0) + REPS;
            float p2 = RATIO * fexp(c[nt][2] + cc1) + REPS;
            float p3 = RATIO * fexp(c[nt][3] + cc1) + REPS;
            unsigned ph, pl;
            split2(p0, p1, ph, pl);
            Qh32[tl0 * 132 + (m >> 1)] = ph;
            Ql32[tl0 * 132 + (m >> 1)] = pl;
            split2(p2, p3, ph, pl);
            Qh32[tl1 * 132 + (m >> 1)] = ph;
            Ql32[tl1 * 132 + (m >> 1)] = pl;
        }
    }
    __syncthreads();

    // out MMA: 16 warps, warp tile 16 tok x 40 d, k = 256 (m)
    const int tg = (w & 7) * 16;
    const int dgr = (w >> 3) * 40;

    float co[5][4];
    #pragma unroll
    for (int dt = 0; dt < 5; dt++)
        #pragma unroll
        for (int j = 0; j < 4; j++) co[dt][j] = 0.0f;

    #pragma unroll
    for (int kc = 0; kc < 16; kc++) {
        const int koff = kc * 16;
        unsigned ah[4], al[4];
        ah[0] = *(const unsigned*)(Qh + (tg + g)     * 528 + (koff + 2*tq) * 2);
        ah[1] = *(const unsigned*)(Qh + (tg + g + 8) * 528 + (koff + 2*tq) * 2);
        ah[2] = *(const unsigned*)(Qh + (tg + g)     * 528 + (koff + 8 + 2*tq) * 2);
        ah[3] = *(const unsigned*)(Qh + (tg + g + 8) * 528 + (koff + 8 + 2*tq) * 2);
        al[0] = *(const unsigned*)(Ql + (tg + g)     * 528 + (koff + 2*tq) * 2);
        al[1] = *(const unsigned*)(Ql + (tg + g + 8) * 528 + (koff + 2*tq) * 2);
        al[2] = *(const unsigned*)(Ql + (tg + g)     * 528 + (koff + 8 + 2*tq) * 2);
        al[3] = *(const unsigned*)(Ql + (tg + g + 8) * 528 + (koff + 8 + 2*tq) * 2);
        #pragma unroll
        for (int dt = 0; dt < 5; dt++) {
            const char* rh = Kh + (dgr + dt * 8 + g) * 528 + (koff + 2*tq) * 2;
            const char* rl = Kl + (dgr + dt * 8 + g) * 528 + (koff + 2*tq) * 2;
            unsigned bh0 = *(const unsigned*)(rh);
            unsigned bh1 = *(const unsigned*)(rh + 16);
            unsigned bl0 = *(const unsigned*)(rl);
            unsigned bl1 = *(const unsigned*)(rl + 16);
            mma16816(co[dt], ah, bh0, bh1);
            mma16816(co[dt], ah, bl0, bl1);
            mma16816(co[dt], al, bh0, bh1);
        }
    }

    // norm column (d = 64): warps with dgr=40, dt=3, tq==0
    if (dgr == 40 && tq == 0) {
        sn[tg + g]     = co[3][0];
        sn[tg + g + 8] = co[3][2];
    }
    __syncthreads();
    const float rn0 = 1.0f / sn[tg + g];
    const float rn1 = 1.0f / sn[tg + g + 8];

    float* op = out + (size_t)head * Dd * Nn + n0;
    #pragma unroll
    for (int dt = 0; dt < 5; dt++) {
        int d0 = dgr + dt * 8 + 2 * tq;
        if (d0 < 64) {
            op[(size_t)d0 * Nn + tg + g]           = co[dt][0] * rn0;
            op[(size_t)(d0 + 1) * Nn + tg + g]     = co[dt][1] * rn0;
            op[(size_t)d0 * Nn + tg + g + 8]       = co[dt][2] * rn1;
            op[(size_t)(d0 + 1) * Nn + tg + g + 8] = co[dt][3] * rn1;
        }
    }
}

// ---------------- launch ----------------
extern "C" void kernel_launch(void* const* d_in, const int* in_sizes, int n_in,
                              void* d_out, int out_size)
{
    const float* query = (const float*)d_in[0];
    const float* key   = (const float*)d_in[1];
    const float* value = (const float*)d_in[2];
    const float* proj  = (const float*)d_in[3];
    float* out = (float*)d_out;

    cudaFuncSetAttribute(k_kv_fused,  cudaFuncAttributeMaxDynamicSharedMemorySize, KF_SMEM);
    cudaFuncSetAttribute(k_out_fused, cudaFuncAttributeMaxDynamicSharedMemorySize, QF_SMEM);

    k_init<<<64, 256>>>(proj);
    k_vsum<<<dim3(64, 32), 256>>>(value);
    k_kv_fused<<<dim3(16, 32), 256, KF_SMEM>>>(key, value);
    k_reduce<<<2560, 256>>>();
    k_out_fused<<<dim3(64, 32), 512, QF_SMEM>>>(query, out);
}

// round 12
// speedup vs baseline: 1.7414x; 1.0182x over previous
#include <cuda_runtime.h>
#include <cuda_bf16.h>
#include <math.h>

#define Dd 64
#define Nn 8192
#define Mm 256
#define NH 32
#define DN     0.3535533905932738f   /* 64^-0.25 */
#define RATIO  0.0625f               /* 256^-0.5 */
#define REPS   6.25e-8f              /* RATIO * 1e-6 */
#define DIAGC  0.0625f               /* DN^2 * 0.5 */

typedef unsigned long long u64;

// ---------------- scratch (device globals; no allocation) ----------------
__device__ float g_smax[NH * 16];                       // per (head, slice) max raw u
__device__ float g_vsum[NH * 64];                       // R[h][d] = sum_n V
__device__ float g_kvpart[(size_t)NH * 16 * 80 * 256];  // [h*16+sl][d][m], scale exp(-Mr_sl)
__device__ __nv_bfloat16 g_kvth[(size_t)NH * 80 * 256]; // kv^T hi, [h][d][m] (d=64 -> knorm)
__device__ __nv_bfloat16 g_kvtl[(size_t)NH * 80 * 256]; // kv^T lo
__device__ __align__(16) __nv_bfloat16 g_pbh[256 * 64]; // proj*DN hi, [m][d]
__device__ __align__(16) __nv_bfloat16 g_pbl[256 * 64]; // proj*DN lo

// branch-free exp on FMA/ALU pipes. Valid for x <= 0, ~2.4e-6 rel err.
static __device__ __forceinline__ float fexp(float x) {
    float t = x * 1.4426950408889634f;
    t = fmaxf(t, -125.0f);
    float r  = t + 12582912.0f;
    float fi = r - 12582912.0f;
    float f  = t - fi;
    float p = 1.3333558e-3f;
    p = fmaf(p, f, 9.6181291e-3f);
    p = fmaf(p, f, 5.5504109e-2f);
    p = fmaf(p, f, 2.4022651e-1f);
    p = fmaf(p, f, 6.9314718e-1f);
    p = fmaf(p, f, 1.0f);
    int ib = __float_as_int(r) - 0x4B400000;
    float s = __int_as_float((ib + 127) << 23);
    return p * s;
}

// HMMA m16n8k16 bf16 -> fp32 accum
static __device__ __forceinline__ void mma16816(float c[4], const unsigned a[4],
                                                unsigned b0, unsigned b1) {
    asm volatile(
        "mma.sync.aligned.m16n8k16.row.col.f32.bf16.bf16.f32 "
        "{%0,%1,%2,%3}, {%4,%5,%6,%7}, {%8,%9}, {%0,%1,%2,%3};"
        : "+f"(c[0]), "+f"(c[1]), "+f"(c[2]), "+f"(c[3])
        : "r"(a[0]), "r"(a[1]), "r"(a[2]), "r"(a[3]), "r"(b0), "r"(b1));
}

// bf16 hi/lo split, packing pairs (v0,v1) -> (hi-pair, lo-pair)
static __device__ __forceinline__ void split2(float v0, float v1, unsigned& ph, unsigned& pl) {
    __nv_bfloat16 h0 = __float2bfloat16(v0);
    __nv_bfloat16 h1 = __float2bfloat16(v1);
    __nv_bfloat16 l0 = __float2bfloat16(v0 - __bfloat162float(h0));
    __nv_bfloat16 l1 = __float2bfloat16(v1 - __bfloat162float(h1));
    ph = ((unsigned)__bfloat16_as_ushort(h1) << 16) | __bfloat16_as_ushort(h0);
    pl = ((unsigned)__bfloat16_as_ushort(l1) << 16) | __bfloat16_as_ushort(l0);
}

// single-value bf16 split stored as 16-bit into hi/lo smem planes (144 B rows)
static __device__ __forceinline__ void sts_split(char* H, char* L, int m, int tok, float v) {
    __nv_bfloat16 h = __float2bfloat16(v);
    __nv_bfloat16 l = __float2bfloat16(v - __bfloat162float(h));
    *(unsigned short*)(H + m * 144 + tok * 2) = __bfloat16_as_ushort(h);
    *(unsigned short*)(L + m * 144 + tok * 2) = __bfloat16_as_ushort(l);
}

// ---------------- K0: bf16-split scaled proj ----------------
__global__ void k_init(const float* __restrict__ proj)
{
    int idx = blockIdx.x * 256 + threadIdx.x;   // 64 blocks x 256
    if (idx < 256 * 64) {
        float v = proj[idx] * DN;               // [m][d] layout preserved
        __nv_bfloat16 h = __float2bfloat16(v);
        g_pbh[idx] = h;
        g_pbl[idx] = __float2bfloat16(v - __bfloat162float(h));
    }
}

// ---------------- K_vsum: R[h][d] = sum_n V ----------------
__global__ void k_vsum(const float* __restrict__ value)
{
    __shared__ float red[8];
    const int h = blockIdx.y, d = blockIdx.x, t = threadIdx.x;
    const float4* src = (const float4*)(value + ((size_t)h * 64 + d) * Nn);
    float s = 0.0f;
    #pragma unroll
    for (int i = 0; i < 8; i++) {
        float4 v = src[t + 256 * i];
        s += (v.x + v.y) + (v.z + v.w);
    }
    #pragma unroll
    for (int o = 16; o; o >>= 1) s += __shfl_xor_sync(0xffffffffu, s, o);
    if ((t & 31) == 0) red[t >> 5] = s;
    __syncthreads();
    if (t == 0) {
        float r = 0.0f;
        #pragma unroll
        for (int w2 = 0; w2 < 8; w2++) r += red[w2];
        g_vsum[h * 64 + d] = r;
    }
}

// ---------------- K1 (fused): key proj + exp + kv accumulation -------------
// grid (16 slices, 32 heads), block 512 (16 warps).
// Per chunk of 64 tokens: proj MMA (warp 16tok x 64feat) -> online-max rescale
// -> E = exp(u - diag - Mr) into smem bf16 planes -> kv MMA (warp 32m x 40d).
#define KF_AH   0
#define KF_AL   9216
#define KF_PH   18432
#define KF_PL   55296
#define KF_EH   92160
#define KF_EL   129024
#define KF_VH   165888
#define KF_VL   177408
#define KF_SQP  188928
#define KF_SQ   190976
#define KF_RED  191232
#define KF_SMEM 191296

__global__ void __launch_bounds__(512, 1) k_kv_fused(const float* __restrict__ key,
                                                     const float* __restrict__ value)
{
    extern __shared__ char smem[];
    char* Ah = smem + KF_AH;   // [64 tok][72 bf16] (144 B rows)
    char* Al = smem + KF_AL;
    char* Ph = smem + KF_PH;   // [256 feat][72 bf16]
    char* Pl = smem + KF_PL;
    char* Eh = smem + KF_EH;   // [256 m][64 tok as k] hi
    char* El = smem + KF_EL;
    char* Vh = smem + KF_VH;   // [80 d][64 tok as k] hi
    char* Vl = smem + KF_VL;
    float* sqp = (float*)(smem + KF_SQP);   // [64][8]
    float* sq  = (float*)(smem + KF_SQ);    // [64]
    float* red = (float*)(smem + KF_RED);   // [16]

    const int t = threadIdx.x;
    const int head = blockIdx.y;
    const int slice = blockIdx.x;

    // stage P once
    #pragma unroll
    for (int cc = 0; cc < 4; cc++) {
        int e = t + 512 * cc;           // < 2048
        int row = e >> 3, j = e & 7;
        *(uint4*)(Ph + row * 144 + j * 16) = ((const uint4*)g_pbh)[e];
        *(uint4*)(Pl + row * 144 + j * 16) = ((const uint4*)g_pbl)[e];
    }
    // V const rows: row 64 = 1.0 (knorm via ones), rows 65..79 = 0
    for (int e = t; e < 576; e += 512) {
        int row = 64 + e / 36, col = e % 36;
        ((unsigned*)(Vh + row * 144))[col] = (row == 64) ? 0x3F803F80u : 0u;
        ((unsigned*)(Vl + row * 144))[col] = 0u;
    }

    const int w = t >> 5, lane = t & 31;
    const int g = lane >> 2, tq = lane & 3;
    const int tb = (w & 3) * 16;            // proj: token base (0..48)
    const int fb = (w >> 2) * 64;           // proj: feature base (0..192)
    const int mg = (w & 7) * 32;            // kv: m base (0..224)
    const int dgr = (w >> 3) * 40;          // kv: d base (0 or 40)
    const int tl0 = tb + g, tl1 = tb + g + 8;

    float Mr = -3.0e38f;                    // running slice max of raw u
    float c2[2][5][4];
    #pragma unroll
    for (int mt = 0; mt < 2; mt++)
        #pragma unroll
        for (int dt = 0; dt < 5; dt++)
            #pragma unroll
            for (int j = 0; j < 4; j++) c2[mt][dt][j] = 0.0f;

    const float* kp = key + (size_t)head * Dd * Nn;
    const float* vp = value + (size_t)head * Dd * Nn;

    for (int ch = 0; ch < 8; ch++) {
        const int n0 = slice * 512 + ch * 64;
        __syncthreads();   // prior kv MMA reads of E/V done; prior proj reads of A done

        // stage key chunk -> Ah/Al + partial sumsq (8 d per thread)
        {
            const int tok = t & 63, dblk = t >> 6;   // dblk in 0..7
            const float* xp = kp + n0 + tok;
            float s = 0.0f;
            #pragma unroll
            for (int i = 0; i < 4; i++) {
                int d = dblk * 8 + 2 * i;
                float v0 = xp[(size_t)d * Nn];
                float v1 = xp[(size_t)(d + 1) * Nn];
                s = fmaf(v0, v0, fmaf(v1, v1, s));
                unsigned ph, pl;
                split2(v0, v1, ph, pl);
                *(unsigned*)(Ah + tok * 144 + d * 2) = ph;
                *(unsigned*)(Al + tok * 144 + d * 2) = pl;
            }
            sqp[tok * 8 + dblk] = s;
        }
        // stage V chunk rows 0..63 (unscaled; scale lives in E), 8 floats/thread
        {
            int d = t >> 3, q = t & 7;
            const float* src = vp + (size_t)d * Nn + n0 + q * 8;
            unsigned* rowh = (unsigned*)(Vh + d * 144 + q * 16);
            unsigned* rowl = (unsigned*)(Vl + d * 144 + q * 16);
            #pragma unroll
            for (int i = 0; i < 2; i++) {
                float4 v = *(const float4*)(src + 4 * i);
                unsigned ph, pl;
                split2(v.x, v.y, ph, pl);
                rowh[2 * i] = ph;  rowl[2 * i] = pl;
                split2(v.z, v.w, ph, pl);
                rowh[2 * i + 1] = ph;  rowl[2 * i + 1] = pl;
            }
        }
        __syncthreads();
        if (t < 64) {
            float s = 0.0f;
            #pragma unroll
            for (int j = 0; j < 8; j++) s += sqp[t * 8 + j];
            sq[t] = s;
        }

        // proj MMA: u[tok][feat], warp tile 16 x 64
        float c[8][4];
        #pragma unroll
        for (int nt = 0; nt < 8; nt++)
            #pragma unroll
            for (int j = 0; j < 4; j++) c[nt][j] = 0.0f;

        #pragma unroll
        for (int k = 0; k < 4; k++) {
            const int koff = k * 16;
            unsigned ah[4], al[4];
            ah[0] = *(const unsigned*)(Ah + (tb + g)     * 144 + (koff + 2*tq) * 2);
            ah[1] = *(const unsigned*)(Ah + (tb + g + 8) * 144 + (koff + 2*tq) * 2);
            ah[2] = *(const unsigned*)(Ah + (tb + g)     * 144 + (koff + 8 + 2*tq) * 2);
            ah[3] = *(const unsigned*)(Ah + (tb + g + 8) * 144 + (koff + 8 + 2*tq) * 2);
            al[0] = *(const unsigned*)(Al + (tb + g)     * 144 + (koff + 2*tq) * 2);
            al[1] = *(const unsigned*)(Al + (tb + g + 8) * 144 + (koff + 2*tq) * 2);
            al[2] = *(const unsigned*)(Al + (tb + g)     * 144 + (koff + 8 + 2*tq) * 2);
            al[3] = *(const unsigned*)(Al + (tb + g + 8) * 144 + (koff + 8 + 2*tq) * 2);
            #pragma unroll
            for (int nt = 0; nt < 8; nt++) {
                const char* prow_h = Ph + (fb + nt * 8 + g) * 144 + (koff + 2*tq) * 2;
                const char* prow_l = Pl + (fb + nt * 8 + g) * 144 + (koff + 2*tq) * 2;
                unsigned bh0 = *(const unsigned*)(prow_h);
                unsigned bh1 = *(const unsigned*)(prow_h + 16);
                unsigned bl0 = *(const unsigned*)(prow_l);
                unsigned bl1 = *(const unsigned*)(prow_l + 16);
                mma16816(c[nt], ah, bh0, bh1);
                mma16816(c[nt], ah, bl0, bl1);
                mma16816(c[nt], al, bh0, bh1);
            }
        }

        // chunk max of raw u
        float bm = -3.4e38f;
        #pragma unroll
        for (int nt = 0; nt < 8; nt++)
            bm = fmaxf(bm, fmaxf(fmaxf(c[nt][0], c[nt][1]), fmaxf(c[nt][2], c[nt][3])));
        #pragma unroll
        for (int o = 16; o; o >>= 1) bm = fmaxf(bm, __shfl_xor_sync(0xffffffffu, bm, o));
        if (lane == 0) red[w] = bm;
        __syncthreads();                 // also guards sq + proj MMA smem reads
        float Mb = red[0];
        #pragma unroll
        for (int r2 = 1; r2 < 16; r2++) Mb = fmaxf(Mb, red[r2]);

        // online rescale
        float Mn = fmaxf(Mr, Mb);
        float rsc = fexp(Mr - Mn);
        #pragma unroll
        for (int mt = 0; mt < 2; mt++)
            #pragma unroll
            for (int dt = 0; dt < 5; dt++)
                #pragma unroll
                for (int j = 0; j < 4; j++) c2[mt][dt][j] *= rsc;
        Mr = Mn;

        // epilogue: E = exp(u - diag - Mr) -> Eh/El (16-bit scatter), 32 elems/thread
        const float dg0 = sq[tl0] * DIAGC;
        const float dg1 = sq[tl1] * DIAGC;
        #pragma unroll
        for (int nt = 0; nt < 8; nt++) {
            int m = fb + nt * 8 + 2 * tq;
            sts_split(Eh, El, m,     tl0, fexp(c[nt][0] - dg0 - Mr));
            sts_split(Eh, El, m + 1, tl0, fexp(c[nt][1] - dg0 - Mr));
            sts_split(Eh, El, m,     tl1, fexp(c[nt][2] - dg1 - Mr));
            sts_split(Eh, El, m + 1, tl1, fexp(c[nt][3] - dg1 - Mr));
        }
        __syncthreads();

        // kv MMA: c2[m][d] += E[m][n] * V[d][n], k = 64 tokens, warp tile 32m x 40d
        #pragma unroll
        for (int k = 0; k < 4; k++) {
            const int koff = k * 16;
            unsigned ah[2][4], al[2][4];
            #pragma unroll
            for (int mt = 0; mt < 2; mt++) {
                int r0 = mg + mt * 16 + g, r1 = r0 + 8;
                ah[mt][0] = *(const unsigned*)(Eh + r0 * 144 + (koff + 2*tq) * 2);
                ah[mt][1] = *(const unsigned*)(Eh + r1 * 144 + (koff + 2*tq) * 2);
                ah[mt][2] = *(const unsigned*)(Eh + r0 * 144 + (koff + 8 + 2*tq) * 2);
                ah[mt][3] = *(const unsigned*)(Eh + r1 * 144 + (koff + 8 + 2*tq) * 2);
                al[mt][0] = *(const unsigned*)(El + r0 * 144 + (koff + 2*tq) * 2);
                al[mt][1] = *(const unsigned*)(El + r1 * 144 + (koff + 2*tq) * 2);
                al[mt][2] = *(const unsigned*)(El + r0 * 144 + (koff + 8 + 2*tq) * 2);
                al[mt][3] = *(const unsigned*)(El + r1 * 144 + (koff + 8 + 2*tq) * 2);
            }
            #pragma unroll
            for (int dt = 0; dt < 5; dt++) {
                const char* rh = Vh + (dgr + dt * 8 + g) * 144 + (koff + 2*tq) * 2;
                const char* rl = Vl + (dgr + dt * 8 + g) * 144 + (koff + 2*tq) * 2;
                unsigned bh0 = *(const unsigned*)(rh);
                unsigned bh1 = *(const unsigned*)(rh + 16);
                unsigned bl0 = *(const unsigned*)(rl);
                unsigned bl1 = *(const unsigned*)(rl + 16);
                #pragma unroll
                for (int mt = 0; mt < 2; mt++) {
                    mma16816(c2[mt][dt], ah[mt], bh0, bh1);
                    mma16816(c2[mt][dt], ah[mt], bl0, bl1);
                    mma16816(c2[mt][dt], al[mt], bh0, bh1);
                }
            }
        }
    }

    if (t == 0) g_smax[head * 16 + slice] = Mr;

    // write partials [d][m]
    float* dst = g_kvpart + (size_t)(head * 16 + slice) * 20480;
    #pragma unroll
    for (int mt = 0; mt < 2; mt++) {
        int m0 = mg + mt * 16 + g, m1 = m0 + 8;
        #pragma unroll
        for (int dt = 0; dt < 5; dt++) {
            int d0 = dgr + dt * 8 + 2 * tq;
            dst[d0 * 256 + m0]       = c2[mt][dt][0];
            dst[(d0 + 1) * 256 + m0] = c2[mt][dt][1];
            dst[d0 * 256 + m1]       = c2[mt][dt][2];
            dst[(d0 + 1) * 256 + m1] = c2[mt][dt][3];
        }
    }
}

// ---------------- K2: reduce partials (rescale per slice) -> bf16 kv^T -----
__global__ void k_reduce()
{
    int idx = blockIdx.x * 256 + threadIdx.x;   // < 32*80*256 = 655360
    int h = idx / 20480;
    int rem = idx - h * 20480;
    int d = rem >> 8;
    float Mh = g_smax[h * 16];
    #pragma unroll
    for (int sl = 1; sl < 16; sl++) Mh = fmaxf(Mh, g_smax[h * 16 + sl]);
    float s = 0.0f;
    #pragma unroll
    for (int sl = 0; sl < 16; sl++) {
        float sc = fexp(g_smax[h * 16 + sl] - Mh);
        s = fmaf(g_kvpart[(size_t)(h * 16 + sl) * 20480 + rem], sc, s);
    }
    float corr = (d < 64) ? REPS * g_vsum[h * 64 + d]
               : (d == 64 ? REPS * 8192.0f : 0.0f);
    float val = fmaf(RATIO, s, corr);
    __nv_bfloat16 hi = __float2bfloat16(val);
    g_kvth[idx] = hi;
    g_kvtl[idx] = __float2bfloat16(val - __bfloat162float(hi));
}

// ---------------- K3 (fused): query proj + phi + out GEMM + divide ---------
// grid (64, 32), block 512 (16 warps). 128 tokens per block.
#define QF_AH   0
#define QF_AL   18432
#define QF_PH   36864
#define QF_PL   73728
#define QF_QH   0          /* phase B: [128 tok][264 bf16] 528 B rows (reuses A/P) */
#define QF_QL   67584
#define QF_KH   135168     /* [80 d][264 bf16] */
#define QF_KL   177408
#define QF_SQP  219648
#define QF_SQ   221696
#define QF_SMAX 222208
#define QF_SN   223232
#define QF_SMEM 223744

__global__ void __launch_bounds__(512, 1) k_out_fused(const float* __restrict__ query,
                                                      float* __restrict__ out)
{
    extern __shared__ char smem[];
    char* Ah = smem + QF_AH;    // [128 tok][72 bf16] (144 B rows)
    char* Al = smem + QF_AL;
    char* Ph = smem + QF_PH;    // [256 feat][72 bf16]
    char* Pl = smem + QF_PL;
    char* Qh = smem + QF_QH;    // phase B
    char* Ql = smem + QF_QL;
    char* Kh = smem + QF_KH;
    char* Kl = smem + QF_KL;
    float* sqp  = (float*)(smem + QF_SQP);   // [128][4]
    float* sq   = (float*)(smem + QF_SQ);    // [128]
    float* smax = (float*)(smem + QF_SMAX);  // [2][128]
    float* sn   = (float*)(smem + QF_SN);    // [128]

    const int t = threadIdx.x;
    const int head = blockIdx.y;
    const int n0 = blockIdx.x * 128;

    // stage query chunk -> Ah/Al + partial sumsq
    {
        const int tok = t & 127, dblk = t >> 7;   // 4 dblks of 16 d
        const float* xp = query + (size_t)head * Dd * Nn + n0 + tok;
        float s = 0.0f;
        #pragma unroll
        for (int i = 0; i < 8; i++) {
            int d = dblk * 16 + 2 * i;
            float v0 = xp[(size_t)d * Nn];
            float v1 = xp[(size_t)(d + 1) * Nn];
            s = fmaf(v0, v0, fmaf(v1, v1, s));
            unsigned ph, pl;
            split2(v0, v1, ph, pl);
            *(unsigned*)(Ah + tok * 144 + d * 2) = ph;
            *(unsigned*)(Al + tok * 144 + d * 2) = pl;
        }
        sqp[tok * 4 + dblk] = s;
    }
    // stage P
    #pragma unroll
    for (int cc = 0; cc < 4; cc++) {
        int e = t + 512 * cc;           // < 2048
        int row = e >> 3, j = e & 7;
        *(uint4*)(Ph + row * 144 + j * 16) = ((const uint4*)g_pbh)[e];
        *(uint4*)(Pl + row * 144 + j * 16) = ((const uint4*)g_pbl)[e];
    }
    // stage kv^T pairs (region disjoint from phase A)
    if (t < 320) {
        int row = t >> 2, q = t & 3;
        const uint4* sh = (const uint4*)(g_kvth + ((size_t)head * 80 + row) * 256 + q * 64);
        const uint4* sl = (const uint4*)(g_kvtl + ((size_t)head * 80 + row) * 256 + q * 64);
        uint4* dh = (uint4*)(Kh + row * 528 + q * 128);
        uint4* dl = (uint4*)(Kl + row * 528 + q * 128);
        #pragma unroll
        for (int j = 0; j < 8; j++) { dh[j] = sh[j]; dl[j] = sl[j]; }
    }
    __syncthreads();
    if (t < 128) sq[t] = sqp[4*t] + sqp[4*t+1] + sqp[4*t+2] + sqp[4*t+3];

    const int w = t >> 5, lane = t & 31;
    const int g = lane >> 2, tq = lane & 3;
    const int tb = (w & 7) * 16;            // proj: token base (0..112)
    const int fb = (w >> 3) * 128;          // proj: feature base
    const int tl0 = tb + g, tl1 = tb + g + 8;

    // proj MMA
    float c[16][4];
    #pragma unroll
    for (int nt = 0; nt < 16; nt++)
        #pragma unroll
        for (int j = 0; j < 4; j++) c[nt][j] = 0.0f;

    #pragma unroll
    for (int k = 0; k < 4; k++) {
        const int koff = k * 16;
        unsigned ah[4], al[4];
        ah[0] = *(const unsigned*)(Ah + (tb + g)     * 144 + (koff + 2*tq) * 2);
        ah[1] = *(const unsigned*)(Ah + (tb + g + 8) * 144 + (koff + 2*tq) * 2);
        ah[2] = *(const unsigned*)(Ah + (tb + g)     * 144 + (koff + 8 + 2*tq) * 2);
        ah[3] = *(const unsigned*)(Ah + (tb + g + 8) * 144 + (koff + 8 + 2*tq) * 2);
        al[0] = *(const unsigned*)(Al + (tb + g)     * 144 + (koff + 2*tq) * 2);
        al[1] = *(const unsigned*)(Al + (tb + g + 8) * 144 + (koff + 2*tq) * 2);
        al[2] = *(const unsigned*)(Al + (tb + g)     * 144 + (koff + 8 + 2*tq) * 2);
        al[3] = *(const unsigned*)(Al + (tb + g + 8) * 144 + (koff + 8 + 2*tq) * 2);
        #pragma unroll
        for (int nt = 0; nt < 16; nt++) {
            const char* prow_h = Ph + (fb + nt * 8 + g) * 144 + (koff + 2*tq) * 2;
            const char* prow_l = Pl + (fb + nt * 8 + g) * 144 + (koff + 2*tq) * 2;
            unsigned bh0 = *(const unsigned*)(prow_h);
            unsigned bh1 = *(const unsigned*)(prow_h + 16);
            unsigned bl0 = *(const unsigned*)(prow_l);
            unsigned bl1 = *(const unsigned*)(prow_l + 16);
            mma16816(c[nt], ah, bh0, bh1);
            mma16816(c[nt], ah, bl0, bl1);
            mma16816(c[nt], al, bh0, bh1);
        }
    }

    // per-token max over features (two feature-halves combined via smem)
    {
        float m0 = -3.4e38f, m1 = -3.4e38f;
        #pragma unroll
        for (int nt = 0; nt < 16; nt++) {
            m0 = fmaxf(m0, fmaxf(c[nt][0], c[nt][1]));
            m1 = fmaxf(m1, fmaxf(c[nt][2], c[nt][3]));
        }
        m0 = fmaxf(m0, __shfl_xor_sync(0xffffffffu, m0, 1));
        m0 = fmaxf(m0, __shfl_xor_sync(0xffffffffu, m0, 2));
        m1 = fmaxf(m1, __shfl_xor_sync(0xffffffffu, m1, 1));
        m1 = fmaxf(m1, __shfl_xor_sync(0xffffffffu, m1, 2));
        if (tq == 0) {
            smax[(w >> 3) * 128 + tl0] = m0;
            smax[(w >> 3) * 128 + tl1] = m1;
        }
    }
    __syncthreads();   // proj MMA smem reads done; smax/sq ready

    // epilogue: phi_q -> Qh/Ql (pairs along m)
    {
        const float dg0 = sq[tl0] * DIAGC;
        const float dg1 = sq[tl1] * DIAGC;
        const float cc0 = -dg0 - fmaxf(smax[tl0], smax[128 + tl0]);
        const float cc1 = -dg1 - fmaxf(smax[tl1], smax[128 + tl1]);
        unsigned* Qh32 = (unsigned*)Qh;   // rows of 132 u32 (528 B)
        unsigned* Ql32 = (unsigned*)Ql;
        #pragma unroll
        for (int nt = 0; nt < 16; nt++) {
            int m = fb + nt * 8 + 2 * tq;
            float p0 = RATIO * fexp(c[nt][0] + cc0) + REPS;
            float p1 = RATIO * fexp(c[nt][1] + cc0) + REPS;
            float p2 = RATIO * fexp(c[nt][2] + cc1) + REPS;
            float p3 = RATIO * fexp(c[nt][3] + cc1) + REPS;
            unsigned ph, pl;
            split2(p0, p1, ph, pl);
            Qh32[tl0 * 132 + (m >> 1)] = ph;
            Ql32[tl0 * 132 + (m >> 1)] = pl;
            split2(p2, p3, ph, pl);
            Qh32[tl1 * 132 + (m >> 1)] = ph;
            Ql32[tl1 * 132 + (m >> 1)] = pl;
        }
    }
    __syncthreads();

    // out MMA: 16 warps, warp tile 16 tok x 40 d, k = 256 (m)
    const int tg = (w & 7) * 16;
    const int dgr = (w >> 3) * 40;

    float co[5][4];
    #pragma unroll
    for (int dt = 0; dt < 5; dt++)
        #pragma unroll
        for (int j = 0; j < 4; j++) co[dt][j] = 0.0f;

    #pragma unroll
    for (int kc = 0; kc < 16; kc++) {
        const int koff = kc * 16;
        unsigned ah[4], al[4];
        ah[0] = *(const unsigned*)(Qh + (tg + g)     * 528 + (koff + 2*tq) * 2);
        ah[1] = *(const unsigned*)(Qh + (tg + g + 8) * 528 + (koff + 2*tq) * 2);
        ah[2] = *(const unsigned*)(Qh + (tg + g)     * 528 + (koff + 8 + 2*tq) * 2);
        ah[3] = *(const unsigned*)(Qh + (tg + g + 8) * 528 + (koff + 8 + 2*tq) * 2);
        al[0] = *(const unsigned*)(Ql + (tg + g)     * 528 + (koff + 2*tq) * 2);
        al[1] = *(const unsigned*)(Ql + (tg + g + 8) * 528 + (koff + 2*tq) * 2);
        al[2] = *(const unsigned*)(Ql + (tg + g)     * 528 + (koff + 8 + 2*tq) * 2);
        al[3] = *(const unsigned*)(Ql + (tg + g + 8) * 528 + (koff + 8 + 2*tq) * 2);
        #pragma unroll
        for (int dt = 0; dt < 5; dt++) {
            const char* rh = Kh + (dgr + dt * 8 + g) * 528 + (koff + 2*tq) * 2;
            const char* rl = Kl + (dgr + dt * 8 + g) * 528 + (koff + 2*tq) * 2;
            unsigned bh0 = *(const unsigned*)(rh);
            unsigned bh1 = *(const unsigned*)(rh + 16);
            unsigned bl0 = *(const unsigned*)(rl);
            unsigned bl1 = *(const unsigned*)(rl + 16);
            mma16816(co[dt], ah, bh0, bh1);
            mma16816(co[dt], ah, bl0, bl1);
            mma16816(co[dt], al, bh0, bh1);
        }
    }

    // norm column (d = 64): warps with dgr=40, dt=3, tq==0
    if (dgr == 40 && tq == 0) {
        sn[tg + g]     = co[3][0];
        sn[tg + g + 8] = co[3][2];
    }
    __syncthreads();
    const float rn0 = 1.0f / sn[tg + g];
    const float rn1 = 1.0f / sn[tg + g + 8];

    float* op = out + (size_t)head * Dd * Nn + n0;
    #pragma unroll
    for (int dt = 0; dt < 5; dt++) {
        int d0 = dgr + dt * 8 + 2 * tq;
        if (d0 < 64) {
            op[(size_t)d0 * Nn + tg + g]           = co[dt][0] * rn0;
            op[(size_t)(d0 + 1) * Nn + tg + g]     = co[dt][1] * rn0;
            op[(size_t)d0 * Nn + tg + g + 8]       = co[dt][2] * rn1;
            op[(size_t)(d0 + 1) * Nn + tg + g + 8] = co[dt][3] * rn1;
        }
    }
}

// ---------------- launch ----------------
extern "C" void kernel_launch(void* const* d_in, const int* in_sizes, int n_in,
                              void* d_out, int out_size)
{
    const float* query = (const float*)d_in[0];
    const float* key   = (const float*)d_in[1];
    const float* value = (const float*)d_in[2];
    const float* proj  = (const float*)d_in[3];
    float* out = (float*)d_out;

    cudaFuncSetAttribute(k_kv_fused,  cudaFuncAttributeMaxDynamicSharedMemorySize, KF_SMEM);
    cudaFuncSetAttribute(k_out_fused, cudaFuncAttributeMaxDynamicSharedMemorySize, QF_SMEM);

    k_init<<<64, 256>>>(proj);
    k_vsum<<<dim3(64, 32), 256>>>(value);
    k_kv_fused<<<dim3(16, 32), 512, KF_SMEM>>>(key, value);
    k_reduce<<<2560, 256>>>();
    k_out_fused<<<dim3(64, 32), 512, QF_SMEM>>>(query, out);
}

// round 13
// speedup vs baseline: 1.7987x; 1.0329x over previous
#include <cuda_runtime.h>
#include <cuda_bf16.h>
#include <math.h>

#define Dd 64
#define Nn 8192
#define Mm 256
#define NH 32
#define DN     0.3535533905932738f   /* 64^-0.25 */
#define RATIO  0.0625f               /* 256^-0.5 */
#define REPS   6.25e-8f              /* RATIO * 1e-6 */
#define DIAGC  0.0625f               /* DN^2 * 0.5 */

typedef unsigned long long u64;

// ---------------- scratch (device globals; no allocation) ----------------
__device__ float g_smax[NH * 16];                       // per (head, slice) max raw u
__device__ float g_vsum[NH * 64];                       // R[h][d] = sum_n V
__device__ float g_kvpart[(size_t)NH * 16 * 80 * 256];  // [h*16+sl][d][m], scale exp(-Mr_sl)
__device__ __nv_bfloat16 g_kvth[(size_t)NH * 80 * 256]; // kv^T hi, [h][d][m] (d=64 -> knorm)
__device__ __nv_bfloat16 g_kvtl[(size_t)NH * 80 * 256]; // kv^T lo
__device__ __align__(16) __nv_bfloat16 g_pbh[256 * 64]; // proj*DN hi, [m][d]
__device__ __align__(16) __nv_bfloat16 g_pbl[256 * 64]; // proj*DN lo

// exp on MUFU (FMUL + MUFU.EX2): 2 instructions, ~2 ulp, frees FMA issue slots.
static __device__ __forceinline__ float fexp(float x) {
    return __expf(x);
}

// HMMA m16n8k16 bf16 -> fp32 accum
static __device__ __forceinline__ void mma16816(float c[4], const unsigned a[4],
                                                unsigned b0, unsigned b1) {
    asm volatile(
        "mma.sync.aligned.m16n8k16.row.col.f32.bf16.bf16.f32 "
        "{%0,%1,%2,%3}, {%4,%5,%6,%7}, {%8,%9}, {%0,%1,%2,%3};"
        : "+f"(c[0]), "+f"(c[1]), "+f"(c[2]), "+f"(c[3])
        : "r"(a[0]), "r"(a[1]), "r"(a[2]), "r"(a[3]), "r"(b0), "r"(b1));
}

// bf16 hi/lo split, packing pairs (v0,v1) -> (hi-pair, lo-pair)
static __device__ __forceinline__ void split2(float v0, float v1, unsigned& ph, unsigned& pl) {
    __nv_bfloat16 h0 = __float2bfloat16(v0);
    __nv_bfloat16 h1 = __float2bfloat16(v1);
    __nv_bfloat16 l0 = __float2bfloat16(v0 - __bfloat162float(h0));
    __nv_bfloat16 l1 = __float2bfloat16(v1 - __bfloat162float(h1));
    ph = ((unsigned)__bfloat16_as_ushort(h1) << 16) | __bfloat16_as_ushort(h0);
    pl = ((unsigned)__bfloat16_as_ushort(l1) << 16) | __bfloat16_as_ushort(l0);
}

// single-value bf16 split stored as 16-bit into hi/lo smem planes (144 B rows)
static __device__ __forceinline__ void sts_split(char* H, char* L, int m, int tok, float v) {
    __nv_bfloat16 h = __float2bfloat16(v);
    __nv_bfloat16 l = __float2bfloat16(v - __bfloat162float(h));
    *(unsigned short*)(H + m * 144 + tok * 2) = __bfloat16_as_ushort(h);
    *(unsigned short*)(L + m * 144 + tok * 2) = __bfloat16_as_ushort(l);
}

// ---------------- K0: bf16-split scaled proj ----------------
__global__ void k_init(const float* __restrict__ proj)
{
    int idx = blockIdx.x * 256 + threadIdx.x;   // 64 blocks x 256
    if (idx < 256 * 64) {
        float v = proj[idx] * DN;               // [m][d] layout preserved
        __nv_bfloat16 h = __float2bfloat16(v);
        g_pbh[idx] = h;
        g_pbl[idx] = __float2bfloat16(v - __bfloat162float(h));
    }
}

// ---------------- K_vsum: R[h][d] = sum_n V ----------------
__global__ void k_vsum(const float* __restrict__ value)
{
    __shared__ float red[8];
    const int h = blockIdx.y, d = blockIdx.x, t = threadIdx.x;
    const float4* src = (const float4*)(value + ((size_t)h * 64 + d) * Nn);
    float s = 0.0f;
    #pragma unroll
    for (int i = 0; i < 8; i++) {
        float4 v = src[t + 256 * i];
        s += (v.x + v.y) + (v.z + v.w);
    }
    #pragma unroll
    for (int o = 16; o; o >>= 1) s += __shfl_xor_sync(0xffffffffu, s, o);
    if ((t & 31) == 0) red[t >> 5] = s;
    __syncthreads();
    if (t == 0) {
        float r = 0.0f;
        #pragma unroll
        for (int w2 = 0; w2 < 8; w2++) r += red[w2];
        g_vsum[h * 64 + d] = r;
    }
}

// ---------------- K1 (fused): key proj + exp + kv accumulation -------------
// grid (16 slices, 32 heads), block 512 (16 warps).
#define KF_AH   0
#define KF_AL   9216
#define KF_PH   18432
#define KF_PL   55296
#define KF_EH   92160
#define KF_EL   129024
#define KF_VH   165888
#define KF_VL   177408
#define KF_SQP  188928
#define KF_SQ   190976
#define KF_RED  191232
#define KF_SMEM 191296

__global__ void __launch_bounds__(512, 1) k_kv_fused(const float* __restrict__ key,
                                                     const float* __restrict__ value)
{
    extern __shared__ char smem[];
    char* Ah = smem + KF_AH;   // [64 tok][72 bf16] (144 B rows)
    char* Al = smem + KF_AL;
    char* Ph = smem + KF_PH;   // [256 feat][72 bf16]
    char* Pl = smem + KF_PL;
    char* Eh = smem + KF_EH;   // [256 m][64 tok as k] hi
    char* El = smem + KF_EL;
    char* Vh = smem + KF_VH;   // [80 d][64 tok as k] hi
    char* Vl = smem + KF_VL;
    float* sqp = (float*)(smem + KF_SQP);   // [64][8]
    float* sq  = (float*)(smem + KF_SQ);    // [64]
    float* red = (float*)(smem + KF_RED);   // [16]

    const int t = threadIdx.x;
    const int head = blockIdx.y;
    const int slice = blockIdx.x;

    // stage P once
    #pragma unroll
    for (int cc = 0; cc < 4; cc++) {
        int e = t + 512 * cc;           // < 2048
        int row = e >> 3, j = e & 7;
        *(uint4*)(Ph + row * 144 + j * 16) = ((const uint4*)g_pbh)[e];
        *(uint4*)(Pl + row * 144 + j * 16) = ((const uint4*)g_pbl)[e];
    }
    // V const rows: row 64 = 1.0 (knorm via ones), rows 65..79 = 0
    for (int e = t; e < 576; e += 512) {
        int row = 64 + e / 36, col = e % 36;
        ((unsigned*)(Vh + row * 144))[col] = (row == 64) ? 0x3F803F80u : 0u;
        ((unsigned*)(Vl + row * 144))[col] = 0u;
    }

    const int w = t >> 5, lane = t & 31;
    const int g = lane >> 2, tq = lane & 3;
    const int tb = (w & 3) * 16;            // proj: token base (0..48)
    const int fb = (w >> 2) * 64;           // proj: feature base (0..192)
    const int mg = (w & 7) * 32;            // kv: m base (0..224)
    const int dgr = (w >> 3) * 40;          // kv: d base (0 or 40)
    const int tl0 = tb + g, tl1 = tb + g + 8;

    float Mr = -3.0e38f;                    // running slice max of raw u
    float c2[2][5][4];
    #pragma unroll
    for (int mt = 0; mt < 2; mt++)
        #pragma unroll
        for (int dt = 0; dt < 5; dt++)
            #pragma unroll
            for (int j = 0; j < 4; j++) c2[mt][dt][j] = 0.0f;

    const float* kp = key + (size_t)head * Dd * Nn;
    const float* vp = value + (size_t)head * Dd * Nn;

    for (int ch = 0; ch < 8; ch++) {
        const int n0 = slice * 512 + ch * 64;
        __syncthreads();   // prior kv MMA reads of E/V done; prior proj reads of A done

        // stage key chunk -> Ah/Al + partial sumsq (8 d per thread)
        {
            const int tok = t & 63, dblk = t >> 6;   // dblk in 0..7
            const float* xp = kp + n0 + tok;
            float s = 0.0f;
            #pragma unroll
            for (int i = 0; i < 4; i++) {
                int d = dblk * 8 + 2 * i;
                float v0 = xp[(size_t)d * Nn];
                float v1 = xp[(size_t)(d + 1) * Nn];
                s = fmaf(v0, v0, fmaf(v1, v1, s));
                unsigned ph, pl;
                split2(v0, v1, ph, pl);
                *(unsigned*)(Ah + tok * 144 + d * 2) = ph;
                *(unsigned*)(Al + tok * 144 + d * 2) = pl;
            }
            sqp[tok * 8 + dblk] = s;
        }
        // stage V chunk rows 0..63 (unscaled; scale lives in E), 8 floats/thread
        {
            int d = t >> 3, q = t & 7;
            const float* src = vp + (size_t)d * Nn + n0 + q * 8;
            unsigned* rowh = (unsigned*)(Vh + d * 144 + q * 16);
            unsigned* rowl = (unsigned*)(Vl + d * 144 + q * 16);
            #pragma unroll
            for (int i = 0; i < 2; i++) {
                float4 v = *(const float4*)(src + 4 * i);
                unsigned ph, pl;
                split2(v.x, v.y, ph, pl);
                rowh[2 * i] = ph;  rowl[2 * i] = pl;
                split2(v.z, v.w, ph, pl);
                rowh[2 * i + 1] = ph;  rowl[2 * i + 1] = pl;
            }
        }
        __syncthreads();
        if (t < 64) {
            float s = 0.0f;
            #pragma unroll
            for (int j = 0; j < 8; j++) s += sqp[t * 8 + j];
            sq[t] = s;
        }

        // proj MMA: u[tok][feat], warp tile 16 x 64
        float c[8][4];
        #pragma unroll
        for (int nt = 0; nt < 8; nt++)
            #pragma unroll
            for (int j = 0; j < 4; j++) c[nt][j] = 0.0f;

        #pragma unroll
        for (int k = 0; k < 4; k++) {
            const int koff = k * 16;
            unsigned ah[4], al[4];
            ah[0] = *(const unsigned*)(Ah + (tb + g)     * 144 + (koff + 2*tq) * 2);
            ah[1] = *(const unsigned*)(Ah + (tb + g + 8) * 144 + (koff + 2*tq) * 2);
            ah[2] = *(const unsigned*)(Ah + (tb + g)     * 144 + (koff + 8 + 2*tq) * 2);
            ah[3] = *(const unsigned*)(Ah + (tb + g + 8) * 144 + (koff + 8 + 2*tq) * 2);
            al[0] = *(const unsigned*)(Al + (tb + g)     * 144 + (koff + 2*tq) * 2);
            al[1] = *(const unsigned*)(Al + (tb + g + 8) * 144 + (koff + 2*tq) * 2);
            al[2] = *(const unsigned*)(Al + (tb + g)     * 144 + (koff + 8 + 2*tq) * 2);
            al[3] = *(const unsigned*)(Al + (tb + g + 8) * 144 + (koff + 8 + 2*tq) * 2);
            #pragma unroll
            for (int nt = 0; nt < 8; nt++) {
                const char* prow_h = Ph + (fb + nt * 8 + g) * 144 + (koff + 2*tq) * 2;
                const char* prow_l = Pl + (fb + nt * 8 + g) * 144 + (koff + 2*tq) * 2;
                unsigned bh0 = *(const unsigned*)(prow_h);
                unsigned bh1 = *(const unsigned*)(prow_h + 16);
                unsigned bl0 = *(const unsigned*)(prow_l);
                unsigned bl1 = *(const unsigned*)(prow_l + 16);
                mma16816(c[nt], ah, bh0, bh1);
                mma16816(c[nt], ah, bl0, bl1);
                mma16816(c[nt], al, bh0, bh1);
            }
        }

        // chunk max of raw u
        float bm = -3.4e38f;
        #pragma unroll
        for (int nt = 0; nt < 8; nt++)
            bm = fmaxf(bm, fmaxf(fmaxf(c[nt][0], c[nt][1]), fmaxf(c[nt][2], c[nt][3])));
        #pragma unroll
        for (int o = 16; o; o >>= 1) bm = fmaxf(bm, __shfl_xor_sync(0xffffffffu, bm, o));
        if (lane == 0) red[w] = bm;
        __syncthreads();                 // also guards sq + proj MMA smem reads
        float Mb = red[0];
        #pragma unroll
        for (int r2 = 1; r2 < 16; r2++) Mb = fmaxf(Mb, red[r2]);

        // online rescale
        float Mn = fmaxf(Mr, Mb);
        float rsc = fexp(Mr - Mn);
        #pragma unroll
        for (int mt = 0; mt < 2; mt++)
            #pragma unroll
            for (int dt = 0; dt < 5; dt++)
                #pragma unroll
                for (int j = 0; j < 4; j++) c2[mt][dt][j] *= rsc;
        Mr = Mn;

        // epilogue: E = exp(u - diag - Mr) -> Eh/El (16-bit scatter), 32 elems/thread
        const float dg0 = sq[tl0] * DIAGC;
        const float dg1 = sq[tl1] * DIAGC;
        #pragma unroll
        for (int nt = 0; nt < 8; nt++) {
            int m = fb + nt * 8 + 2 * tq;
            sts_split(Eh, El, m,     tl0, fexp(c[nt][0] - dg0 - Mr));
            sts_split(Eh, El, m + 1, tl0, fexp(c[nt][1] - dg0 - Mr));
            sts_split(Eh, El, m,     tl1, fexp(c[nt][2] - dg1 - Mr));
            sts_split(Eh, El, m + 1, tl1, fexp(c[nt][3] - dg1 - Mr));
        }
        __syncthreads();

        // kv MMA: c2[m][d] += E[m][n] * V[d][n], k = 64 tokens, warp tile 32m x 40d
        #pragma unroll
        for (int k = 0; k < 4; k++) {
            const int koff = k * 16;
            unsigned ah[2][4], al[2][4];
            #pragma unroll
            for (int mt = 0; mt < 2; mt++) {
                int r0 = mg + mt * 16 + g, r1 = r0 + 8;
                ah[mt][0] = *(const unsigned*)(Eh + r0 * 144 + (koff + 2*tq) * 2);
                ah[mt][1] = *(const unsigned*)(Eh + r1 * 144 + (koff + 2*tq) * 2);
                ah[mt][2] = *(const unsigned*)(Eh + r0 * 144 + (koff + 8 + 2*tq) * 2);
                ah[mt][3] = *(const unsigned*)(Eh + r1 * 144 + (koff + 8 + 2*tq) * 2);
                al[mt][0] = *(const unsigned*)(El + r0 * 144 + (koff + 2*tq) * 2);
                al[mt][1] = *(const unsigned*)(El + r1 * 144 + (koff + 2*tq) * 2);
                al[mt][2] = *(const unsigned*)(El + r0 * 144 + (koff + 8 + 2*tq) * 2);
                al[mt][3] = *(const unsigned*)(El + r1 * 144 + (koff + 8 + 2*tq) * 2);
            }
            #pragma unroll
            for (int dt = 0; dt < 5; dt++) {
                const char* rh = Vh + (dgr + dt * 8 + g) * 144 + (koff + 2*tq) * 2;
                const char* rl = Vl + (dgr + dt * 8 + g) * 144 + (koff + 2*tq) * 2;
                unsigned bh0 = *(const unsigned*)(rh);
                unsigned bh1 = *(const unsigned*)(rh + 16);
                unsigned bl0 = *(const unsigned*)(rl);
                unsigned bl1 = *(const unsigned*)(rl + 16);
                #pragma unroll
                for (int mt = 0; mt < 2; mt++) {
                    mma16816(c2[mt][dt], ah[mt], bh0, bh1);
                    mma16816(c2[mt][dt], ah[mt], bl0, bl1);
                    mma16816(c2[mt][dt], al[mt], bh0, bh1);
                }
            }
        }
    }

    if (t == 0) g_smax[head * 16 + slice] = Mr;

    // write partials [d][m]
    float* dst = g_kvpart + (size_t)(head * 16 + slice) * 20480;
    #pragma unroll
    for (int mt = 0; mt < 2; mt++) {
        int m0 = mg + mt * 16 + g, m1 = m0 + 8;
        #pragma unroll
        for (int dt = 0; dt < 5; dt++) {
            int d0 = dgr + dt * 8 + 2 * tq;
            dst[d0 * 256 + m0]       = c2[mt][dt][0];
            dst[(d0 + 1) * 256 + m0] = c2[mt][dt][1];
            dst[d0 * 256 + m1]       = c2[mt][dt][2];
            dst[(d0 + 1) * 256 + m1] = c2[mt][dt][3];
        }
    }
}

// ---------------- K2: reduce partials (rescale per slice) -> bf16 kv^T -----
__global__ void k_reduce()
{
    int idx = blockIdx.x * 256 + threadIdx.x;   // < 32*80*256 = 655360
    int h = idx / 20480;
    int rem = idx - h * 20480;
    int d = rem >> 8;
    float Mh = g_smax[h * 16];
    #pragma unroll
    for (int sl = 1; sl < 16; sl++) Mh = fmaxf(Mh, g_smax[h * 16 + sl]);
    float s = 0.0f;
    #pragma unroll
    for (int sl = 0; sl < 16; sl++) {
        float sc = fexp(g_smax[h * 16 + sl] - Mh);
        s = fmaf(g_kvpart[(size_t)(h * 16 + sl) * 20480 + rem], sc, s);
    }
    float corr = (d < 64) ? REPS * g_vsum[h * 64 + d]
               : (d == 64 ? REPS * 8192.0f : 0.0f);
    float val = fmaf(RATIO, s, corr);
    __nv_bfloat16 hi = __float2bfloat16(val);
    g_kvth[idx] = hi;
    g_kvtl[idx] = __float2bfloat16(val - __bfloat162float(hi));
}

// ---------------- K3 (fused): query proj + phi + out GEMM + divide ---------
// grid (64, 32), block 512 (16 warps). 128 tokens per block.
#define QF_AH   0
#define QF_AL   18432
#define QF_PH   36864
#define QF_PL   73728
#define QF_QH   0          /* phase B: [128 tok][264 bf16] 528 B rows (reuses A/P) */
#define QF_QL   67584
#define QF_KH   135168     /* [80 d][264 bf16] */
#define QF_KL   177408
#define QF_SQP  219648
#define QF_SQ   221696
#define QF_SMAX 222208
#define QF_SN   223232
#define QF_SMEM 223744

__global__ void __launch_bounds__(512, 1) k_out_fused(const float* __restrict__ query,
                                                      float* __restrict__ out)
{
    extern __shared__ char smem[];
    char* Ah = smem + QF_AH;    // [128 tok][72 bf16] (144 B rows)
    char* Al = smem + QF_AL;
    char* Ph = smem + QF_PH;    // [256 feat][72 bf16]
    char* Pl = smem + QF_PL;
    char* Qh = smem + QF_QH;    // phase B
    char* Ql = smem + QF_QL;
    char* Kh = smem + QF_KH;
    char* Kl = smem + QF_KL;
    float* sqp  = (float*)(smem + QF_SQP);   // [128][4]
    float* sq   = (float*)(smem + QF_SQ);    // [128]
    float* smax = (float*)(smem + QF_SMAX);  // [2][128]
    float* sn   = (float*)(smem + QF_SN);    // [128]

    const int t = threadIdx.x;
    const int head = blockIdx.y;
    const int n0 = blockIdx.x * 128;

    // stage kv^T pairs FIRST (LDGs issue earliest; region disjoint from phase A)
    if (t < 320) {
        int row = t >> 2, q = t & 3;
        const uint4* sh = (const uint4*)(g_kvth + ((size_t)head * 80 + row) * 256 + q * 64);
        const uint4* sl = (const uint4*)(g_kvtl + ((size_t)head * 80 + row) * 256 + q * 64);
        uint4* dh = (uint4*)(Kh + row * 528 + q * 128);
        uint4* dl = (uint4*)(Kl + row * 528 + q * 128);
        #pragma unroll
        for (int j = 0; j < 8; j++) { dh[j] = sh[j]; dl[j] = sl[j]; }
    }
    // stage query chunk -> Ah/Al + partial sumsq
    {
        const int tok = t & 127, dblk = t >> 7;   // 4 dblks of 16 d
        const float* xp = query + (size_t)head * Dd * Nn + n0 + tok;
        float s = 0.0f;
        #pragma unroll
        for (int i = 0; i < 8; i++) {
            int d = dblk * 16 + 2 * i;
            float v0 = xp[(size_t)d * Nn];
            float v1 = xp[(size_t)(d + 1) * Nn];
            s = fmaf(v0, v0, fmaf(v1, v1, s));
            unsigned ph, pl;
            split2(v0, v1, ph, pl);
            *(unsigned*)(Ah + tok * 144 + d * 2) = ph;
            *(unsigned*)(Al + tok * 144 + d * 2) = pl;
        }
        sqp[tok * 4 + dblk] = s;
    }
    // stage P
    #pragma unroll
    for (int cc = 0; cc < 4; cc++) {
        int e = t + 512 * cc;           // < 2048
        int row = e >> 3, j = e & 7;
        *(uint4*)(Ph + row * 144 + j * 16) = ((const uint4*)g_pbh)[e];
        *(uint4*)(Pl + row * 144 + j * 16) = ((const uint4*)g_pbl)[e];
    }
    __syncthreads();
    if (t < 128) sq[t] = sqp[4*t] + sqp[4*t+1] + sqp[4*t+2] + sqp[4*t+3];

    const int w = t >> 5, lane = t & 31;
    const int g = lane >> 2, tq = lane & 3;
    const int tb = (w & 7) * 16;            // proj: token base (0..112)
    const int fb = (w >> 3) * 128;          // proj: feature base
    const int tl0 = tb + g, tl1 = tb + g + 8;

    // proj MMA
    float c[16][4];
    #pragma unroll
    for (int nt = 0; nt < 16; nt++)
        #pragma unroll
        for (int j = 0; j < 4; j++) c[nt][j] = 0.0f;

    #pragma unroll
    for (int k = 0; k < 4; k++) {
        const int koff = k * 16;
        unsigned ah[4], al[4];
        ah[0] = *(const unsigned*)(Ah + (tb + g)     * 144 + (koff + 2*tq) * 2);
        ah[1] = *(const unsigned*)(Ah + (tb + g + 8) * 144 + (koff + 2*tq) * 2);
        ah[2] = *(const unsigned*)(Ah + (tb + g)     * 144 + (koff + 8 + 2*tq) * 2);
        ah[3] = *(const unsigned*)(Ah + (tb + g + 8) * 144 + (koff + 8 + 2*tq) * 2);
        al[0] = *(const unsigned*)(Al + (tb + g)     * 144 + (koff + 2*tq) * 2);
        al[1] = *(const unsigned*)(Al + (tb + g + 8) * 144 + (koff + 2*tq) * 2);
        al[2] = *(const unsigned*)(Al + (tb + g)     * 144 + (koff + 8 + 2*tq) * 2);
        al[3] = *(const unsigned*)(Al + (tb + g + 8) * 144 + (koff + 8 + 2*tq) * 2);
        #pragma unroll
        for (int nt = 0; nt < 16; nt++) {
            const char* prow_h = Ph + (fb + nt * 8 + g) * 144 + (koff + 2*tq) * 2;
            const char* prow_l = Pl + (fb + nt * 8 + g) * 144 + (koff + 2*tq) * 2;
            unsigned bh0 = *(const unsigned*)(prow_h);
            unsigned bh1 = *(const unsigned*)(prow_h + 16);
            unsigned bl0 = *(const unsigned*)(prow_l);
            unsigned bl1 = *(const unsigned*)(prow_l + 16);
            mma16816(c[nt], ah, bh0, bh1);
            mma16816(c[nt], ah, bl0, bl1);
            mma16816(c[nt], al, bh0, bh1);
        }
    }

    // per-token max over features (two feature-halves combined via smem)
    {
        float m0 = -3.4e38f, m1 = -3.4e38f;
        #pragma unroll
        for (int nt = 0; nt < 16; nt++) {
            m0 = fmaxf(m0, fmaxf(c[nt][0], c[nt][1]));
            m1 = fmaxf(m1, fmaxf(c[nt][2], c[nt][3]));
        }
        m0 = fmaxf(m0, __shfl_xor_sync(0xffffffffu, m0, 1));
        m0 = fmaxf(m0, __shfl_xor_sync(0xffffffffu, m0, 2));
        m1 = fmaxf(m1, __shfl_xor_sync(0xffffffffu, m1, 1));
        m1 = fmaxf(m1, __shfl_xor_sync(0xffffffffu, m1, 2));
        if (tq == 0) {
            smax[(w >> 3) * 128 + tl0] = m0;
            smax[(w >> 3) * 128 + tl1] = m1;
        }
    }
    __syncthreads();   // proj MMA smem reads done; smax/sq ready

    // epilogue: phi_q -> Qh/Ql (pairs along m)
    {
        const float dg0 = sq[tl0] * DIAGC;
        const float dg1 = sq[tl1] * DIAGC;
        const float cc0 = -dg0 - fmaxf(smax[tl0], smax[128 + tl0]);
        const float cc1 = -dg1 - fmaxf(smax[tl1], smax[128 + tl1]);
        unsigned* Qh32 = (unsigned*)Qh;   // rows of 132 u32 (528 B)
        unsigned* Ql32 = (unsigned*)Ql;
        #pragma unroll
        for (int nt = 0; nt < 16; nt++) {
            int m = fb + nt * 8 + 2 * tq;
            float p0 = RATIO * fexp(c[nt][0] + cc0) + REPS;
            float p1 = RATIO * fexp(c[nt][1] + cc0) + REPS;
            float p2 = RATIO * fexp(c[nt][2] + cc1) + REPS;
            float p3 = RATIO * fexp(c[nt][3] + cc1) + REPS;
            unsigned ph, pl;
            split2(p0, p1, ph, pl);
            Qh32[tl0 * 132 + (m >> 1)] = ph;
            Ql32[tl0 * 132 + (m >> 1)] = pl;
            split2(p2, p3, ph, pl);
            Qh32[tl1 * 132 + (m >> 1)] = ph;
            Ql32[tl1 * 132 + (m >> 1)] = pl;
        }
    }
    __syncthreads();

    // out MMA: 16 warps, warp tile 16 tok x 40 d, k = 256 (m)
    const int tg = (w & 7) * 16;
    const int dgr = (w >> 3) * 40;

    float co[5][4];
    #pragma unroll
    for (int dt = 0; dt < 5; dt++)
        #pragma unroll
        for (int j = 0; j < 4; j++) co[dt][j] = 0.0f;

    #pragma unroll
    for (int kc = 0; kc < 16; kc++) {
        const int koff = kc * 16;
        unsigned ah[4], al[4];
        ah[0] = *(const unsigned*)(Qh + (tg + g)     * 528 + (koff + 2*tq) * 2);
        ah[1] = *(const unsigned*)(Qh + (tg + g + 8) * 528 + (koff + 2*tq) * 2);
        ah[2] = *(const unsigned*)(Qh + (tg + g)     * 528 + (koff + 8 + 2*tq) * 2);
        ah[3] = *(const unsigned*)(Qh + (tg + g + 8) * 528 + (koff + 8 + 2*tq) * 2);
        al[0] = *(const unsigned*)(Ql + (tg + g)     * 528 + (koff + 2*tq) * 2);
        al[1] = *(const unsigned*)(Ql + (tg + g + 8) * 528 + (koff + 2*tq) * 2);
        al[2] = *(const unsigned*)(Ql + (tg + g)     * 528 + (koff + 8 + 2*tq) * 2);
        al[3] = *(const unsigned*)(Ql + (tg + g + 8) * 528 + (koff + 8 + 2*tq) * 2);
        #pragma unroll
        for (int dt = 0; dt < 5; dt++) {
            const char* rh = Kh + (dgr + dt * 8 + g) * 528 + (koff + 2*tq) * 2;
            const char* rl = Kl + (dgr + dt * 8 + g) * 528 + (koff + 2*tq) * 2;
            unsigned bh0 = *(const unsigned*)(rh);
            unsigned bh1 = *(const unsigned*)(rh + 16);
            unsigned bl0 = *(const unsigned*)(rl);
            unsigned bl1 = *(const unsigned*)(rl + 16);
            mma16816(co[dt], ah, bh0, bh1);
            mma16816(co[dt], ah, bl0, bl1);
            mma16816(co[dt], al, bh0, bh1);
        }
    }

    // norm column (d = 64): warps with dgr=40, dt=3, tq==0
    if (dgr == 40 && tq == 0) {
        sn[tg + g]     = co[3][0];
        sn[tg + g + 8] = co[3][2];
    }
    __syncthreads();
    const float rn0 = 1.0f / sn[tg + g];
    const float rn1 = 1.0f / sn[tg + g + 8];

    float* op = out + (size_t)head * Dd * Nn + n0;
    #pragma unroll
    for (int dt = 0; dt < 5; dt++) {
        int d0 = dgr + dt * 8 + 2 * tq;
        if (d0 < 64) {
            op[(size_t)d0 * Nn + tg + g]           = co[dt][0] * rn0;
            op[(size_t)(d0 + 1) * Nn + tg + g]     = co[dt][1] * rn0;
            op[(size_t)d0 * Nn + tg + g + 8]       = co[dt][2] * rn1;
            op[(size_t)(d0 + 1) * Nn + tg + g + 8] = co[dt][3] * rn1;
        }
    }
}

// ---------------- launch ----------------
extern "C" void kernel_launch(void* const* d_in, const int* in_sizes, int n_in,
                              void* d_out, int out_size)
{
    const float* query = (const float*)d_in[0];
    const float* key   = (const float*)d_in[1];
    const float* value = (const float*)d_in[2];
    const float* proj  = (const float*)d_in[3];
    float* out = (float*)d_out;

    cudaFuncSetAttribute(k_kv_fused,  cudaFuncAttributeMaxDynamicSharedMemorySize, KF_SMEM);
    cudaFuncSetAttribute(k_out_fused, cudaFuncAttributeMaxDynamicSharedMemorySize, QF_SMEM);

    k_init<<<64, 256>>>(proj);
    k_vsum<<<dim3(64, 32), 256>>>(value);
    k_kv_fused<<<dim3(16, 32), 512, KF_SMEM>>>(key, value);
    k_reduce<<<2560, 256>>>();
    k_out_fused<<<dim3(64, 32), 512, QF_SMEM>>>(query, out);
}

// round 14
// speedup vs baseline: 2.3335x; 1.2974x over previous
#include <cuda_runtime.h>
#include <cuda_bf16.h>
#include <cuda_fp16.h>
#include <math.h>

#define Dd 64
#define Nn 8192
#define Mm 256
#define NH 32
#define DN     0.3535533905932738f   /* 64^-0.25 */
#define RATIO  0.0625f               /* 256^-0.5 */
#define REPS   6.25e-8f              /* RATIO * 1e-6 */
#define DIAGC  0.0625f               /* DN^2 * 0.5 */

typedef unsigned long long u64;

// ---------------- scratch (device globals; no allocation) ----------------
__device__ float g_smax[NH * 16];                       // per (head, slice) max raw u
__device__ float g_vsum[NH * 64];                       // R[h][d] = sum_n V
__device__ float g_kvpart[(size_t)NH * 16 * 80 * 256];  // [h*16+sl][d][m], scale exp(-Mr_sl)
__device__ __half g_kvt[(size_t)NH * 80 * 256];         // kv^T fp16, [h][d][m] (d=64 -> knorm)
__device__ __align__(16) __nv_bfloat16 g_pbh[256 * 64]; // proj*DN hi, [m][d]
__device__ __align__(16) __nv_bfloat16 g_pbl[256 * 64]; // proj*DN lo

// exp on MUFU (FMUL + MUFU.EX2)
static __device__ __forceinline__ float fexp(float x) { return __expf(x); }

// HMMA m16n8k16 bf16 -> fp32 accum
static __device__ __forceinline__ void mma16816(float c[4], const unsigned a[4],
                                                unsigned b0, unsigned b1) {
    asm volatile(
        "mma.sync.aligned.m16n8k16.row.col.f32.bf16.bf16.f32 "
        "{%0,%1,%2,%3}, {%4,%5,%6,%7}, {%8,%9}, {%0,%1,%2,%3};"
        : "+f"(c[0]), "+f"(c[1]), "+f"(c[2]), "+f"(c[3])
        : "r"(a[0]), "r"(a[1]), "r"(a[2]), "r"(a[3]), "r"(b0), "r"(b1));
}
// HMMA m16n8k16 fp16 -> fp32 accum
static __device__ __forceinline__ void mma16816h(float c[4], const unsigned a[4],
                                                 unsigned b0, unsigned b1) {
    asm volatile(
        "mma.sync.aligned.m16n8k16.row.col.f32.f16.f16.f32 "
        "{%0,%1,%2,%3}, {%4,%5,%6,%7}, {%8,%9}, {%0,%1,%2,%3};"
        : "+f"(c[0]), "+f"(c[1]), "+f"(c[2]), "+f"(c[3])
        : "r"(a[0]), "r"(a[1]), "r"(a[2]), "r"(a[3]), "r"(b0), "r"(b1));
}

static __device__ __forceinline__ unsigned h2u(__half2 h) {
    return *reinterpret_cast<unsigned*>(&h);
}

// bf16 hi/lo split, packing pairs (v0,v1) -> (hi-pair, lo-pair)
static __device__ __forceinline__ void split2(float v0, float v1, unsigned& ph, unsigned& pl) {
    __nv_bfloat16 h0 = __float2bfloat16(v0);
    __nv_bfloat16 h1 = __float2bfloat16(v1);
    __nv_bfloat16 l0 = __float2bfloat16(v0 - __bfloat162float(h0));
    __nv_bfloat16 l1 = __float2bfloat16(v1 - __bfloat162float(h1));
    ph = ((unsigned)__bfloat16_as_ushort(h1) << 16) | __bfloat16_as_ushort(h0);
    pl = ((unsigned)__bfloat16_as_ushort(l1) << 16) | __bfloat16_as_ushort(l0);
}
// fp16 hi/lo split of a pair
static __device__ __forceinline__ void split2h(float v0, float v1, unsigned& ph, unsigned& pl) {
    __half2 h = __float22half2_rn(make_float2(v0, v1));
    float2 hf = __half22float2(h);
    __half2 l = __float22half2_rn(make_float2(v0 - hf.x, v1 - hf.y));
    ph = h2u(h);  pl = h2u(l);
}

// ---------------- K0: bf16-split scaled proj ----------------
__global__ void k_init(const float* __restrict__ proj)
{
    int idx = blockIdx.x * 256 + threadIdx.x;   // 64 blocks x 256
    if (idx < 256 * 64) {
        float v = proj[idx] * DN;               // [m][d] layout preserved
        __nv_bfloat16 h = __float2bfloat16(v);
        g_pbh[idx] = h;
        g_pbl[idx] = __float2bfloat16(v - __bfloat162float(h));
    }
}

// ---------------- K_vsum: R[h][d] = sum_n V ----------------
__global__ void k_vsum(const float* __restrict__ value)
{
    __shared__ float red[8];
    const int h = blockIdx.y, d = blockIdx.x, t = threadIdx.x;
    const float4* src = (const float4*)(value + ((size_t)h * 64 + d) * Nn);
    float s = 0.0f;
    #pragma unroll
    for (int i = 0; i < 8; i++) {
        float4 v = src[t + 256 * i];
        s += (v.x + v.y) + (v.z + v.w);
    }
    #pragma unroll
    for (int o = 16; o; o >>= 1) s += __shfl_xor_sync(0xffffffffu, s, o);
    if ((t & 31) == 0) red[t >> 5] = s;
    __syncthreads();
    if (t == 0) {
        float r = 0.0f;
        #pragma unroll
        for (int w2 = 0; w2 < 8; w2++) r += red[w2];
        g_vsum[h * 64 + d] = r;
    }
}

// ---------------- K1 (fused): key proj + exp + kv accumulation -------------
// grid (16 slices, 32 heads), block 512 (16 warps).
// proj MMA swapped: A = P (m rows), B = x (tok rows) -> u[m][tok].
// E stored fp16 hi/lo, V single fp16. kv MMA fp16 2-term.
#define KF_XH   0
#define KF_XL   9216
#define KF_PH   18432
#define KF_PL   55296
#define KF_EH   92160
#define KF_EL   129024
#define KF_VH   165888
#define KF_SQP  177408
#define KF_SQ   179456
#define KF_RED  179712
#define KF_SMEM 179776

__global__ void __launch_bounds__(512, 1) k_kv_fused(const float* __restrict__ key,
                                                     const float* __restrict__ value)
{
    extern __shared__ char smem[];
    char* Xh = smem + KF_XH;   // [64 tok][72 bf16] (144 B rows)
    char* Xl = smem + KF_XL;
    char* Ph = smem + KF_PH;   // [256 m][72 bf16]
    char* Pl = smem + KF_PL;
    char* Eh = smem + KF_EH;   // [256 m][64 tok] fp16 hi (144 B rows)
    char* El = smem + KF_EL;   // fp16 lo
    char* Vh = smem + KF_VH;   // [80 d][64 tok] fp16 (144 B rows)
    float* sqp = (float*)(smem + KF_SQP);   // [64][8]
    float* sq  = (float*)(smem + KF_SQ);    // [64]
    float* red = (float*)(smem + KF_RED);   // [16]

    const int t = threadIdx.x;
    const int head = blockIdx.y;
    const int slice = blockIdx.x;

    // stage P once (bf16 planes, now the A operand: rows = m)
    #pragma unroll
    for (int cc = 0; cc < 4; cc++) {
        int e = t + 512 * cc;           // < 2048
        int row = e >> 3, j = e & 7;
        *(uint4*)(Ph + row * 144 + j * 16) = ((const uint4*)g_pbh)[e];
        *(uint4*)(Pl + row * 144 + j * 16) = ((const uint4*)g_pbl)[e];
    }
    // V const rows: row 64 = fp16 1.0 (knorm), rows 65..79 = 0
    for (int e = t; e < 576; e += 512) {
        int row = 64 + e / 36, col = e % 36;
        ((unsigned*)(Vh + row * 144))[col] = (row == 64 && col < 32) ? 0x3C003C00u : 0u;
    }

    const int w = t >> 5, lane = t & 31;
    const int g = lane >> 2, tq = lane & 3;
    const int mb2 = w * 16;                 // proj: m base (0..240)
    const int mg = (w & 7) * 32;            // kv: m base (0..224)
    const int dgr = (w >> 3) * 40;          // kv: d base (0 or 40)

    float Mr = -3.0e38f;                    // running slice max of raw u
    float c2[2][5][4];
    #pragma unroll
    for (int mt = 0; mt < 2; mt++)
        #pragma unroll
        for (int dt = 0; dt < 5; dt++)
            #pragma unroll
            for (int j = 0; j < 4; j++) c2[mt][dt][j] = 0.0f;

    const float* kp = key + (size_t)head * Dd * Nn;
    const float* vp = value + (size_t)head * Dd * Nn;

    for (int ch = 0; ch < 8; ch++) {
        const int n0 = slice * 512 + ch * 64;
        __syncthreads();   // prior kv MMA reads of E/V done; prior proj reads of X done

        // stage key chunk -> Xh/Xl + partial sumsq (8 d per thread)
        {
            const int tok = t & 63, dblk = t >> 6;   // dblk in 0..7
            const float* xp = kp + n0 + tok;
            float s = 0.0f;
            #pragma unroll
            for (int i = 0; i < 4; i++) {
                int d = dblk * 8 + 2 * i;
                float v0 = xp[(size_t)d * Nn];
                float v1 = xp[(size_t)(d + 1) * Nn];
                s = fmaf(v0, v0, fmaf(v1, v1, s));
                unsigned ph, pl;
                split2(v0, v1, ph, pl);
                *(unsigned*)(Xh + tok * 144 + d * 2) = ph;
                *(unsigned*)(Xl + tok * 144 + d * 2) = pl;
            }
            sqp[tok * 8 + dblk] = s;
        }
        // stage V chunk rows 0..63 as single fp16 (8 tok per thread)
        {
            int d = t >> 3, q = t & 7;
            const float* src = vp + (size_t)d * Nn + n0 + q * 8;
            float4 va = *(const float4*)(src);
            float4 vb = *(const float4*)(src + 4);
            __half2 x0 = __float22half2_rn(make_float2(va.x, va.y));
            __half2 x1 = __float22half2_rn(make_float2(va.z, va.w));
            __half2 x2 = __float22half2_rn(make_float2(vb.x, vb.y));
            __half2 x3 = __float22half2_rn(make_float2(vb.z, vb.w));
            *(uint4*)(Vh + d * 144 + q * 16) = make_uint4(h2u(x0), h2u(x1), h2u(x2), h2u(x3));
        }
        __syncthreads();
        if (t < 64) {
            float s = 0.0f;
            #pragma unroll
            for (int j = 0; j < 8; j++) s += sqp[t * 8 + j];
            sq[t] = s;
        }

        // proj MMA (swapped): u[m][tok], warp tile 16 m x 64 tok, bf16 3-term
        float c[8][4];
        #pragma unroll
        for (int nt = 0; nt < 8; nt++)
            #pragma unroll
            for (int j = 0; j < 4; j++) c[nt][j] = 0.0f;

        #pragma unroll
        for (int k = 0; k < 4; k++) {
            const int koff = k * 16;
            unsigned ah[4], al[4];
            ah[0] = *(const unsigned*)(Ph + (mb2 + g)     * 144 + (koff + 2*tq) * 2);
            ah[1] = *(const unsigned*)(Ph + (mb2 + g + 8) * 144 + (koff + 2*tq) * 2);
            ah[2] = *(const unsigned*)(Ph + (mb2 + g)     * 144 + (koff + 8 + 2*tq) * 2);
            ah[3] = *(const unsigned*)(Ph + (mb2 + g + 8) * 144 + (koff + 8 + 2*tq) * 2);
            al[0] = *(const unsigned*)(Pl + (mb2 + g)     * 144 + (koff + 2*tq) * 2);
            al[1] = *(const unsigned*)(Pl + (mb2 + g + 8) * 144 + (koff + 2*tq) * 2);
            al[2] = *(const unsigned*)(Pl + (mb2 + g)     * 144 + (koff + 8 + 2*tq) * 2);
            al[3] = *(const unsigned*)(Pl + (mb2 + g + 8) * 144 + (koff + 8 + 2*tq) * 2);
            #pragma unroll
            for (int nt = 0; nt < 8; nt++) {
                const char* xrow_h = Xh + (nt * 8 + g) * 144 + (koff + 2*tq) * 2;
                const char* xrow_l = Xl + (nt * 8 + g) * 144 + (koff + 2*tq) * 2;
                unsigned bh0 = *(const unsigned*)(xrow_h);
                unsigned bh1 = *(const unsigned*)(xrow_h + 16);
                unsigned bl0 = *(const unsigned*)(xrow_l);
                unsigned bl1 = *(const unsigned*)(xrow_l + 16);
                mma16816(c[nt], ah, bh0, bh1);
                mma16816(c[nt], ah, bl0, bl1);
                mma16816(c[nt], al, bh0, bh1);
            }
        }

        // chunk max of raw u
        float bm = -3.4e38f;
        #pragma unroll
        for (int nt = 0; nt < 8; nt++)
            bm = fmaxf(bm, fmaxf(fmaxf(c[nt][0], c[nt][1]), fmaxf(c[nt][2], c[nt][3])));
        #pragma unroll
        for (int o = 16; o; o >>= 1) bm = fmaxf(bm, __shfl_xor_sync(0xffffffffu, bm, o));
        if (lane == 0) red[w] = bm;
        __syncthreads();                 // also guards sq + proj MMA smem reads
        float Mb = red[0];
        #pragma unroll
        for (int r2 = 1; r2 < 16; r2++) Mb = fmaxf(Mb, red[r2]);

        // online rescale
        float Mn = fmaxf(Mr, Mb);
        float rsc = fexp(Mr - Mn);
        #pragma unroll
        for (int mt = 0; mt < 2; mt++)
            #pragma unroll
            for (int dt = 0; dt < 5; dt++)
                #pragma unroll
                for (int j = 0; j < 4; j++) c2[mt][dt][j] *= rsc;
        Mr = Mn;

        // epilogue: E = exp(u - diag - Mr) -> Eh/El fp16 pair stores (tok-contiguous)
        #pragma unroll
        for (int nt = 0; nt < 8; nt++) {
            int tok0 = nt * 8 + 2 * tq;
            float a0 = fmaf(sq[tok0],     DIAGC, Mr);
            float a1 = fmaf(sq[tok0 + 1], DIAGC, Mr);
            {
                float e0 = fexp(c[nt][0] - a0);
                float e1 = fexp(c[nt][1] - a1);
                unsigned ph, pl;
                split2h(e0, e1, ph, pl);
                *(unsigned*)(Eh + (mb2 + g) * 144 + tok0 * 2) = ph;
                *(unsigned*)(El + (mb2 + g) * 144 + tok0 * 2) = pl;
            }
            {
                float e2 = fexp(c[nt][2] - a0);
                float e3 = fexp(c[nt][3] - a1);
                unsigned ph, pl;
                split2h(e2, e3, ph, pl);
                *(unsigned*)(Eh + (mb2 + g + 8) * 144 + tok0 * 2) = ph;
                *(unsigned*)(El + (mb2 + g + 8) * 144 + tok0 * 2) = pl;
            }
        }
        __syncthreads();

        // kv MMA fp16 2-term: c2[m][d] += E[m][n] * V[d][n], warp tile 32m x 40d
        #pragma unroll
        for (int k = 0; k < 4; k++) {
            const int koff = k * 16;
            unsigned ah[2][4], al[2][4];
            #pragma unroll
            for (int mt = 0; mt < 2; mt++) {
                int r0 = mg + mt * 16 + g, r1 = r0 + 8;
                ah[mt][0] = *(const unsigned*)(Eh + r0 * 144 + (koff + 2*tq) * 2);
                ah[mt][1] = *(const unsigned*)(Eh + r1 * 144 + (koff + 2*tq) * 2);
                ah[mt][2] = *(const unsigned*)(Eh + r0 * 144 + (koff + 8 + 2*tq) * 2);
                ah[mt][3] = *(const unsigned*)(Eh + r1 * 144 + (koff + 8 + 2*tq) * 2);
                al[mt][0] = *(const unsigned*)(El + r0 * 144 + (koff + 2*tq) * 2);
                al[mt][1] = *(const unsigned*)(El + r1 * 144 + (koff + 2*tq) * 2);
                al[mt][2] = *(const unsigned*)(El + r0 * 144 + (koff + 8 + 2*tq) * 2);
                al[mt][3] = *(const unsigned*)(El + r1 * 144 + (koff + 8 + 2*tq) * 2);
            }
            #pragma unroll
            for (int dt = 0; dt < 5; dt++) {
                const char* rh = Vh + (dgr + dt * 8 + g) * 144 + (koff + 2*tq) * 2;
                unsigned b0 = *(const unsigned*)(rh);
                unsigned b1 = *(const unsigned*)(rh + 16);
                #pragma unroll
                for (int mt = 0; mt < 2; mt++) {
                    mma16816h(c2[mt][dt], ah[mt], b0, b1);
                    mma16816h(c2[mt][dt], al[mt], b0, b1);
                }
            }
        }
    }

    if (t == 0) g_smax[head * 16 + slice] = Mr;

    // write partials [d][m]
    float* dst = g_kvpart + (size_t)(head * 16 + slice) * 20480;
    #pragma unroll
    for (int mt = 0; mt < 2; mt++) {
        int m0 = mg + mt * 16 + g, m1 = m0 + 8;
        #pragma unroll
        for (int dt = 0; dt < 5; dt++) {
            int d0 = dgr + dt * 8 + 2 * tq;
            dst[d0 * 256 + m0]       = c2[mt][dt][0];
            dst[(d0 + 1) * 256 + m0] = c2[mt][dt][1];
            dst[d0 * 256 + m1]       = c2[mt][dt][2];
            dst[(d0 + 1) * 256 + m1] = c2[mt][dt][3];
        }
    }
}

// ---------------- K2: reduce partials (rescale per slice) -> fp16 kv^T -----
__global__ void k_reduce()
{
    int idx = blockIdx.x * 256 + threadIdx.x;   // < 32*80*256 = 655360
    int h = idx / 20480;
    int rem = idx - h * 20480;
    int d = rem >> 8;
    float Mh = g_smax[h * 16];
    #pragma unroll
    for (int sl = 1; sl < 16; sl++) Mh = fmaxf(Mh, g_smax[h * 16 + sl]);
    float s = 0.0f;
    #pragma unroll
    for (int sl = 0; sl < 16; sl++) {
        float sc = fexp(g_smax[h * 16 + sl] - Mh);
        s = fmaf(g_kvpart[(size_t)(h * 16 + sl) * 20480 + rem], sc, s);
    }
    float corr = (d < 64) ? REPS * g_vsum[h * 64 + d]
               : (d == 64 ? REPS * 8192.0f : 0.0f);
    float val = fmaf(RATIO, s, corr);
    g_kvt[idx] = __float2half(val);
}

// ---------------- K3 (fused): query proj + phi + out GEMM + divide ---------
// grid (64, 32), block 512 (16 warps). 128 tokens per block.
// phi_q fp16 split; kv single fp16; out MMA fp16 2-term. Proj stays bf16 3-term.
#define QF_AH   0
#define QF_AL   18432
#define QF_PH   36864
#define QF_PL   73728
#define QF_QH   0          /* phase B: [128 tok][264 fp16] 528 B rows (reuses A/P) */
#define QF_QL   67584
#define QF_KH   135168     /* [80 d][264 fp16] single plane */
#define QF_SQP  177408
#define QF_SQ   179456
#define QF_SMAX 179968
#define QF_SN   180992
#define QF_SMEM 181504

__global__ void __launch_bounds__(512, 1) k_out_fused(const float* __restrict__ query,
                                                      float* __restrict__ out)
{
    extern __shared__ char smem[];
    char* Ah = smem + QF_AH;    // [128 tok][72 bf16] (144 B rows)
    char* Al = smem + QF_AL;
    char* Ph = smem + QF_PH;    // [256 feat][72 bf16]
    char* Pl = smem + QF_PL;
    char* Qh = smem + QF_QH;    // phase B, fp16 planes
    char* Ql = smem + QF_QL;
    char* Kh = smem + QF_KH;    // fp16 single
    float* sqp  = (float*)(smem + QF_SQP);   // [128][4]
    float* sq   = (float*)(smem + QF_SQ);    // [128]
    float* smax = (float*)(smem + QF_SMAX);  // [2][128]
    float* sn   = (float*)(smem + QF_SN);    // [128]

    const int t = threadIdx.x;
    const int head = blockIdx.y;
    const int n0 = blockIdx.x * 128;

    // stage kv^T fp16 FIRST (LDGs issue earliest; region disjoint from phase A)
    if (t < 320) {
        int row = t >> 2, q = t & 3;
        const uint4* src = (const uint4*)(g_kvt + ((size_t)head * 80 + row) * 256 + q * 64);
        uint4* dst = (uint4*)(Kh + row * 528 + q * 128);
        #pragma unroll
        for (int j = 0; j < 8; j++) dst[j] = src[j];
    }
    // stage query chunk -> Ah/Al + partial sumsq
    {
        const int tok = t & 127, dblk = t >> 7;   // 4 dblks of 16 d
        const float* xp = query + (size_t)head * Dd * Nn + n0 + tok;
        float s = 0.0f;
        #pragma unroll
        for (int i = 0; i < 8; i++) {
            int d = dblk * 16 + 2 * i;
            float v0 = xp[(size_t)d * Nn];
            float v1 = xp[(size_t)(d + 1) * Nn];
            s = fmaf(v0, v0, fmaf(v1, v1, s));
            unsigned ph, pl;
            split2(v0, v1, ph, pl);
            *(unsigned*)(Ah + tok * 144 + d * 2) = ph;
            *(unsigned*)(Al + tok * 144 + d * 2) = pl;
        }
        sqp[tok * 4 + dblk] = s;
    }
    // stage P
    #pragma unroll
    for (int cc = 0; cc < 4; cc++) {
        int e = t + 512 * cc;           // < 2048
        int row = e >> 3, j = e & 7;
        *(uint4*)(Ph + row * 144 + j * 16) = ((const uint4*)g_pbh)[e];
        *(uint4*)(Pl + row * 144 + j * 16) = ((const uint4*)g_pbl)[e];
    }
    __syncthreads();
    if (t < 128) sq[t] = sqp[4*t] + sqp[4*t+1] + sqp[4*t+2] + sqp[4*t+3];

    const int w = t >> 5, lane = t & 31;
    const int g = lane >> 2, tq = lane & 3;
    const int tb = (w & 7) * 16;            // proj: token base (0..112)
    const int fb = (w >> 3) * 128;          // proj: feature base
    const int tl0 = tb + g, tl1 = tb + g + 8;

    // proj MMA (bf16 3-term, unchanged)
    float c[16][4];
    #pragma unroll
    for (int nt = 0; nt < 16; nt++)
        #pragma unroll
        for (int j = 0; j < 4; j++) c[nt][j] = 0.0f;

    #pragma unroll
    for (int k = 0; k < 4; k++) {
        const int koff = k * 16;
        unsigned ah[4], al[4];
        ah[0] = *(const unsigned*)(Ah + (tb + g)     * 144 + (koff + 2*tq) * 2);
        ah[1] = *(const unsigned*)(Ah + (tb + g + 8) * 144 + (koff + 2*tq) * 2);
        ah[2] = *(const unsigned*)(Ah + (tb + g)     * 144 + (koff + 8 + 2*tq) * 2);
        ah[3] = *(const unsigned*)(Ah + (tb + g + 8) * 144 + (koff + 8 + 2*tq) * 2);
        al[0] = *(const unsigned*)(Al + (tb + g)     * 144 + (koff + 2*tq) * 2);
        al[1] = *(const unsigned*)(Al + (tb + g + 8) * 144 + (koff + 2*tq) * 2);
        al[2] = *(const unsigned*)(Al + (tb + g)     * 144 + (koff + 8 + 2*tq) * 2);
        al[3] = *(const unsigned*)(Al + (tb + g + 8) * 144 + (koff + 8 + 2*tq) * 2);
        #pragma unroll
        for (int nt = 0; nt < 16; nt++) {
            const char* prow_h = Ph + (fb + nt * 8 + g) * 144 + (koff + 2*tq) * 2;
            const char* prow_l = Pl + (fb + nt * 8 + g) * 144 + (koff + 2*tq) * 2;
            unsigned bh0 = *(const unsigned*)(prow_h);
            unsigned bh1 = *(const unsigned*)(prow_h + 16);
            unsigned bl0 = *(const unsigned*)(prow_l);
            unsigned bl1 = *(const unsigned*)(prow_l + 16);
            mma16816(c[nt], ah, bh0, bh1);
            mma16816(c[nt], ah, bl0, bl1);
            mma16816(c[nt], al, bh0, bh1);
        }
    }

    // per-token max over features (two feature-halves combined via smem)
    {
        float m0 = -3.4e38f, m1 = -3.4e38f;
        #pragma unroll
        for (int nt = 0; nt < 16; nt++) {
            m0 = fmaxf(m0, fmaxf(c[nt][0], c[nt][1]));
            m1 = fmaxf(m1, fmaxf(c[nt][2], c[nt][3]));
        }
        m0 = fmaxf(m0, __shfl_xor_sync(0xffffffffu, m0, 1));
        m0 = fmaxf(m0, __shfl_xor_sync(0xffffffffu, m0, 2));
        m1 = fmaxf(m1, __shfl_xor_sync(0xffffffffu, m1, 1));
        m1 = fmaxf(m1, __shfl_xor_sync(0xffffffffu, m1, 2));
        if (tq == 0) {
            smax[(w >> 3) * 128 + tl0] = m0;
            smax[(w >> 3) * 128 + tl1] = m1;
        }
    }
    __syncthreads();   // proj MMA smem reads done; smax/sq ready

    // epilogue: phi_q -> Qh/Ql fp16 split (pairs along m)
    {
        const float dg0 = sq[tl0] * DIAGC;
        const float dg1 = sq[tl1] * DIAGC;
        const float cc0 = -dg0 - fmaxf(smax[tl0], smax[128 + tl0]);
        const float cc1 = -dg1 - fmaxf(smax[tl1], smax[128 + tl1]);
        unsigned* Qh32 = (unsigned*)Qh;   // rows of 132 u32 (528 B)
        unsigned* Ql32 = (unsigned*)Ql;
        #pragma unroll
        for (int nt = 0; nt < 16; nt++) {
            int m = fb + nt * 8 + 2 * tq;
            float p0 = RATIO * fexp(c[nt][0] + cc0) + REPS;
            float p1 = RATIO * fexp(c[nt][1] + cc0) + REPS;
            float p2 = RATIO * fexp(c[nt][2] + cc1) + REPS;
            float p3 = RATIO * fexp(c[nt][3] + cc1) + REPS;
            unsigned ph, pl;
            split2h(p0, p1, ph, pl);
            Qh32[tl0 * 132 + (m >> 1)] = ph;
            Ql32[tl0 * 132 + (m >> 1)] = pl;
            split2h(p2, p3, ph, pl);
            Qh32[tl1 * 132 + (m >> 1)] = ph;
            Ql32[tl1 * 132 + (m >> 1)] = pl;
        }
    }
    __syncthreads();

    // out MMA fp16 2-term: 16 warps, warp tile 16 tok x 40 d, k = 256 (m)
    const int tg = (w & 7) * 16;
    const int dgr = (w >> 3) * 40;

    float co[5][4];
    #pragma unroll
    for (int dt = 0; dt < 5; dt++)
        #pragma unroll
        for (int j = 0; j < 4; j++) co[dt][j] = 0.0f;

    #pragma unroll
    for (int kc = 0; kc < 16; kc++) {
        const int koff = kc * 16;
        unsigned ah[4], al[4];
        ah[0] = *(const unsigned*)(Qh + (tg + g)     * 528 + (koff + 2*tq) * 2);
        ah[1] = *(const unsigned*)(Qh + (tg + g + 8) * 528 + (koff + 2*tq) * 2);
        ah[2] = *(const unsigned*)(Qh + (tg + g)     * 528 + (koff + 8 + 2*tq) * 2);
        ah[3] = *(const unsigned*)(Qh + (tg + g + 8) * 528 + (koff + 8 + 2*tq) * 2);
        al[0] = *(const unsigned*)(Ql + (tg + g)     * 528 + (koff + 2*tq) * 2);
        al[1] = *(const unsigned*)(Ql + (tg + g + 8) * 528 + (koff + 2*tq) * 2);
        al[2] = *(const unsigned*)(Ql + (tg + g)     * 528 + (koff + 8 + 2*tq) * 2);
        al[3] = *(const unsigned*)(Ql + (tg + g + 8) * 528 + (koff + 8 + 2*tq) * 2);
        #pragma unroll
        for (int dt = 0; dt < 5; dt++) {
            const char* rh = Kh + (dgr + dt * 8 + g) * 528 + (koff + 2*tq) * 2;
            unsigned b0 = *(const unsigned*)(rh);
            unsigned b1 = *(const unsigned*)(rh + 16);
            mma16816h(co[dt], ah, b0, b1);
            mma16816h(co[dt], al, b0, b1);
        }
    }

    // norm column (d = 64): warps with dgr=40, dt=3, tq==0
    if (dgr == 40 && tq == 0) {
        sn[tg + g]     = co[3][0];
        sn[tg + g + 8] = co[3][2];
    }
    __syncthreads();
    const float rn0 = 1.0f / sn[tg + g];
    const float rn1 = 1.0f / sn[tg + g + 8];

    float* op = out + (size_t)head * Dd * Nn + n0;
    #pragma unroll
    for (int dt = 0; dt < 5; dt++) {
        int d0 = dgr + dt * 8 + 2 * tq;
        if (d0 < 64) {
            op[(size_t)d0 * Nn + tg + g]           = co[dt][0] * rn0;
            op[(size_t)(d0 + 1) * Nn + tg + g]     = co[dt][1] * rn0;
            op[(size_t)d0 * Nn + tg + g + 8]       = co[dt][2] * rn1;
            op[(size_t)(d0 + 1) * Nn + tg + g + 8] = co[dt][3] * rn1;
        }
    }
}

// ---------------- launch ----------------
extern "C" void kernel_launch(void* const* d_in, const int* in_sizes, int n_in,
                              void* d_out, int out_size)
{
    const float* query = (const float*)d_in[0];
    const float* key   = (const float*)d_in[1];
    const float* value = (const float*)d_in[2];
    const float* proj  = (const float*)d_in[3];
    float* out = (float*)d_out;

    cudaFuncSetAttribute(k_kv_fused,  cudaFuncAttributeMaxDynamicSharedMemorySize, KF_SMEM);
    cudaFuncSetAttribute(k_out_fused, cudaFuncAttributeMaxDynamicSharedMemorySize, QF_SMEM);

    k_init<<<64, 256>>>(proj);
    k_vsum<<<dim3(64, 32), 256>>>(value);
    k_kv_fused<<<dim3(16, 32), 512, KF_SMEM>>>(key, value);
    k_reduce<<<2560, 256>>>();
    k_out_fused<<<dim3(64, 32), 512, QF_SMEM>>>(query, out);
}